// round 7
// baseline (speedup 1.0000x reference)
#include <cuda_runtime.h>
#include <cuda_bf16.h>
#include <math.h>
#include <cstdint>

#define HEADS 32
#define S_LEN 2048
#define BATCH 2
#define HID   4096
#define DH    128
#define NROWS (BATCH*S_LEN)   // 4096
#define NBH   (BATCH*HEADS)   // 64

// ---------------- scratch (static __device__, no allocs) ----------------
__device__ float g_Q[(size_t)NBH*S_LEN*DH];
__device__ float g_K[(size_t)NBH*S_LEN*DH];
__device__ float g_V[(size_t)NBH*S_LEN*DH];
__device__ float g_cos[S_LEN*64];
__device__ float g_sin[S_LEN*64];

__device__ __nv_bfloat16 g_hsH[(size_t)NROWS*HID],  g_hsL[(size_t)NROWS*HID];
__device__ __nv_bfloat16 g_WqH[(size_t)HID*HID],    g_WqL[(size_t)HID*HID];
__device__ __nv_bfloat16 g_WkH[(size_t)HID*HID],    g_WkL[(size_t)HID*HID];
__device__ __nv_bfloat16 g_WvH[(size_t)HID*HID],    g_WvL[(size_t)HID*HID];
__device__ __nv_bfloat16 g_WoH[(size_t)HID*HID],    g_WoL[(size_t)HID*HID];
__device__ __nv_bfloat16 g_CtxH[(size_t)NROWS*HID], g_CtxL[(size_t)NROWS*HID];
__device__ __nv_bfloat16 g_QH[(size_t)NBH*S_LEN*DH], g_QL[(size_t)NBH*S_LEN*DH];
__device__ __nv_bfloat16 g_KH[(size_t)NBH*S_LEN*DH], g_KL[(size_t)NBH*S_LEN*DH];
__device__ __nv_bfloat16 g_VtH[(size_t)NBH*DH*S_LEN], g_VtL[(size_t)NBH*DH*S_LEN]; // [bh][dh][s]

// ---------------- helpers ----------------
__device__ __forceinline__ uint32_t smem_u32(const void* p) {
    uint32_t a;
    asm("{ .reg .u64 t; cvta.to.shared.u64 t, %1; cvt.u32.u64 %0, t; }" : "=r"(a) : "l"(p));
    return a;
}
#define CP16(dst, src)    asm volatile("cp.async.cg.shared.global [%0], [%1], 16;" :: "r"(dst), "l"(src) : "memory")
#define CP_COMMIT()       asm volatile("cp.async.commit_group;" ::: "memory")
#define CP_WAIT(n)        asm volatile("cp.async.wait_group %0;" :: "n"(n) : "memory")

#define LDSM_X4(r0,r1,r2,r3,a) \
    asm volatile("ldmatrix.sync.aligned.m8n8.x4.shared.b16 {%0,%1,%2,%3}, [%4];" \
        : "=r"(r0),"=r"(r1),"=r"(r2),"=r"(r3) : "r"(a))

#define MMA16816(d, a, b) \
    asm volatile("mma.sync.aligned.m16n8k16.row.col.f32.bf16.bf16.f32 " \
        "{%0,%1,%2,%3}, {%4,%5,%6,%7}, {%8,%9}, {%0,%1,%2,%3};" \
        : "+f"((d)[0]),"+f"((d)[1]),"+f"((d)[2]),"+f"((d)[3]) \
        : "r"((a)[0]),"r"((a)[1]),"r"((a)[2]),"r"((a)[3]), "r"((b)[0]),"r"((b)[1]))

#define SWZ128(x) ((x) ^ (((x) >> 3) & 0x70))

__device__ __forceinline__ uint32_t packbf(float lo, float hi) {
    uint32_t r;
    asm("cvt.rn.bf16x2.f32 %0, %1, %2;" : "=r"(r) : "f"(hi), "f"(lo));
    return r;
}

// ---------------- fp32 -> bf16 hi/lo split ----------------
__global__ void split_bf16_kernel(const float* __restrict__ src,
                                  __nv_bfloat16* __restrict__ hi,
                                  __nv_bfloat16* __restrict__ lo)
{
    int i = (blockIdx.x*blockDim.x + threadIdx.x) * 4;
    float4 v = *(const float4*)(src + i);
    __nv_bfloat16 h0 = __float2bfloat16(v.x), h1 = __float2bfloat16(v.y);
    __nv_bfloat16 h2 = __float2bfloat16(v.z), h3 = __float2bfloat16(v.w);
    __nv_bfloat162 H0 = {h0, h1}, H1 = {h2, h3};
    __nv_bfloat162 L0 = {__float2bfloat16(v.x - __bfloat162float(h0)),
                         __float2bfloat16(v.y - __bfloat162float(h1))};
    __nv_bfloat162 L1 = {__float2bfloat16(v.z - __bfloat162float(h2)),
                         __float2bfloat16(v.w - __bfloat162float(h3))};
    *(__nv_bfloat162*)(hi + i)     = H0;
    *(__nv_bfloat162*)(hi + i + 2) = H1;
    *(__nv_bfloat162*)(lo + i)     = L0;
    *(__nv_bfloat162*)(lo + i + 2) = L1;
}

// ---------------- HMMA GEMM: 128x256 CTA tile, 8 warps x (64x64) ----------
// smem/stage: Ah 16K | Al 16K | Bh 32K | Bl 32K = 96K; double-buffered = 192K
#define GT_STAGE_BYTES 98304
#define GT_SMEM_TOTAL  (2*GT_STAGE_BYTES)

__global__ __launch_bounds__(256, 1) void gemm_mma(
    const __nv_bfloat16* __restrict__ Ah, const __nv_bfloat16* __restrict__ Al,
    const __nv_bfloat16* __restrict__ Bh, const __nv_bfloat16* __restrict__ Bl,
    float* __restrict__ C, int splitHeads)
{
    extern __shared__ char smem[];
    const uint32_t sb = smem_u32(smem);
    const int tid = threadIdx.x, wid = tid >> 5, lid = tid & 31;
    const int bm = blockIdx.y * 128, bn = blockIdx.x * 256;
    const int wm = (wid >> 2) * 64, wn = (wid & 3) * 64;

    const char* aH = (const char*)Ah + (size_t)bm * (HID*2);
    const char* aL = (const char*)Al + (size_t)bm * (HID*2);
    const char* bH = (const char*)Bh + (size_t)bn * (HID*2);
    const char* bL = (const char*)Bl + (size_t)bn * (HID*2);

    auto load_chunk = [&](int stage, int chunk) {
        uint32_t st = sb + stage * GT_STAGE_BYTES;
        size_t off = (size_t)chunk * 128;
        // A: 128 rows x 8 segs per panel (1024 segs, 4 iters)
        #pragma unroll
        for (int it = 0; it < 4; it++) {
            int sidx = it*256 + tid;
            int row = sidx >> 3, col = (sidx & 7) * 16;
            uint32_t d = SWZ128((uint32_t)(row*128 + col));
            size_t g = (size_t)row * (HID*2) + off + col;
            CP16(st +     0 + d, aH + g);
            CP16(st + 16384 + d, aL + g);
        }
        // B: 256 rows x 8 segs per panel (2048 segs, 8 iters)
        #pragma unroll
        for (int it = 0; it < 8; it++) {
            int sidx = it*256 + tid;
            int row = sidx >> 3, col = (sidx & 7) * 16;
            uint32_t d = SWZ128((uint32_t)(row*128 + col));
            size_t g = (size_t)row * (HID*2) + off + col;
            CP16(st + 32768 + d, bH + g);
            CP16(st + 65536 + d, bL + g);
        }
    };

    float acc[4][8][4];
    #pragma unroll
    for (int i = 0; i < 4; i++)
        #pragma unroll
        for (int j = 0; j < 8; j++)
            #pragma unroll
            for (int c = 0; c < 4; c++) acc[i][j][c] = 0.f;

    const int q  = lid >> 3;
    const int r8 = lid & 7;

    load_chunk(0, 0);
    CP_COMMIT();

    const int NCHUNK = HID / 64;
    for (int chunk = 0; chunk < NCHUNK; chunk++) {
        int buf = chunk & 1;
        if (chunk + 1 < NCHUNK) {
            load_chunk(buf ^ 1, chunk + 1);
            CP_COMMIT();
            CP_WAIT(1);
        } else {
            CP_WAIT(0);
        }
        __syncthreads();

        uint32_t stA  = sb + buf * GT_STAGE_BYTES;
        uint32_t stAl = stA + 16384, stBh = stA + 32768, stBl = stA + 65536;

        #pragma unroll
        for (int kk = 0; kk < 4; kk++) {
            uint32_t ah[16], al[16];
            #pragma unroll
            for (int i = 0; i < 4; i++) {
                int rowA = wm + i*16 + (q & 1)*8 + r8;
                int kb   = kk*32 + (q >> 1)*16;
                uint32_t off = SWZ128((uint32_t)(rowA*128 + kb));
                LDSM_X4(ah[i*4+0], ah[i*4+1], ah[i*4+2], ah[i*4+3], stA  + off);
                LDSM_X4(al[i*4+0], al[i*4+1], al[i*4+2], al[i*4+3], stAl + off);
            }
            #pragma unroll
            for (int j2 = 0; j2 < 4; j2++) {
                int rowB = wn + j2*16 + (q >> 1)*8 + r8;
                int kb   = kk*32 + (q & 1)*16;
                uint32_t off = SWZ128((uint32_t)(rowB*128 + kb));
                uint32_t bh[4], bl[4];
                LDSM_X4(bh[0],bh[1],bh[2],bh[3], stBh + off);
                LDSM_X4(bl[0],bl[1],bl[2],bl[3], stBl + off);
                #pragma unroll
                for (int i = 0; i < 4; i++) {
                    MMA16816(acc[i][j2*2],   &ah[i*4], &bh[0]);
                    MMA16816(acc[i][j2*2],   &ah[i*4], &bl[0]);
                    MMA16816(acc[i][j2*2],   &al[i*4], &bh[0]);
                    MMA16816(acc[i][j2*2+1], &ah[i*4], &bh[2]);
                    MMA16816(acc[i][j2*2+1], &ah[i*4], &bl[2]);
                    MMA16816(acc[i][j2*2+1], &al[i*4], &bh[2]);
                }
            }
        }
        __syncthreads();
    }

    const int gr = lid >> 2;
    const int gc = (lid & 3) * 2;
    #pragma unroll
    for (int i = 0; i < 4; i++) {
        #pragma unroll
        for (int half = 0; half < 2; half++) {
            int row = bm + wm + i*16 + gr + half*8;
            #pragma unroll
            for (int j = 0; j < 8; j++) {
                int col = bn + wn + j*8 + gc;
                float2 v = half ? make_float2(acc[i][j][2], acc[i][j][3])
                                : make_float2(acc[i][j][0], acc[i][j][1]);
                float* op;
                if (splitHeads) {
                    int b = row >> 11, s = row & (S_LEN-1);
                    int h = col >> 7, d = col & 127;
                    op = C + ((((size_t)(b*HEADS + h))*S_LEN + s) << 7) + d;
                } else {
                    op = C + (size_t)row * HID + col;
                }
                *(float2*)op = v;
            }
        }
    }
}

// ---------------- RoPE ----------------
__global__ void rope_table_kernel(const int* __restrict__ pos_ids)
{
    int idx = blockIdx.x*blockDim.x + threadIdx.x;
    int i = idx & 63;
    int s = idx >> 6;
    float pos = (float)pos_ids[s];
    double invf = pow(10000.0, -(double)(2*i) / 128.0);
    float ang = pos * (float)invf;
    float sn, cs;
    sincosf(ang, &sn, &cs);
    g_cos[idx] = cs;
    g_sin[idx] = sn;
}

__global__ void rope_apply_split_kernel()
{
    int idx = blockIdx.x*blockDim.x + threadIdx.x;
    int i  = idx & 63;
    int s  = (idx >> 6) & (S_LEN-1);
    int bh = idx >> 17;
    float cs = g_cos[(s<<6) + i];
    float sn = g_sin[(s<<6) + i];
    size_t base = (((size_t)bh * S_LEN + s) << 7) + i;

    float q0 = g_Q[base], q1 = g_Q[base+64];
    float qa = q0*cs - q1*sn;
    float qb = q1*cs + q0*sn;
    __nv_bfloat16 h;
    h = __float2bfloat16(qa); g_QH[base]    = h; g_QL[base]    = __float2bfloat16(qa - __bfloat162float(h));
    h = __float2bfloat16(qb); g_QH[base+64] = h; g_QL[base+64] = __float2bfloat16(qb - __bfloat162float(h));

    float k0 = g_K[base], k1 = g_K[base+64];
    float ka = k0*cs - k1*sn;
    float kb = k1*cs + k0*sn;
    h = __float2bfloat16(ka); g_KH[base]    = h; g_KL[base]    = __float2bfloat16(ka - __bfloat162float(h));
    h = __float2bfloat16(kb); g_KH[base+64] = h; g_KL[base+64] = __float2bfloat16(kb - __bfloat162float(h));
}

// ---------------- V transpose + split ----------------
__global__ void vt_split_kernel()
{
    __shared__ float tile[32][33];
    int xs = blockIdx.x * 32;
    int dd = blockIdx.y * 32;
    int bh = blockIdx.z;
    int tx = threadIdx.x, ty = threadIdx.y;

    const float* V = g_V + ((size_t)bh * S_LEN) * DH;
    #pragma unroll
    for (int j = 0; j < 4; j++)
        tile[ty + j*8][tx] = V[(size_t)(xs + ty + j*8)*DH + dd + tx];
    __syncthreads();
    #pragma unroll
    for (int j = 0; j < 4; j++) {
        float v = tile[tx][ty + j*8];
        __nv_bfloat16 h = __float2bfloat16(v);
        size_t o = ((size_t)bh*DH + dd + ty + j*8) * S_LEN + xs + tx;
        g_VtH[o] = h;
        g_VtL[o] = __float2bfloat16(v - __bfloat162float(h));
    }
}

// ---------------- HMMA flash attention (verified) ----------------
#define AT2_SMEM (65536 + 2*65536)

__global__ __launch_bounds__(256, 1) void attn_mma()
{
    extern __shared__ char smem[];
    const uint32_t sb = smem_u32(smem);
    const int tid = threadIdx.x, wid = tid >> 5, lid = tid & 31;
    const int qt = blockIdx.x, h = blockIdx.y, b = blockIdx.z;
    const size_t bh = (size_t)b*HEADS + h;
    const int q  = lid >> 3;
    const int r8 = lid & 7;

    const char* qHb = (const char*)g_QH + (bh*S_LEN + (size_t)qt*128) * 256;
    const char* qLb = (const char*)g_QL + (bh*S_LEN + (size_t)qt*128) * 256;
    const char* kHb = (const char*)g_KH + bh*S_LEN*256;
    const char* kLb = (const char*)g_KL + bh*S_LEN*256;
    const char* vHb = (const char*)g_VtH + bh*DH*(size_t)S_LEN*2;
    const char* vLb = (const char*)g_VtL + bh*DH*(size_t)S_LEN*2;

    #pragma unroll
    for (int it = 0; it < 8; it++) {
        int e = it*256 + tid;
        int row = e >> 4, seg = e & 15;
        int panel = seg >> 3, c = seg & 7;
        uint32_t d = SWZ128((uint32_t)(row*128 + c*16));
        CP16(sb + panel*16384 + d,     qHb + row*256 + seg*16);
        CP16(sb + (2+panel)*16384 + d, qLb + row*256 + seg*16);
    }

    auto load_kv = [&](int st, int kt) {
        uint32_t stb = sb + 65536 + st*65536;
        #pragma unroll
        for (int it = 0; it < 4; it++) {
            int e = it*256 + tid;
            int row = e >> 4, seg = e & 15;
            int panel = seg >> 3, c = seg & 7;
            uint32_t d = SWZ128((uint32_t)(row*128 + c*16));
            size_t g = (size_t)(kt*64 + row)*256 + seg*16;
            CP16(stb + panel*8192 + d,         kHb + g);
            CP16(stb + 16384 + panel*8192 + d, kLb + g);
        }
        #pragma unroll
        for (int it = 0; it < 4; it++) {
            int e = it*256 + tid;
            int row = e >> 3, c = e & 7;
            uint32_t d = SWZ128((uint32_t)(row*128 + c*16));
            size_t g = (size_t)row*4096 + (size_t)kt*128 + c*16;
            CP16(stb + 32768 + d, vHb + g);
            CP16(stb + 49152 + d, vLb + g);
        }
    };

    load_kv(0, 0);
    CP_COMMIT();

    float o[16][4];
    #pragma unroll
    for (int t = 0; t < 16; t++)
        #pragma unroll
        for (int c = 0; c < 4; c++) o[t][c] = 0.f;
    float m0 = -1e30f, m1 = -1e30f, l0 = 0.f, l1 = 0.f;

    const float scale = 0.08838834764831845f;
    const int qrow_lo = qt*128 + wid*16;
    const int row0 = qrow_lo + (lid >> 2);
    const int col_in = (lid & 3) * 2;

    const int nkv = 2*qt + 2;
    for (int kt = 0; kt < nkv; kt++) {
        int buf = kt & 1;
        if (kt + 1 < nkv) {
            load_kv(buf ^ 1, kt + 1);
            CP_COMMIT();
            CP_WAIT(1);
        } else {
            CP_WAIT(0);
        }
        __syncthreads();

        bool skip = (kt*64 > qrow_lo + 15);
        if (!skip) {
            uint32_t stb = sb + 65536 + buf*65536;

            float sacc[8][4];
            #pragma unroll
            for (int t = 0; t < 8; t++)
                #pragma unroll
                for (int c = 0; c < 4; c++) sacc[t][c] = 0.f;

            #pragma unroll
            for (int kk = 0; kk < 8; kk++) {
                int panel = kk >> 2;
                int kb = (kk & 3)*32;
                uint32_t qh[4], ql[4];
                {
                    int rowA = wid*16 + (q & 1)*8 + r8;
                    uint32_t off = SWZ128((uint32_t)(rowA*128 + kb + (q >> 1)*16));
                    LDSM_X4(qh[0],qh[1],qh[2],qh[3], sb + panel*16384 + off);
                    LDSM_X4(ql[0],ql[1],ql[2],ql[3], sb + (2+panel)*16384 + off);
                }
                #pragma unroll
                for (int j2 = 0; j2 < 4; j2++) {
                    int rowB = j2*16 + (q >> 1)*8 + r8;
                    uint32_t off = SWZ128((uint32_t)(rowB*128 + kb + (q & 1)*16));
                    uint32_t kh[4], kl[4];
                    LDSM_X4(kh[0],kh[1],kh[2],kh[3], stb + panel*8192 + off);
                    LDSM_X4(kl[0],kl[1],kl[2],kl[3], stb + 16384 + panel*8192 + off);
                    MMA16816(sacc[j2*2],   qh, &kh[0]);
                    MMA16816(sacc[j2*2],   qh, &kl[0]);
                    MMA16816(sacc[j2*2],   ql, &kh[0]);
                    MMA16816(sacc[j2*2+1], qh, &kh[2]);
                    MMA16816(sacc[j2*2+1], qh, &kl[2]);
                    MMA16816(sacc[j2*2+1], ql, &kh[2]);
                }
            }

            #pragma unroll
            for (int t = 0; t < 8; t++)
                #pragma unroll
                for (int c = 0; c < 4; c++) sacc[t][c] *= scale;

            if (kt*64 + 63 > qrow_lo) {
                #pragma unroll
                for (int t = 0; t < 8; t++) {
                    int colg = kt*64 + t*8 + col_in;
                    if (colg   > row0)   sacc[t][0] = -1e30f;
                    if (colg+1 > row0)   sacc[t][1] = -1e30f;
                    if (colg   > row0+8) sacc[t][2] = -1e30f;
                    if (colg+1 > row0+8) sacc[t][3] = -1e30f;
                }
            }

            float mx0 = -1e30f, mx1 = -1e30f;
            #pragma unroll
            for (int t = 0; t < 8; t++) {
                mx0 = fmaxf(mx0, fmaxf(sacc[t][0], sacc[t][1]));
                mx1 = fmaxf(mx1, fmaxf(sacc[t][2], sacc[t][3]));
            }
            mx0 = fmaxf(mx0, __shfl_xor_sync(0xffffffffu, mx0, 1));
            mx0 = fmaxf(mx0, __shfl_xor_sync(0xffffffffu, mx0, 2));
            mx1 = fmaxf(mx1, __shfl_xor_sync(0xffffffffu, mx1, 1));
            mx1 = fmaxf(mx1, __shfl_xor_sync(0xffffffffu, mx1, 2));
            float mn0 = fmaxf(m0, mx0), mn1 = fmaxf(m1, mx1);
            float cr0 = __expf(m0 - mn0), cr1 = __expf(m1 - mn1);
            m0 = mn0; m1 = mn1;

            float s0 = 0.f, s1 = 0.f;
            #pragma unroll
            for (int t = 0; t < 8; t++) {
                sacc[t][0] = __expf(sacc[t][0] - mn0);
                sacc[t][1] = __expf(sacc[t][1] - mn0);
                sacc[t][2] = __expf(sacc[t][2] - mn1);
                sacc[t][3] = __expf(sacc[t][3] - mn1);
                s0 += sacc[t][0] + sacc[t][1];
                s1 += sacc[t][2] + sacc[t][3];
            }
            s0 += __shfl_xor_sync(0xffffffffu, s0, 1);
            s0 += __shfl_xor_sync(0xffffffffu, s0, 2);
            s1 += __shfl_xor_sync(0xffffffffu, s1, 1);
            s1 += __shfl_xor_sync(0xffffffffu, s1, 2);
            l0 = l0*cr0 + s0;
            l1 = l1*cr1 + s1;
            #pragma unroll
            for (int t = 0; t < 16; t++) {
                o[t][0] *= cr0; o[t][1] *= cr0;
                o[t][2] *= cr1; o[t][3] *= cr1;
            }

            uint32_t ph[4][4], pl[4][4];
            #pragma unroll
            for (int t = 0; t < 4; t++) {
                #pragma unroll
                for (int u = 0; u < 2; u++) {
                    float p00 = sacc[2*t+u][0], p01 = sacc[2*t+u][1];
                    float p10 = sacc[2*t+u][2], p11 = sacc[2*t+u][3];
                    float h00 = __bfloat162float(__float2bfloat16(p00));
                    float h01 = __bfloat162float(__float2bfloat16(p01));
                    float h10 = __bfloat162float(__float2bfloat16(p10));
                    float h11 = __bfloat162float(__float2bfloat16(p11));
                    ph[t][u*2+0] = packbf(h00, h01);
                    ph[t][u*2+1] = packbf(h10, h11);
                    pl[t][u*2+0] = packbf(p00-h00, p01-h01);
                    pl[t][u*2+1] = packbf(p10-h10, p11-h11);
                }
            }

            #pragma unroll
            for (int ks = 0; ks < 4; ks++) {
                int kb = ks*32;
                #pragma unroll
                for (int j2 = 0; j2 < 8; j2++) {
                    int rowB = j2*16 + (q >> 1)*8 + r8;
                    uint32_t off = SWZ128((uint32_t)(rowB*128 + kb + (q & 1)*16));
                    uint32_t vh[4], vl[4];
                    LDSM_X4(vh[0],vh[1],vh[2],vh[3], stb + 32768 + off);
                    LDSM_X4(vl[0],vl[1],vl[2],vl[3], stb + 49152 + off);
                    MMA16816(o[j2*2],   ph[ks], &vh[0]);
                    MMA16816(o[j2*2],   ph[ks], &vl[0]);
                    MMA16816(o[j2*2],   pl[ks], &vh[0]);
                    MMA16816(o[j2*2+1], ph[ks], &vh[2]);
                    MMA16816(o[j2*2+1], ph[ks], &vl[2]);
                    MMA16816(o[j2*2+1], pl[ks], &vh[2]);
                }
            }
        }
        __syncthreads();
    }

    // ---- normalize + split to bf16 hi/lo, write Ctx directly ----
    float inv0 = 1.0f / l0, inv1 = 1.0f / l1;
    size_t off0 = ((size_t)b*S_LEN + row0)     * HID + h*DH + col_in;
    size_t off1 = ((size_t)b*S_LEN + row0 + 8) * HID + h*DH + col_in;
    #pragma unroll
    for (int t = 0; t < 16; t++) {
        float x0 = o[t][0]*inv0, x1 = o[t][1]*inv0;
        float y0 = o[t][2]*inv1, y1 = o[t][3]*inv1;
        __nv_bfloat16 hx0 = __float2bfloat16(x0), hx1 = __float2bfloat16(x1);
        __nv_bfloat16 hy0 = __float2bfloat16(y0), hy1 = __float2bfloat16(y1);
        *(__nv_bfloat162*)(g_CtxH + off0 + t*8) = {hx0, hx1};
        *(__nv_bfloat162*)(g_CtxL + off0 + t*8) =
            {__float2bfloat16(x0 - __bfloat162float(hx0)), __float2bfloat16(x1 - __bfloat162float(hx1))};
        *(__nv_bfloat162*)(g_CtxH + off1 + t*8) = {hy0, hy1};
        *(__nv_bfloat162*)(g_CtxL + off1 + t*8) =
            {__float2bfloat16(y0 - __bfloat162float(hy0)), __float2bfloat16(y1 - __bfloat162float(hy1))};
    }
}

// ---------------- launch ----------------
extern "C" void kernel_launch(void* const* d_in, const int* in_sizes, int n_in,
                              void* d_out, int out_size)
{
    const float* hs = (const float*)d_in[0];
    const float* Wq = (const float*)d_in[1];
    const float* Wk = (const float*)d_in[2];
    const float* Wv = (const float*)d_in[3];
    const float* Wo = (const float*)d_in[4];
    const int* pos  = (const int*)d_in[6];
    float* out = (float*)d_out;

    float *Qp, *Kp, *Vp;
    cudaGetSymbolAddress((void**)&Qp, g_Q);
    cudaGetSymbolAddress((void**)&Kp, g_K);
    cudaGetSymbolAddress((void**)&Vp, g_V);

    __nv_bfloat16 *hsH,*hsL,*WqH,*WqL,*WkH,*WkL,*WvH,*WvL,*WoH,*WoL,*CtxH,*CtxL;
    cudaGetSymbolAddress((void**)&hsH, g_hsH);  cudaGetSymbolAddress((void**)&hsL, g_hsL);
    cudaGetSymbolAddress((void**)&WqH, g_WqH);  cudaGetSymbolAddress((void**)&WqL, g_WqL);
    cudaGetSymbolAddress((void**)&WkH, g_WkH);  cudaGetSymbolAddress((void**)&WkL, g_WkL);
    cudaGetSymbolAddress((void**)&WvH, g_WvH);  cudaGetSymbolAddress((void**)&WvL, g_WvL);
    cudaGetSymbolAddress((void**)&WoH, g_WoH);  cudaGetSymbolAddress((void**)&WoL, g_WoL);
    cudaGetSymbolAddress((void**)&CtxH, g_CtxH);cudaGetSymbolAddress((void**)&CtxL, g_CtxL);

    const int NELEM = NROWS*HID;
    const int SPLIT_BLOCKS = NELEM/4/256;

    split_bf16_kernel<<<SPLIT_BLOCKS, 256>>>(hs, hsH, hsL);
    split_bf16_kernel<<<SPLIT_BLOCKS, 256>>>(Wq, WqH, WqL);
    split_bf16_kernel<<<SPLIT_BLOCKS, 256>>>(Wk, WkH, WkL);
    split_bf16_kernel<<<SPLIT_BLOCKS, 256>>>(Wv, WvH, WvL);
    split_bf16_kernel<<<SPLIT_BLOCKS, 256>>>(Wo, WoH, WoL);

    cudaFuncSetAttribute(gemm_mma, cudaFuncAttributeMaxDynamicSharedMemorySize, GT_SMEM_TOTAL);
    dim3 ggrid(HID/256, NROWS/128);   // 16 x 32

    gemm_mma<<<ggrid, 256, GT_SMEM_TOTAL>>>(hsH, hsL, WqH, WqL, Qp, 1);
    gemm_mma<<<ggrid, 256, GT_SMEM_TOTAL>>>(hsH, hsL, WkH, WkL, Kp, 1);
    gemm_mma<<<ggrid, 256, GT_SMEM_TOTAL>>>(hsH, hsL, WvH, WvL, Vp, 1);

    rope_table_kernel<<<(S_LEN*64)/256, 256>>>(pos);
    rope_apply_split_kernel<<<(NBH*S_LEN*64)/256, 256>>>();
    vt_split_kernel<<<dim3(S_LEN/32, DH/32, NBH), dim3(32,8)>>>();

    cudaFuncSetAttribute(attn_mma, cudaFuncAttributeMaxDynamicSharedMemorySize, AT2_SMEM);
    attn_mma<<<dim3(S_LEN/128, HEADS, BATCH), 256, AT2_SMEM>>>();

    gemm_mma<<<ggrid, 256, GT_SMEM_TOTAL>>>(CtxH, CtxL, WoH, WoL, out, 0);
}

// round 8
// speedup vs baseline: 2.3449x; 2.3449x over previous
#include <cuda_runtime.h>
#include <cuda_fp16.h>
#include <math.h>
#include <cstdint>

#define HEADS 32
#define S_LEN 2048
#define BATCH 2
#define HID   4096
#define DH    128
#define NROWS (BATCH*S_LEN)   // 4096
#define NBH   (BATCH*HEADS)   // 64

// ---------------- scratch (static __device__, no allocs) ----------------
__device__ float g_Q[(size_t)NBH*S_LEN*DH];
__device__ float g_K[(size_t)NBH*S_LEN*DH];
__device__ float g_V[(size_t)NBH*S_LEN*DH];
__device__ float g_cos[S_LEN*64];
__device__ float g_sin[S_LEN*64];

__device__ __half g_hsH[(size_t)NROWS*HID];                    // activations: fp16 only
__device__ __half g_WqH[(size_t)HID*HID],  g_WqL[(size_t)HID*HID];
__device__ __half g_WkH[(size_t)HID*HID],  g_WkL[(size_t)HID*HID];
__device__ __half g_WvH[(size_t)HID*HID],  g_WvL[(size_t)HID*HID];
__device__ __half g_WoH[(size_t)HID*HID],  g_WoL[(size_t)HID*HID];
__device__ __half g_CtxH[(size_t)NROWS*HID];                   // attention out: fp16 only
__device__ __half g_QH[(size_t)NBH*S_LEN*DH];                  // Q: fp16 only
__device__ __half g_KH[(size_t)NBH*S_LEN*DH], g_KL[(size_t)NBH*S_LEN*DH];
__device__ __half g_VtH[(size_t)NBH*DH*S_LEN], g_VtL[(size_t)NBH*DH*S_LEN]; // [bh][dh][s]

// ---------------- helpers ----------------
__device__ __forceinline__ uint32_t smem_u32(const void* p) {
    uint32_t a;
    asm("{ .reg .u64 t; cvta.to.shared.u64 t, %1; cvt.u32.u64 %0, t; }" : "=r"(a) : "l"(p));
    return a;
}
#define CP16(dst, src)    asm volatile("cp.async.cg.shared.global [%0], [%1], 16;" :: "r"(dst), "l"(src) : "memory")
#define CP_COMMIT()       asm volatile("cp.async.commit_group;" ::: "memory")
#define CP_WAIT(n)        asm volatile("cp.async.wait_group %0;" :: "n"(n) : "memory")

#define LDSM_X4(r0,r1,r2,r3,a) \
    asm volatile("ldmatrix.sync.aligned.m8n8.x4.shared.b16 {%0,%1,%2,%3}, [%4];" \
        : "=r"(r0),"=r"(r1),"=r"(r2),"=r"(r3) : "r"(a))

#define MMA16816(d, a, b) \
    asm volatile("mma.sync.aligned.m16n8k16.row.col.f32.f16.f16.f32 " \
        "{%0,%1,%2,%3}, {%4,%5,%6,%7}, {%8,%9}, {%0,%1,%2,%3};" \
        : "+f"((d)[0]),"+f"((d)[1]),"+f"((d)[2]),"+f"((d)[3]) \
        : "r"((a)[0]),"r"((a)[1]),"r"((a)[2]),"r"((a)[3]), "r"((b)[0]),"r"((b)[1]))

#define SWZ128(x) ((x) ^ (((x) >> 3) & 0x70))

__device__ __forceinline__ uint32_t packh(float lo, float hi) {
    uint32_t r;   // first src operand -> high half
    asm("cvt.rn.f16x2.f32 %0, %1, %2;" : "=r"(r) : "f"(hi), "f"(lo));
    return r;
}

// ---------------- fp32 -> fp16 convert (activations) ----------------
__global__ void conv_h_kernel(const float* __restrict__ src, __half* __restrict__ dst)
{
    int i = (blockIdx.x*blockDim.x + threadIdx.x) * 4;
    float4 v = *(const float4*)(src + i);
    *(__half2*)(dst + i)     = __half2{__float2half(v.x), __float2half(v.y)};
    *(__half2*)(dst + i + 2) = __half2{__float2half(v.z), __float2half(v.w)};
}

// ---------------- fp32 -> fp16 hi/lo split (weights) ----------------
__global__ void split_h_kernel(const float* __restrict__ src,
                               __half* __restrict__ hi, __half* __restrict__ lo)
{
    int i = (blockIdx.x*blockDim.x + threadIdx.x) * 4;
    float4 v = *(const float4*)(src + i);
    __half h0 = __float2half(v.x), h1 = __float2half(v.y);
    __half h2 = __float2half(v.z), h3 = __float2half(v.w);
    *(__half2*)(hi + i)     = __half2{h0, h1};
    *(__half2*)(hi + i + 2) = __half2{h2, h3};
    *(__half2*)(lo + i)     = __half2{__float2half(v.x - __half2float(h0)),
                                      __float2half(v.y - __half2float(h1))};
    *(__half2*)(lo + i + 2) = __half2{__float2half(v.z - __half2float(h2)),
                                      __float2half(v.w - __half2float(h3))};
}

// ---------------- HMMA GEMM: C[M,N] = A @ (Bh+Bl)^T, 128x128 tile ----------
// smem/stage: Ah 16K | Bh 16K | Bl 16K = 48K; double buffered = 96K
#define GT_STAGE_BYTES 49152
#define GT_SMEM_TOTAL  (2*GT_STAGE_BYTES)

__global__ __launch_bounds__(256, 1) void gemm_mma(
    const __half* __restrict__ Ah,
    const __half* __restrict__ Bh, const __half* __restrict__ Bl,
    float* __restrict__ C, int splitHeads)
{
    extern __shared__ char smem[];
    const uint32_t sb = smem_u32(smem);
    const int tid = threadIdx.x, wid = tid >> 5, lid = tid & 31;
    const int bm = blockIdx.y * 128, bn = blockIdx.x * 128;
    const int wm = (wid >> 2) * 64, wn = (wid & 3) * 32;

    const char* aH = (const char*)Ah + (size_t)bm * (HID*2);
    const char* bH = (const char*)Bh + (size_t)bn * (HID*2);
    const char* bL = (const char*)Bl + (size_t)bn * (HID*2);

    int srow[4], scol[4];
    #pragma unroll
    for (int j = 0; j < 4; j++) {
        int sidx = j*256 + tid;
        srow[j] = sidx >> 3;
        scol[j] = (sidx & 7) * 16;
    }

    auto load_chunk = [&](int stage, int chunk) {
        uint32_t st = sb + stage * GT_STAGE_BYTES;
        size_t off = (size_t)chunk * 128;
        #pragma unroll
        for (int j = 0; j < 4; j++) {
            uint32_t d = SWZ128((uint32_t)(srow[j]*128 + scol[j]));
            size_t g = (size_t)srow[j] * (HID*2) + off + scol[j];
            CP16(st +     0 + d, aH + g);
            CP16(st + 16384 + d, bH + g);
            CP16(st + 32768 + d, bL + g);
        }
    };

    float acc[4][4][4];
    #pragma unroll
    for (int i = 0; i < 4; i++)
        #pragma unroll
        for (int j = 0; j < 4; j++)
            #pragma unroll
            for (int c = 0; c < 4; c++) acc[i][j][c] = 0.f;

    const int q  = lid >> 3;
    const int r8 = lid & 7;

    load_chunk(0, 0);
    CP_COMMIT();

    const int NCHUNK = HID / 64;
    for (int chunk = 0; chunk < NCHUNK; chunk++) {
        int buf = chunk & 1;
        if (chunk + 1 < NCHUNK) {
            load_chunk(buf ^ 1, chunk + 1);
            CP_COMMIT();
            CP_WAIT(1);
        } else {
            CP_WAIT(0);
        }
        __syncthreads();

        uint32_t stA  = sb + buf * GT_STAGE_BYTES;
        uint32_t stBh = stA + 16384, stBl = stA + 32768;

        #pragma unroll
        for (int kk = 0; kk < 4; kk++) {
            uint32_t ah[16];
            #pragma unroll
            for (int i = 0; i < 4; i++) {
                int rowA = wm + i*16 + (q & 1)*8 + r8;
                int kb   = kk*32 + (q >> 1)*16;
                uint32_t off = SWZ128((uint32_t)(rowA*128 + kb));
                LDSM_X4(ah[i*4+0], ah[i*4+1], ah[i*4+2], ah[i*4+3], stA + off);
            }
            #pragma unroll
            for (int j2 = 0; j2 < 2; j2++) {
                int rowB = wn + j2*16 + (q >> 1)*8 + r8;
                int kb   = kk*32 + (q & 1)*16;
                uint32_t off = SWZ128((uint32_t)(rowB*128 + kb));
                uint32_t bh[4], bl[4];
                LDSM_X4(bh[0],bh[1],bh[2],bh[3], stBh + off);
                LDSM_X4(bl[0],bl[1],bl[2],bl[3], stBl + off);
                #pragma unroll
                for (int i = 0; i < 4; i++) {
                    MMA16816(acc[i][j2*2],   &ah[i*4], &bh[0]);
                    MMA16816(acc[i][j2*2],   &ah[i*4], &bl[0]);
                    MMA16816(acc[i][j2*2+1], &ah[i*4], &bh[2]);
                    MMA16816(acc[i][j2*2+1], &ah[i*4], &bl[2]);
                }
            }
        }
        __syncthreads();
    }

    const int gr = lid >> 2;
    const int gc = (lid & 3) * 2;
    #pragma unroll
    for (int i = 0; i < 4; i++) {
        #pragma unroll
        for (int half = 0; half < 2; half++) {
            int row = bm + wm + i*16 + gr + half*8;
            #pragma unroll
            for (int j = 0; j < 4; j++) {
                int col = wn + j*8 + gc;
                float2 v = half ? make_float2(acc[i][j][2], acc[i][j][3])
                                : make_float2(acc[i][j][0], acc[i][j][1]);
                float* op;
                if (splitHeads) {
                    int b = row >> 11, s = row & (S_LEN-1);
                    int h = blockIdx.x;
                    op = C + ((((size_t)(b*HEADS + h))*S_LEN + s) << 7) + col;
                } else {
                    op = C + (size_t)row * HID + bn + col;
                }
                *(float2*)op = v;
            }
        }
    }
}

// ---------------- RoPE ----------------
__global__ void rope_table_kernel(const int* __restrict__ pos_ids)
{
    int idx = blockIdx.x*blockDim.x + threadIdx.x;
    int i = idx & 63;
    int s = idx >> 6;
    float pos = (float)pos_ids[s];
    double invf = pow(10000.0, -(double)(2*i) / 128.0);
    float ang = pos * (float)invf;
    float sn, cs;
    sincosf(ang, &sn, &cs);
    g_cos[idx] = cs;
    g_sin[idx] = sn;
}

// rope + emit Q fp16 (single) and K fp16 hi/lo
__global__ void rope_apply_split_kernel()
{
    int idx = blockIdx.x*blockDim.x + threadIdx.x;
    int i  = idx & 63;
    int s  = (idx >> 6) & (S_LEN-1);
    int bh = idx >> 17;
    float cs = g_cos[(s<<6) + i];
    float sn = g_sin[(s<<6) + i];
    size_t base = (((size_t)bh * S_LEN + s) << 7) + i;

    float q0 = g_Q[base], q1 = g_Q[base+64];
    g_QH[base]    = __float2half(q0*cs - q1*sn);
    g_QH[base+64] = __float2half(q1*cs + q0*sn);

    float k0 = g_K[base], k1 = g_K[base+64];
    float ka = k0*cs - k1*sn;
    float kb = k1*cs + k0*sn;
    __half h;
    h = __float2half(ka); g_KH[base]    = h; g_KL[base]    = __float2half(ka - __half2float(h));
    h = __float2half(kb); g_KH[base+64] = h; g_KL[base+64] = __float2half(kb - __half2float(h));
}

// ---------------- V transpose + split ----------------
__global__ void vt_split_kernel()
{
    __shared__ float tile[32][33];
    int xs = blockIdx.x * 32;
    int dd = blockIdx.y * 32;
    int bh = blockIdx.z;
    int tx = threadIdx.x, ty = threadIdx.y;

    const float* V = g_V + ((size_t)bh * S_LEN) * DH;
    #pragma unroll
    for (int j = 0; j < 4; j++)
        tile[ty + j*8][tx] = V[(size_t)(xs + ty + j*8)*DH + dd + tx];
    __syncthreads();
    #pragma unroll
    for (int j = 0; j < 4; j++) {
        float v = tile[tx][ty + j*8];
        __half h = __float2half(v);
        size_t o = ((size_t)bh*DH + dd + ty + j*8) * S_LEN + xs + tx;
        g_VtH[o] = h;
        g_VtL[o] = __float2half(v - __half2float(h));
    }
}

// ---------------- HMMA flash attention (fp16 2-product) ----------------
// smem: Q 2x16K | 2 stages x { Kh 2x8K, Kl 2x8K, VtH 16K, VtL 16K }
#define AT2_SMEM (32768 + 2*65536)

__global__ __launch_bounds__(256, 1) void attn_mma()
{
    extern __shared__ char smem[];
    const uint32_t sb = smem_u32(smem);
    const int tid = threadIdx.x, wid = tid >> 5, lid = tid & 31;
    const int qt = blockIdx.x, h = blockIdx.y, b = blockIdx.z;
    const size_t bh = (size_t)b*HEADS + h;
    const int q  = lid >> 3;
    const int r8 = lid & 7;

    const char* qHb = (const char*)g_QH + (bh*S_LEN + (size_t)qt*128) * 256;
    const char* kHb = (const char*)g_KH + bh*S_LEN*256;
    const char* kLb = (const char*)g_KL + bh*S_LEN*256;
    const char* vHb = (const char*)g_VtH + bh*DH*(size_t)S_LEN*2;
    const char* vLb = (const char*)g_VtL + bh*DH*(size_t)S_LEN*2;

    #pragma unroll
    for (int it = 0; it < 8; it++) {
        int e = it*256 + tid;
        int row = e >> 4, seg = e & 15;
        int panel = seg >> 3, c = seg & 7;
        uint32_t d = SWZ128((uint32_t)(row*128 + c*16));
        CP16(sb + panel*16384 + d, qHb + row*256 + seg*16);
    }

    auto load_kv = [&](int st, int kt) {
        uint32_t stb = sb + 32768 + st*65536;
        #pragma unroll
        for (int it = 0; it < 4; it++) {
            int e = it*256 + tid;
            int row = e >> 4, seg = e & 15;
            int panel = seg >> 3, c = seg & 7;
            uint32_t d = SWZ128((uint32_t)(row*128 + c*16));
            size_t g = (size_t)(kt*64 + row)*256 + seg*16;
            CP16(stb + panel*8192 + d,         kHb + g);
            CP16(stb + 16384 + panel*8192 + d, kLb + g);
        }
        #pragma unroll
        for (int it = 0; it < 4; it++) {
            int e = it*256 + tid;
            int row = e >> 3, c = e & 7;
            uint32_t d = SWZ128((uint32_t)(row*128 + c*16));
            size_t g = (size_t)row*4096 + (size_t)kt*128 + c*16;
            CP16(stb + 32768 + d, vHb + g);
            CP16(stb + 49152 + d, vLb + g);
        }
    };

    load_kv(0, 0);
    CP_COMMIT();

    float o[16][4];
    #pragma unroll
    for (int t = 0; t < 16; t++)
        #pragma unroll
        for (int c = 0; c < 4; c++) o[t][c] = 0.f;
    float m0 = -1e30f, m1 = -1e30f, l0 = 0.f, l1 = 0.f;

    const float scale = 0.08838834764831845f;
    const int qrow_lo = qt*128 + wid*16;
    const int row0 = qrow_lo + (lid >> 2);
    const int col_in = (lid & 3) * 2;

    const int nkv = 2*qt + 2;
    for (int kt = 0; kt < nkv; kt++) {
        int buf = kt & 1;
        if (kt + 1 < nkv) {
            load_kv(buf ^ 1, kt + 1);
            CP_COMMIT();
            CP_WAIT(1);
        } else {
            CP_WAIT(0);
        }
        __syncthreads();

        bool skip = (kt*64 > qrow_lo + 15);
        if (!skip) {
            uint32_t stb = sb + 32768 + buf*65536;

            float sacc[8][4];
            #pragma unroll
            for (int t = 0; t < 8; t++)
                #pragma unroll
                for (int c = 0; c < 4; c++) sacc[t][c] = 0.f;

            #pragma unroll
            for (int kk = 0; kk < 8; kk++) {
                int panel = kk >> 2;
                int kb = (kk & 3)*32;
                uint32_t qh[4];
                {
                    int rowA = wid*16 + (q & 1)*8 + r8;
                    uint32_t off = SWZ128((uint32_t)(rowA*128 + kb + (q >> 1)*16));
                    LDSM_X4(qh[0],qh[1],qh[2],qh[3], sb + panel*16384 + off);
                }
                #pragma unroll
                for (int j2 = 0; j2 < 4; j2++) {
                    int rowB = j2*16 + (q >> 1)*8 + r8;
                    uint32_t off = SWZ128((uint32_t)(rowB*128 + kb + (q & 1)*16));
                    uint32_t kh[4], kl[4];
                    LDSM_X4(kh[0],kh[1],kh[2],kh[3], stb + panel*8192 + off);
                    LDSM_X4(kl[0],kl[1],kl[2],kl[3], stb + 16384 + panel*8192 + off);
                    MMA16816(sacc[j2*2],   qh, &kh[0]);
                    MMA16816(sacc[j2*2],   qh, &kl[0]);
                    MMA16816(sacc[j2*2+1], qh, &kh[2]);
                    MMA16816(sacc[j2*2+1], qh, &kl[2]);
                }
            }

            #pragma unroll
            for (int t = 0; t < 8; t++)
                #pragma unroll
                for (int c = 0; c < 4; c++) sacc[t][c] *= scale;

            if (kt*64 + 63 > qrow_lo) {
                #pragma unroll
                for (int t = 0; t < 8; t++) {
                    int colg = kt*64 + t*8 + col_in;
                    if (colg   > row0)   sacc[t][0] = -1e30f;
                    if (colg+1 > row0)   sacc[t][1] = -1e30f;
                    if (colg   > row0+8) sacc[t][2] = -1e30f;
                    if (colg+1 > row0+8) sacc[t][3] = -1e30f;
                }
            }

            float mx0 = -1e30f, mx1 = -1e30f;
            #pragma unroll
            for (int t = 0; t < 8; t++) {
                mx0 = fmaxf(mx0, fmaxf(sacc[t][0], sacc[t][1]));
                mx1 = fmaxf(mx1, fmaxf(sacc[t][2], sacc[t][3]));
            }
            mx0 = fmaxf(mx0, __shfl_xor_sync(0xffffffffu, mx0, 1));
            mx0 = fmaxf(mx0, __shfl_xor_sync(0xffffffffu, mx0, 2));
            mx1 = fmaxf(mx1, __shfl_xor_sync(0xffffffffu, mx1, 1));
            mx1 = fmaxf(mx1, __shfl_xor_sync(0xffffffffu, mx1, 2));
            float mn0 = fmaxf(m0, mx0), mn1 = fmaxf(m1, mx1);
            float cr0 = __expf(m0 - mn0), cr1 = __expf(m1 - mn1);
            m0 = mn0; m1 = mn1;

            float s0 = 0.f, s1 = 0.f;
            #pragma unroll
            for (int t = 0; t < 8; t++) {
                sacc[t][0] = __expf(sacc[t][0] - mn0);
                sacc[t][1] = __expf(sacc[t][1] - mn0);
                sacc[t][2] = __expf(sacc[t][2] - mn1);
                sacc[t][3] = __expf(sacc[t][3] - mn1);
                s0 += sacc[t][0] + sacc[t][1];
                s1 += sacc[t][2] + sacc[t][3];
            }
            s0 += __shfl_xor_sync(0xffffffffu, s0, 1);
            s0 += __shfl_xor_sync(0xffffffffu, s0, 2);
            s1 += __shfl_xor_sync(0xffffffffu, s1, 1);
            s1 += __shfl_xor_sync(0xffffffffu, s1, 2);
            l0 = l0*cr0 + s0;
            l1 = l1*cr1 + s1;
            #pragma unroll
            for (int t = 0; t < 16; t++) {
                o[t][0] *= cr0; o[t][1] *= cr0;
                o[t][2] *= cr1; o[t][3] *= cr1;
            }

            uint32_t ph[4][4];
            #pragma unroll
            for (int t = 0; t < 4; t++) {
                #pragma unroll
                for (int u = 0; u < 2; u++) {
                    ph[t][u*2+0] = packh(sacc[2*t+u][0], sacc[2*t+u][1]);
                    ph[t][u*2+1] = packh(sacc[2*t+u][2], sacc[2*t+u][3]);
                }
            }

            #pragma unroll
            for (int ks = 0; ks < 4; ks++) {
                int kb = ks*32;
                #pragma unroll
                for (int j2 = 0; j2 < 8; j2++) {
                    int rowB = j2*16 + (q >> 1)*8 + r8;
                    uint32_t off = SWZ128((uint32_t)(rowB*128 + kb + (q & 1)*16));
                    uint32_t vh[4], vl[4];
                    LDSM_X4(vh[0],vh[1],vh[2],vh[3], stb + 32768 + off);
                    LDSM_X4(vl[0],vl[1],vl[2],vl[3], stb + 49152 + off);
                    MMA16816(o[j2*2],   ph[ks], &vh[0]);
                    MMA16816(o[j2*2],   ph[ks], &vl[0]);
                    MMA16816(o[j2*2+1], ph[ks], &vh[2]);
                    MMA16816(o[j2*2+1], ph[ks], &vl[2]);
                }
            }
        }
        __syncthreads();
    }

    // ---- normalize + write Ctx as fp16 ----
    float inv0 = 1.0f / l0, inv1 = 1.0f / l1;
    size_t off0 = ((size_t)b*S_LEN + row0)     * HID + h*DH + col_in;
    size_t off1 = ((size_t)b*S_LEN + row0 + 8) * HID + h*DH + col_in;
    #pragma unroll
    for (int t = 0; t < 16; t++) {
        *(__half2*)(g_CtxH + off0 + t*8) =
            __half2{__float2half(o[t][0]*inv0), __float2half(o[t][1]*inv0)};
        *(__half2*)(g_CtxH + off1 + t*8) =
            __half2{__float2half(o[t][2]*inv1), __float2half(o[t][3]*inv1)};
    }
}

// ---------------- launch ----------------
extern "C" void kernel_launch(void* const* d_in, const int* in_sizes, int n_in,
                              void* d_out, int out_size)
{
    const float* hs = (const float*)d_in[0];
    const float* Wq = (const float*)d_in[1];
    const float* Wk = (const float*)d_in[2];
    const float* Wv = (const float*)d_in[3];
    const float* Wo = (const float*)d_in[4];
    const int* pos  = (const int*)d_in[6];
    float* out = (float*)d_out;

    float *Qp, *Kp, *Vp;
    cudaGetSymbolAddress((void**)&Qp, g_Q);
    cudaGetSymbolAddress((void**)&Kp, g_K);
    cudaGetSymbolAddress((void**)&Vp, g_V);

    __half *hsH,*WqH,*WqL,*WkH,*WkL,*WvH,*WvL,*WoH,*WoL,*CtxH;
    cudaGetSymbolAddress((void**)&hsH, g_hsH);
    cudaGetSymbolAddress((void**)&WqH, g_WqH);  cudaGetSymbolAddress((void**)&WqL, g_WqL);
    cudaGetSymbolAddress((void**)&WkH, g_WkH);  cudaGetSymbolAddress((void**)&WkL, g_WkL);
    cudaGetSymbolAddress((void**)&WvH, g_WvH);  cudaGetSymbolAddress((void**)&WvL, g_WvL);
    cudaGetSymbolAddress((void**)&WoH, g_WoH);  cudaGetSymbolAddress((void**)&WoL, g_WoL);
    cudaGetSymbolAddress((void**)&CtxH, g_CtxH);

    const int NELEM = NROWS*HID;
    const int SPLIT_BLOCKS = NELEM/4/256;

    conv_h_kernel<<<SPLIT_BLOCKS, 256>>>(hs, hsH);
    split_h_kernel<<<SPLIT_BLOCKS, 256>>>(Wq, WqH, WqL);
    split_h_kernel<<<SPLIT_BLOCKS, 256>>>(Wk, WkH, WkL);
    split_h_kernel<<<SPLIT_BLOCKS, 256>>>(Wv, WvH, WvL);
    split_h_kernel<<<SPLIT_BLOCKS, 256>>>(Wo, WoH, WoL);

    cudaFuncSetAttribute(gemm_mma, cudaFuncAttributeMaxDynamicSharedMemorySize, GT_SMEM_TOTAL);
    dim3 ggrid(HID/128, NROWS/128);   // 32 x 32

    gemm_mma<<<ggrid, 256, GT_SMEM_TOTAL>>>(hsH, WqH, WqL, Qp, 1);
    gemm_mma<<<ggrid, 256, GT_SMEM_TOTAL>>>(hsH, WkH, WkL, Kp, 1);
    gemm_mma<<<ggrid, 256, GT_SMEM_TOTAL>>>(hsH, WvH, WvL, Vp, 1);

    rope_table_kernel<<<(S_LEN*64)/256, 256>>>(pos);
    rope_apply_split_kernel<<<(NBH*S_LEN*64)/256, 256>>>();
    vt_split_kernel<<<dim3(S_LEN/32, DH/32, NBH), dim3(32,8)>>>();

    cudaFuncSetAttribute(attn_mma, cudaFuncAttributeMaxDynamicSharedMemorySize, AT2_SMEM);
    attn_mma<<<dim3(S_LEN/128, HEADS, BATCH), 256, AT2_SMEM>>>();

    gemm_mma<<<ggrid, 256, GT_SMEM_TOTAL>>>(CtxH, WoH, WoL, out, 0);
}

// round 9
// speedup vs baseline: 2.4674x; 1.0522x over previous
#include <cuda_runtime.h>
#include <cuda_fp16.h>
#include <math.h>
#include <cstdint>

#define HEADS 32
#define S_LEN 2048
#define BATCH 2
#define HID   4096
#define DH    128
#define NROWS (BATCH*S_LEN)   // 4096
#define NBH   (BATCH*HEADS)   // 64

// ---------------- scratch (static __device__, no allocs) ----------------
__device__ float g_Q[(size_t)NBH*S_LEN*DH];
__device__ float g_K[(size_t)NBH*S_LEN*DH];
__device__ float g_V[(size_t)NBH*S_LEN*DH];
__device__ float g_cos[S_LEN*64];
__device__ float g_sin[S_LEN*64];

__device__ __half g_hsH[(size_t)NROWS*HID];                    // activations: fp16 only
__device__ __half g_WqH[(size_t)HID*HID],  g_WqL[(size_t)HID*HID];
__device__ __half g_WkH[(size_t)HID*HID],  g_WkL[(size_t)HID*HID];
__device__ __half g_WvH[(size_t)HID*HID],  g_WvL[(size_t)HID*HID];
__device__ __half g_WoH[(size_t)HID*HID],  g_WoL[(size_t)HID*HID];
__device__ __half g_CtxH[(size_t)NROWS*HID];                   // attention out: fp16 only
__device__ __half g_QH[(size_t)NBH*S_LEN*DH];                  // Q: fp16 only
__device__ __half g_KH[(size_t)NBH*S_LEN*DH], g_KL[(size_t)NBH*S_LEN*DH];
__device__ __half g_VtH[(size_t)NBH*DH*S_LEN];                 // [bh][dh][s], fp16 only

// ---------------- helpers ----------------
__device__ __forceinline__ uint32_t smem_u32(const void* p) {
    uint32_t a;
    asm("{ .reg .u64 t; cvta.to.shared.u64 t, %1; cvt.u32.u64 %0, t; }" : "=r"(a) : "l"(p));
    return a;
}
#define CP16(dst, src)    asm volatile("cp.async.cg.shared.global [%0], [%1], 16;" :: "r"(dst), "l"(src) : "memory")
#define CP_COMMIT()       asm volatile("cp.async.commit_group;" ::: "memory")
#define CP_WAIT(n)        asm volatile("cp.async.wait_group %0;" :: "n"(n) : "memory")

#define LDSM_X4(r0,r1,r2,r3,a) \
    asm volatile("ldmatrix.sync.aligned.m8n8.x4.shared.b16 {%0,%1,%2,%3}, [%4];" \
        : "=r"(r0),"=r"(r1),"=r"(r2),"=r"(r3) : "r"(a))

#define MMA16816(d, a, b) \
    asm volatile("mma.sync.aligned.m16n8k16.row.col.f32.f16.f16.f32 " \
        "{%0,%1,%2,%3}, {%4,%5,%6,%7}, {%8,%9}, {%0,%1,%2,%3};" \
        : "+f"((d)[0]),"+f"((d)[1]),"+f"((d)[2]),"+f"((d)[3]) \
        : "r"((a)[0]),"r"((a)[1]),"r"((a)[2]),"r"((a)[3]), "r"((b)[0]),"r"((b)[1]))

#define SWZ128(x) ((x) ^ (((x) >> 3) & 0x70))

__device__ __forceinline__ uint32_t packh(float lo, float hi) {
    uint32_t r;   // first src operand -> high half
    asm("cvt.rn.f16x2.f32 %0, %1, %2;" : "=r"(r) : "f"(hi), "f"(lo));
    return r;
}

// ---------------- fp32 -> fp16 convert (activations) ----------------
__global__ void conv_h_kernel(const float* __restrict__ src, __half* __restrict__ dst)
{
    int i = (blockIdx.x*blockDim.x + threadIdx.x) * 4;
    float4 v = *(const float4*)(src + i);
    *(__half2*)(dst + i)     = __half2{__float2half(v.x), __float2half(v.y)};
    *(__half2*)(dst + i + 2) = __half2{__float2half(v.z), __float2half(v.w)};
}

// ---------------- fp32 -> fp16 hi/lo split (weights) ----------------
__global__ void split_h_kernel(const float* __restrict__ src,
                               __half* __restrict__ hi, __half* __restrict__ lo)
{
    int i = (blockIdx.x*blockDim.x + threadIdx.x) * 4;
    float4 v = *(const float4*)(src + i);
    __half h0 = __float2half(v.x), h1 = __float2half(v.y);
    __half h2 = __float2half(v.z), h3 = __float2half(v.w);
    *(__half2*)(hi + i)     = __half2{h0, h1};
    *(__half2*)(hi + i + 2) = __half2{h2, h3};
    *(__half2*)(lo + i)     = __half2{__float2half(v.x - __half2float(h0)),
                                      __float2half(v.y - __half2float(h1))};
    *(__half2*)(lo + i + 2) = __half2{__float2half(v.z - __half2float(h2)),
                                      __float2half(v.w - __half2float(h3))};
}

// ---------------- HMMA GEMM: C[M,N] = A @ (Bh+Bl)^T, 128x128 tile ----------
// smem/stage: Ah 16K | Bh 16K | Bl 16K = 48K; double buffered = 96K; 2 CTAs/SM
#define GT_STAGE_BYTES 49152
#define GT_SMEM_TOTAL  (2*GT_STAGE_BYTES)

__global__ __launch_bounds__(256, 2) void gemm_mma(
    const __half* __restrict__ Ah,
    const __half* __restrict__ Bh, const __half* __restrict__ Bl,
    float* __restrict__ C, int splitHeads)
{
    extern __shared__ char smem[];
    const uint32_t sb = smem_u32(smem);
    const int tid = threadIdx.x, wid = tid >> 5, lid = tid & 31;
    const int bm = blockIdx.y * 128, bn = blockIdx.x * 128;
    const int wm = (wid >> 2) * 64, wn = (wid & 3) * 32;

    const char* aH = (const char*)Ah + (size_t)bm * (HID*2);
    const char* bH = (const char*)Bh + (size_t)bn * (HID*2);
    const char* bL = (const char*)Bl + (size_t)bn * (HID*2);

    int srow[4], scol[4];
    #pragma unroll
    for (int j = 0; j < 4; j++) {
        int sidx = j*256 + tid;
        srow[j] = sidx >> 3;
        scol[j] = (sidx & 7) * 16;
    }

    auto load_chunk = [&](int stage, int chunk) {
        uint32_t st = sb + stage * GT_STAGE_BYTES;
        size_t off = (size_t)chunk * 128;
        #pragma unroll
        for (int j = 0; j < 4; j++) {
            uint32_t d = SWZ128((uint32_t)(srow[j]*128 + scol[j]));
            size_t g = (size_t)srow[j] * (HID*2) + off + scol[j];
            CP16(st +     0 + d, aH + g);
            CP16(st + 16384 + d, bH + g);
            CP16(st + 32768 + d, bL + g);
        }
    };

    float acc[4][4][4];
    #pragma unroll
    for (int i = 0; i < 4; i++)
        #pragma unroll
        for (int j = 0; j < 4; j++)
            #pragma unroll
            for (int c = 0; c < 4; c++) acc[i][j][c] = 0.f;

    const int q  = lid >> 3;
    const int r8 = lid & 7;

    load_chunk(0, 0);
    CP_COMMIT();

    const int NCHUNK = HID / 64;
    for (int chunk = 0; chunk < NCHUNK; chunk++) {
        int buf = chunk & 1;
        if (chunk + 1 < NCHUNK) {
            load_chunk(buf ^ 1, chunk + 1);
            CP_COMMIT();
            CP_WAIT(1);
        } else {
            CP_WAIT(0);
        }
        __syncthreads();

        uint32_t stA  = sb + buf * GT_STAGE_BYTES;
        uint32_t stBh = stA + 16384, stBl = stA + 32768;

        #pragma unroll
        for (int kk = 0; kk < 4; kk++) {
            uint32_t ah[16];
            #pragma unroll
            for (int i = 0; i < 4; i++) {
                int rowA = wm + i*16 + (q & 1)*8 + r8;
                int kb   = kk*32 + (q >> 1)*16;
                uint32_t off = SWZ128((uint32_t)(rowA*128 + kb));
                LDSM_X4(ah[i*4+0], ah[i*4+1], ah[i*4+2], ah[i*4+3], stA + off);
            }
            #pragma unroll
            for (int j2 = 0; j2 < 2; j2++) {
                int rowB = wn + j2*16 + (q >> 1)*8 + r8;
                int kb   = kk*32 + (q & 1)*16;
                uint32_t off = SWZ128((uint32_t)(rowB*128 + kb));
                uint32_t bh[4], bl[4];
                LDSM_X4(bh[0],bh[1],bh[2],bh[3], stBh + off);
                LDSM_X4(bl[0],bl[1],bl[2],bl[3], stBl + off);
                #pragma unroll
                for (int i = 0; i < 4; i++) {
                    MMA16816(acc[i][j2*2],   &ah[i*4], &bh[0]);
                    MMA16816(acc[i][j2*2],   &ah[i*4], &bl[0]);
                    MMA16816(acc[i][j2*2+1], &ah[i*4], &bh[2]);
                    MMA16816(acc[i][j2*2+1], &ah[i*4], &bl[2]);
                }
            }
        }
        __syncthreads();
    }

    const int gr = lid >> 2;
    const int gc = (lid & 3) * 2;
    #pragma unroll
    for (int i = 0; i < 4; i++) {
        #pragma unroll
        for (int half = 0; half < 2; half++) {
            int row = bm + wm + i*16 + gr + half*8;
            #pragma unroll
            for (int j = 0; j < 4; j++) {
                int col = wn + j*8 + gc;
                float2 v = half ? make_float2(acc[i][j][2], acc[i][j][3])
                                : make_float2(acc[i][j][0], acc[i][j][1]);
                float* op;
                if (splitHeads) {
                    int b = row >> 11, s = row & (S_LEN-1);
                    int h = blockIdx.x;
                    op = C + ((((size_t)(b*HEADS + h))*S_LEN + s) << 7) + col;
                } else {
                    op = C + (size_t)row * HID + bn + col;
                }
                *(float2*)op = v;
            }
        }
    }
}

// ---------------- RoPE ----------------
__global__ void rope_table_kernel(const int* __restrict__ pos_ids)
{
    int idx = blockIdx.x*blockDim.x + threadIdx.x;
    int i = idx & 63;
    int s = idx >> 6;
    float pos = (float)pos_ids[s];
    double invf = pow(10000.0, -(double)(2*i) / 128.0);
    float ang = pos * (float)invf;
    float sn, cs;
    sincosf(ang, &sn, &cs);
    g_cos[idx] = cs;
    g_sin[idx] = sn;
}

// rope + emit Q fp16 (single) and K fp16 hi/lo
__global__ void rope_apply_split_kernel()
{
    int idx = blockIdx.x*blockDim.x + threadIdx.x;
    int i  = idx & 63;
    int s  = (idx >> 6) & (S_LEN-1);
    int bh = idx >> 17;
    float cs = g_cos[(s<<6) + i];
    float sn = g_sin[(s<<6) + i];
    size_t base = (((size_t)bh * S_LEN + s) << 7) + i;

    float q0 = g_Q[base], q1 = g_Q[base+64];
    g_QH[base]    = __float2half(q0*cs - q1*sn);
    g_QH[base+64] = __float2half(q1*cs + q0*sn);

    float k0 = g_K[base], k1 = g_K[base+64];
    float ka = k0*cs - k1*sn;
    float kb = k1*cs + k0*sn;
    __half h;
    h = __float2half(ka); g_KH[base]    = h; g_KL[base]    = __float2half(ka - __half2float(h));
    h = __float2half(kb); g_KH[base+64] = h; g_KL[base+64] = __float2half(kb - __half2float(h));
}

// ---------------- V transpose (fp16 only) ----------------
__global__ void vt_split_kernel()
{
    __shared__ float tile[32][33];
    int xs = blockIdx.x * 32;
    int dd = blockIdx.y * 32;
    int bh = blockIdx.z;
    int tx = threadIdx.x, ty = threadIdx.y;

    const float* V = g_V + ((size_t)bh * S_LEN) * DH;
    #pragma unroll
    for (int j = 0; j < 4; j++)
        tile[ty + j*8][tx] = V[(size_t)(xs + ty + j*8)*DH + dd + tx];
    __syncthreads();
    #pragma unroll
    for (int j = 0; j < 4; j++) {
        float v = tile[tx][ty + j*8];
        size_t o = ((size_t)bh*DH + dd + ty + j*8) * S_LEN + xs + tx;
        g_VtH[o] = __float2half(v);
    }
}

// ---------------- HMMA flash attention (fp16; S 2-product, PV 1-product) ----
// smem: Q 2x16K | 2 stages x { Kh 2x8K, Kl 2x8K, VtH 16K } = 32K + 96K
#define AT_STAGE 49152
#define AT2_SMEM (32768 + 2*AT_STAGE)

__global__ __launch_bounds__(256, 1) void attn_mma()
{
    extern __shared__ char smem[];
    const uint32_t sb = smem_u32(smem);
    const int tid = threadIdx.x, wid = tid >> 5, lid = tid & 31;
    const int qt = gridDim.x - 1 - blockIdx.x;     // largest q-tiles first
    const int h = blockIdx.y, b = blockIdx.z;
    const size_t bh = (size_t)b*HEADS + h;
    const int q  = lid >> 3;
    const int r8 = lid & 7;

    const char* qHb = (const char*)g_QH + (bh*S_LEN + (size_t)qt*128) * 256;
    const char* kHb = (const char*)g_KH + bh*S_LEN*256;
    const char* kLb = (const char*)g_KL + bh*S_LEN*256;
    const char* vHb = (const char*)g_VtH + bh*DH*(size_t)S_LEN*2;

    #pragma unroll
    for (int it = 0; it < 8; it++) {
        int e = it*256 + tid;
        int row = e >> 4, seg = e & 15;
        int panel = seg >> 3, c = seg & 7;
        uint32_t d = SWZ128((uint32_t)(row*128 + c*16));
        CP16(sb + panel*16384 + d, qHb + row*256 + seg*16);
    }

    auto load_kv = [&](int st, int kt) {
        uint32_t stb = sb + 32768 + st*AT_STAGE;
        #pragma unroll
        for (int it = 0; it < 4; it++) {
            int e = it*256 + tid;
            int row = e >> 4, seg = e & 15;
            int panel = seg >> 3, c = seg & 7;
            uint32_t d = SWZ128((uint32_t)(row*128 + c*16));
            size_t g = (size_t)(kt*64 + row)*256 + seg*16;
            CP16(stb + panel*8192 + d,         kHb + g);
            CP16(stb + 16384 + panel*8192 + d, kLb + g);
        }
        #pragma unroll
        for (int it = 0; it < 4; it++) {
            int e = it*256 + tid;
            int row = e >> 3, c = e & 7;
            uint32_t d = SWZ128((uint32_t)(row*128 + c*16));
            size_t g = (size_t)row*4096 + (size_t)kt*128 + c*16;
            CP16(stb + 32768 + d, vHb + g);
        }
    };

    load_kv(0, 0);
    CP_COMMIT();

    float o[16][4];
    #pragma unroll
    for (int t = 0; t < 16; t++)
        #pragma unroll
        for (int c = 0; c < 4; c++) o[t][c] = 0.f;
    float m0 = -1e30f, m1 = -1e30f, l0 = 0.f, l1 = 0.f;

    const float scale = 0.08838834764831845f;
    const int qrow_lo = qt*128 + wid*16;
    const int row0 = qrow_lo + (lid >> 2);
    const int col_in = (lid & 3) * 2;

    const int nkv = 2*qt + 2;
    for (int kt = 0; kt < nkv; kt++) {
        int buf = kt & 1;
        if (kt + 1 < nkv) {
            load_kv(buf ^ 1, kt + 1);
            CP_COMMIT();
            CP_WAIT(1);
        } else {
            CP_WAIT(0);
        }
        __syncthreads();

        bool skip = (kt*64 > qrow_lo + 15);
        if (!skip) {
            uint32_t stb = sb + 32768 + buf*AT_STAGE;

            float sacc[8][4];
            #pragma unroll
            for (int t = 0; t < 8; t++)
                #pragma unroll
                for (int c = 0; c < 4; c++) sacc[t][c] = 0.f;

            #pragma unroll
            for (int kk = 0; kk < 8; kk++) {
                int panel = kk >> 2;
                int kb = (kk & 3)*32;
                uint32_t qh[4];
                {
                    int rowA = wid*16 + (q & 1)*8 + r8;
                    uint32_t off = SWZ128((uint32_t)(rowA*128 + kb + (q >> 1)*16));
                    LDSM_X4(qh[0],qh[1],qh[2],qh[3], sb + panel*16384 + off);
                }
                #pragma unroll
                for (int j2 = 0; j2 < 4; j2++) {
                    int rowB = j2*16 + (q >> 1)*8 + r8;
                    uint32_t off = SWZ128((uint32_t)(rowB*128 + kb + (q & 1)*16));
                    uint32_t kh[4], kl[4];
                    LDSM_X4(kh[0],kh[1],kh[2],kh[3], stb + panel*8192 + off);
                    LDSM_X4(kl[0],kl[1],kl[2],kl[3], stb + 16384 + panel*8192 + off);
                    MMA16816(sacc[j2*2],   qh, &kh[0]);
                    MMA16816(sacc[j2*2],   qh, &kl[0]);
                    MMA16816(sacc[j2*2+1], qh, &kh[2]);
                    MMA16816(sacc[j2*2+1], qh, &kl[2]);
                }
            }

            #pragma unroll
            for (int t = 0; t < 8; t++)
                #pragma unroll
                for (int c = 0; c < 4; c++) sacc[t][c] *= scale;

            if (kt*64 + 63 > qrow_lo) {
                #pragma unroll
                for (int t = 0; t < 8; t++) {
                    int colg = kt*64 + t*8 + col_in;
                    if (colg   > row0)   sacc[t][0] = -1e30f;
                    if (colg+1 > row0)   sacc[t][1] = -1e30f;
                    if (colg   > row0+8) sacc[t][2] = -1e30f;
                    if (colg+1 > row0+8) sacc[t][3] = -1e30f;
                }
            }

            float mx0 = -1e30f, mx1 = -1e30f;
            #pragma unroll
            for (int t = 0; t < 8; t++) {
                mx0 = fmaxf(mx0, fmaxf(sacc[t][0], sacc[t][1]));
                mx1 = fmaxf(mx1, fmaxf(sacc[t][2], sacc[t][3]));
            }
            mx0 = fmaxf(mx0, __shfl_xor_sync(0xffffffffu, mx0, 1));
            mx0 = fmaxf(mx0, __shfl_xor_sync(0xffffffffu, mx0, 2));
            mx1 = fmaxf(mx1, __shfl_xor_sync(0xffffffffu, mx1, 1));
            mx1 = fmaxf(mx1, __shfl_xor_sync(0xffffffffu, mx1, 2));
            float mn0 = fmaxf(m0, mx0), mn1 = fmaxf(m1, mx1);
            float cr0 = __expf(m0 - mn0), cr1 = __expf(m1 - mn1);
            m0 = mn0; m1 = mn1;

            float s0 = 0.f, s1 = 0.f;
            #pragma unroll
            for (int t = 0; t < 8; t++) {
                sacc[t][0] = __expf(sacc[t][0] - mn0);
                sacc[t][1] = __expf(sacc[t][1] - mn0);
                sacc[t][2] = __expf(sacc[t][2] - mn1);
                sacc[t][3] = __expf(sacc[t][3] - mn1);
                s0 += sacc[t][0] + sacc[t][1];
                s1 += sacc[t][2] + sacc[t][3];
            }
            s0 += __shfl_xor_sync(0xffffffffu, s0, 1);
            s0 += __shfl_xor_sync(0xffffffffu, s0, 2);
            s1 += __shfl_xor_sync(0xffffffffu, s1, 1);
            s1 += __shfl_xor_sync(0xffffffffu, s1, 2);
            l0 = l0*cr0 + s0;
            l1 = l1*cr1 + s1;
            #pragma unroll
            for (int t = 0; t < 16; t++) {
                o[t][0] *= cr0; o[t][1] *= cr0;
                o[t][2] *= cr1; o[t][3] *= cr1;
            }

            uint32_t ph[4][4];
            #pragma unroll
            for (int t = 0; t < 4; t++) {
                #pragma unroll
                for (int u = 0; u < 2; u++) {
                    ph[t][u*2+0] = packh(sacc[2*t+u][0], sacc[2*t+u][1]);
                    ph[t][u*2+1] = packh(sacc[2*t+u][2], sacc[2*t+u][3]);
                }
            }

            #pragma unroll
            for (int ks = 0; ks < 4; ks++) {
                int kb = ks*32;
                #pragma unroll
                for (int j2 = 0; j2 < 8; j2++) {
                    int rowB = j2*16 + (q >> 1)*8 + r8;
                    uint32_t off = SWZ128((uint32_t)(rowB*128 + kb + (q & 1)*16));
                    uint32_t vh[4];
                    LDSM_X4(vh[0],vh[1],vh[2],vh[3], stb + 32768 + off);
                    MMA16816(o[j2*2],   ph[ks], &vh[0]);
                    MMA16816(o[j2*2+1], ph[ks], &vh[2]);
                }
            }
        }
        __syncthreads();
    }

    // ---- normalize + write Ctx as fp16 ----
    float inv0 = 1.0f / l0, inv1 = 1.0f / l1;
    size_t off0 = ((size_t)b*S_LEN + row0)     * HID + h*DH + col_in;
    size_t off1 = ((size_t)b*S_LEN + row0 + 8) * HID + h*DH + col_in;
    #pragma unroll
    for (int t = 0; t < 16; t++) {
        *(__half2*)(g_CtxH + off0 + t*8) =
            __half2{__float2half(o[t][0]*inv0), __float2half(o[t][1]*inv0)};
        *(__half2*)(g_CtxH + off1 + t*8) =
            __half2{__float2half(o[t][2]*inv1), __float2half(o[t][3]*inv1)};
    }
}

// ---------------- launch ----------------
extern "C" void kernel_launch(void* const* d_in, const int* in_sizes, int n_in,
                              void* d_out, int out_size)
{
    const float* hs = (const float*)d_in[0];
    const float* Wq = (const float*)d_in[1];
    const float* Wk = (const float*)d_in[2];
    const float* Wv = (const float*)d_in[3];
    const float* Wo = (const float*)d_in[4];
    const int* pos  = (const int*)d_in[6];
    float* out = (float*)d_out;

    float *Qp, *Kp, *Vp;
    cudaGetSymbolAddress((void**)&Qp, g_Q);
    cudaGetSymbolAddress((void**)&Kp, g_K);
    cudaGetSymbolAddress((void**)&Vp, g_V);

    __half *hsH,*WqH,*WqL,*WkH,*WkL,*WvH,*WvL,*WoH,*WoL,*CtxH;
    cudaGetSymbolAddress((void**)&hsH, g_hsH);
    cudaGetSymbolAddress((void**)&WqH, g_WqH);  cudaGetSymbolAddress((void**)&WqL, g_WqL);
    cudaGetSymbolAddress((void**)&WkH, g_WkH);  cudaGetSymbolAddress((void**)&WkL, g_WkL);
    cudaGetSymbolAddress((void**)&WvH, g_WvH);  cudaGetSymbolAddress((void**)&WvL, g_WvL);
    cudaGetSymbolAddress((void**)&WoH, g_WoH);  cudaGetSymbolAddress((void**)&WoL, g_WoL);
    cudaGetSymbolAddress((void**)&CtxH, g_CtxH);

    const int NELEM = NROWS*HID;
    const int SPLIT_BLOCKS = NELEM/4/256;

    conv_h_kernel<<<SPLIT_BLOCKS, 256>>>(hs, hsH);
    split_h_kernel<<<SPLIT_BLOCKS, 256>>>(Wq, WqH, WqL);
    split_h_kernel<<<SPLIT_BLOCKS, 256>>>(Wk, WkH, WkL);
    split_h_kernel<<<SPLIT_BLOCKS, 256>>>(Wv, WvH, WvL);
    split_h_kernel<<<SPLIT_BLOCKS, 256>>>(Wo, WoH, WoL);

    cudaFuncSetAttribute(gemm_mma, cudaFuncAttributeMaxDynamicSharedMemorySize, GT_SMEM_TOTAL);
    dim3 ggrid(HID/128, NROWS/128);   // 32 x 32

    gemm_mma<<<ggrid, 256, GT_SMEM_TOTAL>>>(hsH, WqH, WqL, Qp, 1);
    gemm_mma<<<ggrid, 256, GT_SMEM_TOTAL>>>(hsH, WkH, WkL, Kp, 1);
    gemm_mma<<<ggrid, 256, GT_SMEM_TOTAL>>>(hsH, WvH, WvL, Vp, 1);

    rope_table_kernel<<<(S_LEN*64)/256, 256>>>(pos);
    rope_apply_split_kernel<<<(NBH*S_LEN*64)/256, 256>>>();
    vt_split_kernel<<<dim3(S_LEN/32, DH/32, NBH), dim3(32,8)>>>();

    cudaFuncSetAttribute(attn_mma, cudaFuncAttributeMaxDynamicSharedMemorySize, AT2_SMEM);
    attn_mma<<<dim3(S_LEN/128, HEADS, BATCH), 256, AT2_SMEM>>>();

    gemm_mma<<<ggrid, 256, GT_SMEM_TOTAL>>>(CtxH, WoH, WoL, out, 0);
}

// round 10
// speedup vs baseline: 3.1301x; 1.2686x over previous
#include <cuda_runtime.h>
#include <cuda_fp16.h>
#include <math.h>
#include <cstdint>

#define HEADS 32
#define S_LEN 2048
#define BATCH 2
#define HID   4096
#define DH    128
#define NROWS (BATCH*S_LEN)   // 4096
#define NBH   (BATCH*HEADS)   // 64

// ---------------- scratch (static __device__, no allocs) ----------------
__device__ float g_Q[(size_t)NBH*S_LEN*DH];
__device__ float g_K[(size_t)NBH*S_LEN*DH];
__device__ float g_V[(size_t)NBH*S_LEN*DH];
__device__ float g_cos[S_LEN*64];
__device__ float g_sin[S_LEN*64];

__device__ __half g_hsH[(size_t)NROWS*HID];                    // activations: fp16 only
__device__ __half g_WqH[(size_t)HID*HID];                      // Q weights: fp16 only
__device__ __half g_WkH[(size_t)HID*HID],  g_WkL[(size_t)HID*HID];
__device__ __half g_WvH[(size_t)HID*HID];                      // V weights: fp16 only
__device__ __half g_WoH[(size_t)HID*HID],  g_WoL[(size_t)HID*HID];
__device__ __half g_CtxH[(size_t)NROWS*HID];                   // attention out: fp16 only
__device__ __half g_QH[(size_t)NBH*S_LEN*DH];                  // Q: fp16 only
__device__ __half g_KH[(size_t)NBH*S_LEN*DH], g_KL[(size_t)NBH*S_LEN*DH];
__device__ __half g_VtH[(size_t)NBH*DH*S_LEN];                 // [bh][dh][s], fp16 only

// ---------------- helpers ----------------
__device__ __forceinline__ uint32_t smem_u32(const void* p) {
    uint32_t a;
    asm("{ .reg .u64 t; cvta.to.shared.u64 t, %1; cvt.u32.u64 %0, t; }" : "=r"(a) : "l"(p));
    return a;
}
#define CP16(dst, src)    asm volatile("cp.async.cg.shared.global [%0], [%1], 16;" :: "r"(dst), "l"(src) : "memory")
#define CP_COMMIT()       asm volatile("cp.async.commit_group;" ::: "memory")
#define CP_WAIT(n)        asm volatile("cp.async.wait_group %0;" :: "n"(n) : "memory")

#define LDSM_X4(r0,r1,r2,r3,a) \
    asm volatile("ldmatrix.sync.aligned.m8n8.x4.shared.b16 {%0,%1,%2,%3}, [%4];" \
        : "=r"(r0),"=r"(r1),"=r"(r2),"=r"(r3) : "r"(a))

#define MMA16816(d, a, b) \
    asm volatile("mma.sync.aligned.m16n8k16.row.col.f32.f16.f16.f32 " \
        "{%0,%1,%2,%3}, {%4,%5,%6,%7}, {%8,%9}, {%0,%1,%2,%3};" \
        : "+f"((d)[0]),"+f"((d)[1]),"+f"((d)[2]),"+f"((d)[3]) \
        : "r"((a)[0]),"r"((a)[1]),"r"((a)[2]),"r"((a)[3]), "r"((b)[0]),"r"((b)[1]))

#define SWZ128(x) ((x) ^ (((x) >> 3) & 0x70))

__device__ __forceinline__ uint32_t packh(float lo, float hi) {
    uint32_t r;   // first src operand -> high half
    asm("cvt.rn.f16x2.f32 %0, %1, %2;" : "=r"(r) : "f"(hi), "f"(lo));
    return r;
}

// ---------------- fp32 -> fp16 convert ----------------
__global__ void conv_h_kernel(const float* __restrict__ src, __half* __restrict__ dst)
{
    int i = (blockIdx.x*blockDim.x + threadIdx.x) * 4;
    float4 v = *(const float4*)(src + i);
    *(__half2*)(dst + i)     = __half2{__float2half(v.x), __float2half(v.y)};
    *(__half2*)(dst + i + 2) = __half2{__float2half(v.z), __float2half(v.w)};
}

// ---------------- fp32 -> fp16 hi/lo split ----------------
__global__ void split_h_kernel(const float* __restrict__ src,
                               __half* __restrict__ hi, __half* __restrict__ lo)
{
    int i = (blockIdx.x*blockDim.x + threadIdx.x) * 4;
    float4 v = *(const float4*)(src + i);
    __half h0 = __float2half(v.x), h1 = __float2half(v.y);
    __half h2 = __float2half(v.z), h3 = __float2half(v.w);
    *(__half2*)(hi + i)     = __half2{h0, h1};
    *(__half2*)(hi + i + 2) = __half2{h2, h3};
    *(__half2*)(lo + i)     = __half2{__float2half(v.x - __half2float(h0)),
                                      __float2half(v.y - __half2float(h1))};
    *(__half2*)(lo + i + 2) = __half2{__float2half(v.z - __half2float(h2)),
                                      __float2half(v.w - __half2float(h3))};
}

// ---------------- HMMA GEMM, 2-product: C = A @ (Bh+Bl)^T ----------------
#define GT2_STAGE 49152
#define GT2_SMEM  (2*GT2_STAGE)

__global__ __launch_bounds__(256, 2) void gemm_mma2(
    const __half* __restrict__ Ah,
    const __half* __restrict__ Bh, const __half* __restrict__ Bl,
    float* __restrict__ C, int splitHeads)
{
    extern __shared__ char smem[];
    const uint32_t sb = smem_u32(smem);
    const int tid = threadIdx.x, wid = tid >> 5, lid = tid & 31;
    const int bm = blockIdx.y * 128, bn = blockIdx.x * 128;
    const int wm = (wid >> 2) * 64, wn = (wid & 3) * 32;

    const char* aH = (const char*)Ah + (size_t)bm * (HID*2);
    const char* bH = (const char*)Bh + (size_t)bn * (HID*2);
    const char* bL = (const char*)Bl + (size_t)bn * (HID*2);

    int srow[4], scol[4];
    #pragma unroll
    for (int j = 0; j < 4; j++) {
        int sidx = j*256 + tid;
        srow[j] = sidx >> 3;
        scol[j] = (sidx & 7) * 16;
    }

    auto load_chunk = [&](int stage, int chunk) {
        uint32_t st = sb + stage * GT2_STAGE;
        size_t off = (size_t)chunk * 128;
        #pragma unroll
        for (int j = 0; j < 4; j++) {
            uint32_t d = SWZ128((uint32_t)(srow[j]*128 + scol[j]));
            size_t g = (size_t)srow[j] * (HID*2) + off + scol[j];
            CP16(st +     0 + d, aH + g);
            CP16(st + 16384 + d, bH + g);
            CP16(st + 32768 + d, bL + g);
        }
    };

    float acc[4][4][4];
    #pragma unroll
    for (int i = 0; i < 4; i++)
        #pragma unroll
        for (int j = 0; j < 4; j++)
            #pragma unroll
            for (int c = 0; c < 4; c++) acc[i][j][c] = 0.f;

    const int q  = lid >> 3;
    const int r8 = lid & 7;

    load_chunk(0, 0);
    CP_COMMIT();

    const int NCHUNK = HID / 64;
    for (int chunk = 0; chunk < NCHUNK; chunk++) {
        int buf = chunk & 1;
        if (chunk + 1 < NCHUNK) {
            load_chunk(buf ^ 1, chunk + 1);
            CP_COMMIT();
            CP_WAIT(1);
        } else {
            CP_WAIT(0);
        }
        __syncthreads();

        uint32_t stA  = sb + buf * GT2_STAGE;
        uint32_t stBh = stA + 16384, stBl = stA + 32768;

        #pragma unroll
        for (int kk = 0; kk < 4; kk++) {
            uint32_t ah[16];
            #pragma unroll
            for (int i = 0; i < 4; i++) {
                int rowA = wm + i*16 + (q & 1)*8 + r8;
                int kb   = kk*32 + (q >> 1)*16;
                uint32_t off = SWZ128((uint32_t)(rowA*128 + kb));
                LDSM_X4(ah[i*4+0], ah[i*4+1], ah[i*4+2], ah[i*4+3], stA + off);
            }
            #pragma unroll
            for (int j2 = 0; j2 < 2; j2++) {
                int rowB = wn + j2*16 + (q >> 1)*8 + r8;
                int kb   = kk*32 + (q & 1)*16;
                uint32_t off = SWZ128((uint32_t)(rowB*128 + kb));
                uint32_t bh[4], bl[4];
                LDSM_X4(bh[0],bh[1],bh[2],bh[3], stBh + off);
                LDSM_X4(bl[0],bl[1],bl[2],bl[3], stBl + off);
                #pragma unroll
                for (int i = 0; i < 4; i++) {
                    MMA16816(acc[i][j2*2],   &ah[i*4], &bh[0]);
                    MMA16816(acc[i][j2*2],   &ah[i*4], &bl[0]);
                    MMA16816(acc[i][j2*2+1], &ah[i*4], &bh[2]);
                    MMA16816(acc[i][j2*2+1], &ah[i*4], &bl[2]);
                }
            }
        }
        __syncthreads();
    }

    const int gr = lid >> 2;
    const int gc = (lid & 3) * 2;
    #pragma unroll
    for (int i = 0; i < 4; i++) {
        #pragma unroll
        for (int half = 0; half < 2; half++) {
            int row = bm + wm + i*16 + gr + half*8;
            #pragma unroll
            for (int j = 0; j < 4; j++) {
                int col = wn + j*8 + gc;
                float2 v = half ? make_float2(acc[i][j][2], acc[i][j][3])
                                : make_float2(acc[i][j][0], acc[i][j][1]);
                float* op;
                if (splitHeads) {
                    int b = row >> 11, s = row & (S_LEN-1);
                    int h = blockIdx.x;
                    op = C + ((((size_t)(b*HEADS + h))*S_LEN + s) << 7) + col;
                } else {
                    op = C + (size_t)row * HID + bn + col;
                }
                *(float2*)op = v;
            }
        }
    }
}

// ---------------- HMMA GEMM, 1-product: C = A @ Bh^T ----------------
#define GT1_STAGE 32768
#define GT1_SMEM  (2*GT1_STAGE)

__global__ __launch_bounds__(256, 2) void gemm_mma1(
    const __half* __restrict__ Ah, const __half* __restrict__ Bh,
    float* __restrict__ C, int splitHeads)
{
    extern __shared__ char smem[];
    const uint32_t sb = smem_u32(smem);
    const int tid = threadIdx.x, wid = tid >> 5, lid = tid & 31;
    const int bm = blockIdx.y * 128, bn = blockIdx.x * 128;
    const int wm = (wid >> 2) * 64, wn = (wid & 3) * 32;

    const char* aH = (const char*)Ah + (size_t)bm * (HID*2);
    const char* bH = (const char*)Bh + (size_t)bn * (HID*2);

    int srow[4], scol[4];
    #pragma unroll
    for (int j = 0; j < 4; j++) {
        int sidx = j*256 + tid;
        srow[j] = sidx >> 3;
        scol[j] = (sidx & 7) * 16;
    }

    auto load_chunk = [&](int stage, int chunk) {
        uint32_t st = sb + stage * GT1_STAGE;
        size_t off = (size_t)chunk * 128;
        #pragma unroll
        for (int j = 0; j < 4; j++) {
            uint32_t d = SWZ128((uint32_t)(srow[j]*128 + scol[j]));
            size_t g = (size_t)srow[j] * (HID*2) + off + scol[j];
            CP16(st +     0 + d, aH + g);
            CP16(st + 16384 + d, bH + g);
        }
    };

    float acc[4][4][4];
    #pragma unroll
    for (int i = 0; i < 4; i++)
        #pragma unroll
        for (int j = 0; j < 4; j++)
            #pragma unroll
            for (int c = 0; c < 4; c++) acc[i][j][c] = 0.f;

    const int q  = lid >> 3;
    const int r8 = lid & 7;

    load_chunk(0, 0);
    CP_COMMIT();

    const int NCHUNK = HID / 64;
    for (int chunk = 0; chunk < NCHUNK; chunk++) {
        int buf = chunk & 1;
        if (chunk + 1 < NCHUNK) {
            load_chunk(buf ^ 1, chunk + 1);
            CP_COMMIT();
            CP_WAIT(1);
        } else {
            CP_WAIT(0);
        }
        __syncthreads();

        uint32_t stA  = sb + buf * GT1_STAGE;
        uint32_t stBh = stA + 16384;

        #pragma unroll
        for (int kk = 0; kk < 4; kk++) {
            uint32_t ah[16];
            #pragma unroll
            for (int i = 0; i < 4; i++) {
                int rowA = wm + i*16 + (q & 1)*8 + r8;
                int kb   = kk*32 + (q >> 1)*16;
                uint32_t off = SWZ128((uint32_t)(rowA*128 + kb));
                LDSM_X4(ah[i*4+0], ah[i*4+1], ah[i*4+2], ah[i*4+3], stA + off);
            }
            #pragma unroll
            for (int j2 = 0; j2 < 2; j2++) {
                int rowB = wn + j2*16 + (q >> 1)*8 + r8;
                int kb   = kk*32 + (q & 1)*16;
                uint32_t off = SWZ128((uint32_t)(rowB*128 + kb));
                uint32_t bh[4];
                LDSM_X4(bh[0],bh[1],bh[2],bh[3], stBh + off);
                #pragma unroll
                for (int i = 0; i < 4; i++) {
                    MMA16816(acc[i][j2*2],   &ah[i*4], &bh[0]);
                    MMA16816(acc[i][j2*2+1], &ah[i*4], &bh[2]);
                }
            }
        }
        __syncthreads();
    }

    const int gr = lid >> 2;
    const int gc = (lid & 3) * 2;
    #pragma unroll
    for (int i = 0; i < 4; i++) {
        #pragma unroll
        for (int half = 0; half < 2; half++) {
            int row = bm + wm + i*16 + gr + half*8;
            #pragma unroll
            for (int j = 0; j < 4; j++) {
                int col = wn + j*8 + gc;
                float2 v = half ? make_float2(acc[i][j][2], acc[i][j][3])
                                : make_float2(acc[i][j][0], acc[i][j][1]);
                float* op;
                if (splitHeads) {
                    int b = row >> 11, s = row & (S_LEN-1);
                    int h = blockIdx.x;
                    op = C + ((((size_t)(b*HEADS + h))*S_LEN + s) << 7) + col;
                } else {
                    op = C + (size_t)row * HID + bn + col;
                }
                *(float2*)op = v;
            }
        }
    }
}

// ---------------- RoPE ----------------
__global__ void rope_table_kernel(const int* __restrict__ pos_ids)
{
    int idx = blockIdx.x*blockDim.x + threadIdx.x;
    int i = idx & 63;
    int s = idx >> 6;
    float pos = (float)pos_ids[s];
    double invf = pow(10000.0, -(double)(2*i) / 128.0);
    float ang = pos * (float)invf;
    float sn, cs;
    sincosf(ang, &sn, &cs);
    g_cos[idx] = cs;
    g_sin[idx] = sn;
}

// rope + emit Q fp16 (single) and K fp16 hi/lo
__global__ void rope_apply_split_kernel()
{
    int idx = blockIdx.x*blockDim.x + threadIdx.x;
    int i  = idx & 63;
    int s  = (idx >> 6) & (S_LEN-1);
    int bh = idx >> 17;
    float cs = g_cos[(s<<6) + i];
    float sn = g_sin[(s<<6) + i];
    size_t base = (((size_t)bh * S_LEN + s) << 7) + i;

    float q0 = g_Q[base], q1 = g_Q[base+64];
    g_QH[base]    = __float2half(q0*cs - q1*sn);
    g_QH[base+64] = __float2half(q1*cs + q0*sn);

    float k0 = g_K[base], k1 = g_K[base+64];
    float ka = k0*cs - k1*sn;
    float kb = k1*cs + k0*sn;
    __half h;
    h = __float2half(ka); g_KH[base]    = h; g_KL[base]    = __float2half(ka - __half2float(h));
    h = __float2half(kb); g_KH[base+64] = h; g_KL[base+64] = __float2half(kb - __half2float(h));
}

// ---------------- V transpose (fp16 only) ----------------
__global__ void vt_split_kernel()
{
    __shared__ float tile[32][33];
    int xs = blockIdx.x * 32;
    int dd = blockIdx.y * 32;
    int bh = blockIdx.z;
    int tx = threadIdx.x, ty = threadIdx.y;

    const float* V = g_V + ((size_t)bh * S_LEN) * DH;
    #pragma unroll
    for (int j = 0; j < 4; j++)
        tile[ty + j*8][tx] = V[(size_t)(xs + ty + j*8)*DH + dd + tx];
    __syncthreads();
    #pragma unroll
    for (int j = 0; j < 4; j++) {
        float v = tile[tx][ty + j*8];
        size_t o = ((size_t)bh*DH + dd + ty + j*8) * S_LEN + xs + tx;
        g_VtH[o] = __float2half(v);
    }
}

// ---------------- HMMA flash attention (fp16; S 2-product, PV 1-product) ----
#define AT_STAGE 49152
#define AT2_SMEM (32768 + 2*AT_STAGE)

__global__ __launch_bounds__(256, 1) void attn_mma()
{
    extern __shared__ char smem[];
    const uint32_t sb = smem_u32(smem);
    const int tid = threadIdx.x, wid = tid >> 5, lid = tid & 31;
    const int qt = gridDim.x - 1 - blockIdx.x;     // largest q-tiles first
    const int h = blockIdx.y, b = blockIdx.z;
    const size_t bh = (size_t)b*HEADS + h;
    const int q  = lid >> 3;
    const int r8 = lid & 7;

    const char* qHb = (const char*)g_QH + (bh*S_LEN + (size_t)qt*128) * 256;
    const char* kHb = (const char*)g_KH + bh*S_LEN*256;
    const char* kLb = (const char*)g_KL + bh*S_LEN*256;
    const char* vHb = (const char*)g_VtH + bh*DH*(size_t)S_LEN*2;

    #pragma unroll
    for (int it = 0; it < 8; it++) {
        int e = it*256 + tid;
        int row = e >> 4, seg = e & 15;
        int panel = seg >> 3, c = seg & 7;
        uint32_t d = SWZ128((uint32_t)(row*128 + c*16));
        CP16(sb + panel*16384 + d, qHb + row*256 + seg*16);
    }

    auto load_kv = [&](int st, int kt) {
        uint32_t stb = sb + 32768 + st*AT_STAGE;
        #pragma unroll
        for (int it = 0; it < 4; it++) {
            int e = it*256 + tid;
            int row = e >> 4, seg = e & 15;
            int panel = seg >> 3, c = seg & 7;
            uint32_t d = SWZ128((uint32_t)(row*128 + c*16));
            size_t g = (size_t)(kt*64 + row)*256 + seg*16;
            CP16(stb + panel*8192 + d,         kHb + g);
            CP16(stb + 16384 + panel*8192 + d, kLb + g);
        }
        #pragma unroll
        for (int it = 0; it < 4; it++) {
            int e = it*256 + tid;
            int row = e >> 3, c = e & 7;
            uint32_t d = SWZ128((uint32_t)(row*128 + c*16));
            size_t g = (size_t)row*4096 + (size_t)kt*128 + c*16;
            CP16(stb + 32768 + d, vHb + g);
        }
    };

    load_kv(0, 0);
    CP_COMMIT();

    float o[16][4];
    #pragma unroll
    for (int t = 0; t < 16; t++)
        #pragma unroll
        for (int c = 0; c < 4; c++) o[t][c] = 0.f;
    float m0 = -1e30f, m1 = -1e30f, l0 = 0.f, l1 = 0.f;

    const float scale = 0.08838834764831845f;
    const int qrow_lo = qt*128 + wid*16;
    const int row0 = qrow_lo + (lid >> 2);
    const int col_in = (lid & 3) * 2;

    const int nkv = 2*qt + 2;
    for (int kt = 0; kt < nkv; kt++) {
        int buf = kt & 1;
        if (kt + 1 < nkv) {
            load_kv(buf ^ 1, kt + 1);
            CP_COMMIT();
            CP_WAIT(1);
        } else {
            CP_WAIT(0);
        }
        __syncthreads();

        bool skip = (kt*64 > qrow_lo + 15);
        if (!skip) {
            uint32_t stb = sb + 32768 + buf*AT_STAGE;

            float sacc[8][4];
            #pragma unroll
            for (int t = 0; t < 8; t++)
                #pragma unroll
                for (int c = 0; c < 4; c++) sacc[t][c] = 0.f;

            #pragma unroll
            for (int kk = 0; kk < 8; kk++) {
                int panel = kk >> 2;
                int kb = (kk & 3)*32;
                uint32_t qh[4];
                {
                    int rowA = wid*16 + (q & 1)*8 + r8;
                    uint32_t off = SWZ128((uint32_t)(rowA*128 + kb + (q >> 1)*16));
                    LDSM_X4(qh[0],qh[1],qh[2],qh[3], sb + panel*16384 + off);
                }
                #pragma unroll
                for (int j2 = 0; j2 < 4; j2++) {
                    int rowB = j2*16 + (q >> 1)*8 + r8;
                    uint32_t off = SWZ128((uint32_t)(rowB*128 + kb + (q & 1)*16));
                    uint32_t kh[4], kl[4];
                    LDSM_X4(kh[0],kh[1],kh[2],kh[3], stb + panel*8192 + off);
                    LDSM_X4(kl[0],kl[1],kl[2],kl[3], stb + 16384 + panel*8192 + off);
                    MMA16816(sacc[j2*2],   qh, &kh[0]);
                    MMA16816(sacc[j2*2],   qh, &kl[0]);
                    MMA16816(sacc[j2*2+1], qh, &kh[2]);
                    MMA16816(sacc[j2*2+1], qh, &kl[2]);
                }
            }

            #pragma unroll
            for (int t = 0; t < 8; t++)
                #pragma unroll
                for (int c = 0; c < 4; c++) sacc[t][c] *= scale;

            if (kt*64 + 63 > qrow_lo) {
                #pragma unroll
                for (int t = 0; t < 8; t++) {
                    int colg = kt*64 + t*8 + col_in;
                    if (colg   > row0)   sacc[t][0] = -1e30f;
                    if (colg+1 > row0)   sacc[t][1] = -1e30f;
                    if (colg   > row0+8) sacc[t][2] = -1e30f;
                    if (colg+1 > row0+8) sacc[t][3] = -1e30f;
                }
            }

            float mx0 = -1e30f, mx1 = -1e30f;
            #pragma unroll
            for (int t = 0; t < 8; t++) {
                mx0 = fmaxf(mx0, fmaxf(sacc[t][0], sacc[t][1]));
                mx1 = fmaxf(mx1, fmaxf(sacc[t][2], sacc[t][3]));
            }
            mx0 = fmaxf(mx0, __shfl_xor_sync(0xffffffffu, mx0, 1));
            mx0 = fmaxf(mx0, __shfl_xor_sync(0xffffffffu, mx0, 2));
            mx1 = fmaxf(mx1, __shfl_xor_sync(0xffffffffu, mx1, 1));
            mx1 = fmaxf(mx1, __shfl_xor_sync(0xffffffffu, mx1, 2));
            float mn0 = fmaxf(m0, mx0), mn1 = fmaxf(m1, mx1);
            float cr0 = __expf(m0 - mn0), cr1 = __expf(m1 - mn1);
            m0 = mn0; m1 = mn1;

            float s0 = 0.f, s1 = 0.f;
            #pragma unroll
            for (int t = 0; t < 8; t++) {
                sacc[t][0] = __expf(sacc[t][0] - mn0);
                sacc[t][1] = __expf(sacc[t][1] - mn0);
                sacc[t][2] = __expf(sacc[t][2] - mn1);
                sacc[t][3] = __expf(sacc[t][3] - mn1);
                s0 += sacc[t][0] + sacc[t][1];
                s1 += sacc[t][2] + sacc[t][3];
            }
            s0 += __shfl_xor_sync(0xffffffffu, s0, 1);
            s0 += __shfl_xor_sync(0xffffffffu, s0, 2);
            s1 += __shfl_xor_sync(0xffffffffu, s1, 1);
            s1 += __shfl_xor_sync(0xffffffffu, s1, 2);
            l0 = l0*cr0 + s0;
            l1 = l1*cr1 + s1;
            #pragma unroll
            for (int t = 0; t < 16; t++) {
                o[t][0] *= cr0; o[t][1] *= cr0;
                o[t][2] *= cr1; o[t][3] *= cr1;
            }

            uint32_t ph[4][4];
            #pragma unroll
            for (int t = 0; t < 4; t++) {
                #pragma unroll
                for (int u = 0; u < 2; u++) {
                    ph[t][u*2+0] = packh(sacc[2*t+u][0], sacc[2*t+u][1]);
                    ph[t][u*2+1] = packh(sacc[2*t+u][2], sacc[2*t+u][3]);
                }
            }

            #pragma unroll
            for (int ks = 0; ks < 4; ks++) {
                int kb = ks*32;
                #pragma unroll
                for (int j2 = 0; j2 < 8; j2++) {
                    int rowB = j2*16 + (q >> 1)*8 + r8;
                    uint32_t off = SWZ128((uint32_t)(rowB*128 + kb + (q & 1)*16));
                    uint32_t vh[4];
                    LDSM_X4(vh[0],vh[1],vh[2],vh[3], stb + 32768 + off);
                    MMA16816(o[j2*2],   ph[ks], &vh[0]);
                    MMA16816(o[j2*2+1], ph[ks], &vh[2]);
                }
            }
        }
        __syncthreads();
    }

    // ---- normalize + write Ctx as fp16 ----
    float inv0 = 1.0f / l0, inv1 = 1.0f / l1;
    size_t off0 = ((size_t)b*S_LEN + row0)     * HID + h*DH + col_in;
    size_t off1 = ((size_t)b*S_LEN + row0 + 8) * HID + h*DH + col_in;
    #pragma unroll
    for (int t = 0; t < 16; t++) {
        *(__half2*)(g_CtxH + off0 + t*8) =
            __half2{__float2half(o[t][0]*inv0), __float2half(o[t][1]*inv0)};
        *(__half2*)(g_CtxH + off1 + t*8) =
            __half2{__float2half(o[t][2]*inv1), __float2half(o[t][3]*inv1)};
    }
}

// ---------------- launch ----------------
extern "C" void kernel_launch(void* const* d_in, const int* in_sizes, int n_in,
                              void* d_out, int out_size)
{
    const float* hs = (const float*)d_in[0];
    const float* Wq = (const float*)d_in[1];
    const float* Wk = (const float*)d_in[2];
    const float* Wv = (const float*)d_in[3];
    const float* Wo = (const float*)d_in[4];
    const int* pos  = (const int*)d_in[6];
    float* out = (float*)d_out;

    float *Qp, *Kp, *Vp;
    cudaGetSymbolAddress((void**)&Qp, g_Q);
    cudaGetSymbolAddress((void**)&Kp, g_K);
    cudaGetSymbolAddress((void**)&Vp, g_V);

    __half *hsH,*WqH,*WkH,*WkL,*WvH,*WoH,*WoL,*CtxH;
    cudaGetSymbolAddress((void**)&hsH, g_hsH);
    cudaGetSymbolAddress((void**)&WqH, g_WqH);
    cudaGetSymbolAddress((void**)&WkH, g_WkH);  cudaGetSymbolAddress((void**)&WkL, g_WkL);
    cudaGetSymbolAddress((void**)&WvH, g_WvH);
    cudaGetSymbolAddress((void**)&WoH, g_WoH);  cudaGetSymbolAddress((void**)&WoL, g_WoL);
    cudaGetSymbolAddress((void**)&CtxH, g_CtxH);

    const int NELEM = NROWS*HID;
    const int SPLIT_BLOCKS = NELEM/4/256;

    conv_h_kernel<<<SPLIT_BLOCKS, 256>>>(hs, hsH);
    conv_h_kernel<<<SPLIT_BLOCKS, 256>>>(Wq, WqH);
    split_h_kernel<<<SPLIT_BLOCKS, 256>>>(Wk, WkH, WkL);
    conv_h_kernel<<<SPLIT_BLOCKS, 256>>>(Wv, WvH);
    split_h_kernel<<<SPLIT_BLOCKS, 256>>>(Wo, WoH, WoL);

    cudaFuncSetAttribute(gemm_mma2, cudaFuncAttributeMaxDynamicSharedMemorySize, GT2_SMEM);
    cudaFuncSetAttribute(gemm_mma1, cudaFuncAttributeMaxDynamicSharedMemorySize, GT1_SMEM);
    dim3 ggrid(HID/128, NROWS/128);   // 32 x 32

    gemm_mma1<<<ggrid, 256, GT1_SMEM>>>(hsH, WqH, Qp, 1);
    gemm_mma2<<<ggrid, 256, GT2_SMEM>>>(hsH, WkH, WkL, Kp, 1);
    gemm_mma1<<<ggrid, 256, GT1_SMEM>>>(hsH, WvH, Vp, 1);

    rope_table_kernel<<<(S_LEN*64)/256, 256>>>(pos);
    rope_apply_split_kernel<<<(NBH*S_LEN*64)/256, 256>>>();
    vt_split_kernel<<<dim3(S_LEN/32, DH/32, NBH), dim3(32,8)>>>();

    cudaFuncSetAttribute(attn_mma, cudaFuncAttributeMaxDynamicSharedMemorySize, AT2_SMEM);
    attn_mma<<<dim3(S_LEN/128, HEADS, BATCH), 256, AT2_SMEM>>>();

    gemm_mma2<<<ggrid, 256, GT2_SMEM>>>(CtxH, WoH, WoL, out, 0);
}

// round 11
// speedup vs baseline: 4.4839x; 1.4325x over previous
#include <cuda_runtime.h>
#include <cuda_fp16.h>
#include <math.h>
#include <cstdint>

#define HEADS 32
#define S_LEN 2048
#define BATCH 2
#define HID   4096
#define DH    128
#define NROWS (BATCH*S_LEN)   // 4096
#define NBH   (BATCH*HEADS)   // 64

// ---------------- scratch (static __device__, no allocs) ----------------
__device__ float g_Q[(size_t)NBH*S_LEN*DH];
__device__ float g_K[(size_t)NBH*S_LEN*DH];
__device__ float g_V[(size_t)NBH*S_LEN*DH];
__device__ float g_cos[S_LEN*64];
__device__ float g_sin[S_LEN*64];

__device__ __half g_hsH[(size_t)NROWS*HID];
__device__ __half g_WqH[(size_t)HID*HID];
__device__ __half g_WkH[(size_t)HID*HID];
__device__ __half g_WvH[(size_t)HID*HID];
__device__ __half g_WoH[(size_t)HID*HID];
__device__ __half g_CtxH[(size_t)NROWS*HID];
__device__ __half g_QH[(size_t)NBH*S_LEN*DH];
__device__ __half g_KH[(size_t)NBH*S_LEN*DH];
__device__ __half g_VtH[(size_t)NBH*DH*S_LEN];   // [bh][dh][s]

// ---------------- helpers ----------------
__device__ __forceinline__ uint32_t smem_u32(const void* p) {
    uint32_t a;
    asm("{ .reg .u64 t; cvta.to.shared.u64 t, %1; cvt.u32.u64 %0, t; }" : "=r"(a) : "l"(p));
    return a;
}
#define CP16(dst, src)    asm volatile("cp.async.cg.shared.global [%0], [%1], 16;" :: "r"(dst), "l"(src) : "memory")
#define CP_COMMIT()       asm volatile("cp.async.commit_group;" ::: "memory")
#define CP_WAIT(n)        asm volatile("cp.async.wait_group %0;" :: "n"(n) : "memory")

#define LDSM_X4(r0,r1,r2,r3,a) \
    asm volatile("ldmatrix.sync.aligned.m8n8.x4.shared.b16 {%0,%1,%2,%3}, [%4];" \
        : "=r"(r0),"=r"(r1),"=r"(r2),"=r"(r3) : "r"(a))

#define MMA16816(d, a, b) \
    asm volatile("mma.sync.aligned.m16n8k16.row.col.f32.f16.f16.f32 " \
        "{%0,%1,%2,%3}, {%4,%5,%6,%7}, {%8,%9}, {%0,%1,%2,%3};" \
        : "+f"((d)[0]),"+f"((d)[1]),"+f"((d)[2]),"+f"((d)[3]) \
        : "r"((a)[0]),"r"((a)[1]),"r"((a)[2]),"r"((a)[3]), "r"((b)[0]),"r"((b)[1]))

#define SWZ128(x) ((x) ^ (((x) >> 3) & 0x70))

__device__ __forceinline__ uint32_t packh(float lo, float hi) {
    uint32_t r;   // first src operand -> high half
    asm("cvt.rn.f16x2.f32 %0, %1, %2;" : "=r"(r) : "f"(hi), "f"(lo));
    return r;
}

// ---------------- fp32 -> fp16 convert ----------------
__global__ void conv_h_kernel(const float* __restrict__ src, __half* __restrict__ dst)
{
    int i = (blockIdx.x*blockDim.x + threadIdx.x) * 4;
    float4 v = *(const float4*)(src + i);
    *(__half2*)(dst + i)     = __half2{__float2half(v.x), __float2half(v.y)};
    *(__half2*)(dst + i + 2) = __half2{__float2half(v.z), __float2half(v.w)};
}

// ---------------- HMMA GEMM, 1-product: C = A @ Bh^T, 128x128 tile -------
#define GT1_STAGE 32768
#define GT1_SMEM  (2*GT1_STAGE)

__global__ __launch_bounds__(256, 2) void gemm_mma1(
    const __half* __restrict__ Ah, const __half* __restrict__ Bh,
    float* __restrict__ C, int splitHeads)
{
    extern __shared__ char smem[];
    const uint32_t sb = smem_u32(smem);
    const int tid = threadIdx.x, wid = tid >> 5, lid = tid & 31;
    const int bm = blockIdx.y * 128, bn = blockIdx.x * 128;
    const int wm = (wid >> 2) * 64, wn = (wid & 3) * 32;

    const char* aH = (const char*)Ah + (size_t)bm * (HID*2);
    const char* bH = (const char*)Bh + (size_t)bn * (HID*2);

    int srow[4], scol[4];
    #pragma unroll
    for (int j = 0; j < 4; j++) {
        int sidx = j*256 + tid;
        srow[j] = sidx >> 3;
        scol[j] = (sidx & 7) * 16;
    }

    auto load_chunk = [&](int stage, int chunk) {
        uint32_t st = sb + stage * GT1_STAGE;
        size_t off = (size_t)chunk * 128;
        #pragma unroll
        for (int j = 0; j < 4; j++) {
            uint32_t d = SWZ128((uint32_t)(srow[j]*128 + scol[j]));
            size_t g = (size_t)srow[j] * (HID*2) + off + scol[j];
            CP16(st +     0 + d, aH + g);
            CP16(st + 16384 + d, bH + g);
        }
    };

    float acc[4][4][4];
    #pragma unroll
    for (int i = 0; i < 4; i++)
        #pragma unroll
        for (int j = 0; j < 4; j++)
            #pragma unroll
            for (int c = 0; c < 4; c++) acc[i][j][c] = 0.f;

    const int q  = lid >> 3;
    const int r8 = lid & 7;

    load_chunk(0, 0);
    CP_COMMIT();

    const int NCHUNK = HID / 64;
    for (int chunk = 0; chunk < NCHUNK; chunk++) {
        int buf = chunk & 1;
        if (chunk + 1 < NCHUNK) {
            load_chunk(buf ^ 1, chunk + 1);
            CP_COMMIT();
            CP_WAIT(1);
        } else {
            CP_WAIT(0);
        }
        __syncthreads();

        uint32_t stA  = sb + buf * GT1_STAGE;
        uint32_t stBh = stA + 16384;

        #pragma unroll
        for (int kk = 0; kk < 4; kk++) {
            uint32_t ah[16];
            #pragma unroll
            for (int i = 0; i < 4; i++) {
                int rowA = wm + i*16 + (q & 1)*8 + r8;
                int kb   = kk*32 + (q >> 1)*16;
                uint32_t off = SWZ128((uint32_t)(rowA*128 + kb));
                LDSM_X4(ah[i*4+0], ah[i*4+1], ah[i*4+2], ah[i*4+3], stA + off);
            }
            #pragma unroll
            for (int j2 = 0; j2 < 2; j2++) {
                int rowB = wn + j2*16 + (q >> 1)*8 + r8;
                int kb   = kk*32 + (q & 1)*16;
                uint32_t off = SWZ128((uint32_t)(rowB*128 + kb));
                uint32_t bh[4];
                LDSM_X4(bh[0],bh[1],bh[2],bh[3], stBh + off);
                #pragma unroll
                for (int i = 0; i < 4; i++) {
                    MMA16816(acc[i][j2*2],   &ah[i*4], &bh[0]);
                    MMA16816(acc[i][j2*2+1], &ah[i*4], &bh[2]);
                }
            }
        }
        __syncthreads();
    }

    const int gr = lid >> 2;
    const int gc = (lid & 3) * 2;
    #pragma unroll
    for (int i = 0; i < 4; i++) {
        #pragma unroll
        for (int half = 0; half < 2; half++) {
            int row = bm + wm + i*16 + gr + half*8;
            #pragma unroll
            for (int j = 0; j < 4; j++) {
                int col = wn + j*8 + gc;
                float2 v = half ? make_float2(acc[i][j][2], acc[i][j][3])
                                : make_float2(acc[i][j][0], acc[i][j][1]);
                float* op;
                if (splitHeads) {
                    int b = row >> 11, s = row & (S_LEN-1);
                    int h = blockIdx.x;
                    op = C + ((((size_t)(b*HEADS + h))*S_LEN + s) << 7) + col;
                } else {
                    op = C + (size_t)row * HID + bn + col;
                }
                *(float2*)op = v;
            }
        }
    }
}

// ---------------- RoPE ----------------
__global__ void rope_table_kernel(const int* __restrict__ pos_ids)
{
    int idx = blockIdx.x*blockDim.x + threadIdx.x;
    int i = idx & 63;
    int s = idx >> 6;
    float pos = (float)pos_ids[s];
    double invf = pow(10000.0, -(double)(2*i) / 128.0);
    float ang = pos * (float)invf;
    float sn, cs;
    sincosf(ang, &sn, &cs);
    g_cos[idx] = cs;
    g_sin[idx] = sn;
}

// rope + emit Q,K fp16
__global__ void rope_apply_split_kernel()
{
    int idx = blockIdx.x*blockDim.x + threadIdx.x;
    int i  = idx & 63;
    int s  = (idx >> 6) & (S_LEN-1);
    int bh = idx >> 17;
    float cs = g_cos[(s<<6) + i];
    float sn = g_sin[(s<<6) + i];
    size_t base = (((size_t)bh * S_LEN + s) << 7) + i;

    float q0 = g_Q[base], q1 = g_Q[base+64];
    g_QH[base]    = __float2half(q0*cs - q1*sn);
    g_QH[base+64] = __float2half(q1*cs + q0*sn);

    float k0 = g_K[base], k1 = g_K[base+64];
    g_KH[base]    = __float2half(k0*cs - k1*sn);
    g_KH[base+64] = __float2half(k1*cs + k0*sn);
}

// ---------------- V transpose (fp16) ----------------
__global__ void vt_split_kernel()
{
    __shared__ float tile[32][33];
    int xs = blockIdx.x * 32;
    int dd = blockIdx.y * 32;
    int bh = blockIdx.z;
    int tx = threadIdx.x, ty = threadIdx.y;

    const float* V = g_V + ((size_t)bh * S_LEN) * DH;
    #pragma unroll
    for (int j = 0; j < 4; j++)
        tile[ty + j*8][tx] = V[(size_t)(xs + ty + j*8)*DH + dd + tx];
    __syncthreads();
    #pragma unroll
    for (int j = 0; j < 4; j++) {
        float v = tile[tx][ty + j*8];
        size_t o = ((size_t)bh*DH + dd + ty + j*8) * S_LEN + xs + tx;
        g_VtH[o] = __float2half(v);
    }
}

// ---------------- HMMA flash attention (fp16; S 1-product, PV 1-product) --
// smem: Q 2x16K | 2 stages x { Kh 2x8K, VtH 16K } = 32K + 2x32K = 96K
#define AT_STAGE 32768
#define AT2_SMEM (32768 + 2*AT_STAGE)

__global__ __launch_bounds__(256, 1) void attn_mma()
{
    extern __shared__ char smem[];
    const uint32_t sb = smem_u32(smem);
    const int tid = threadIdx.x, wid = tid >> 5, lid = tid & 31;
    const int qt = gridDim.x - 1 - blockIdx.x;     // largest q-tiles first
    const int h = blockIdx.y, b = blockIdx.z;
    const size_t bh = (size_t)b*HEADS + h;
    const int q  = lid >> 3;
    const int r8 = lid & 7;

    const char* qHb = (const char*)g_QH + (bh*S_LEN + (size_t)qt*128) * 256;
    const char* kHb = (const char*)g_KH + bh*S_LEN*256;
    const char* vHb = (const char*)g_VtH + bh*DH*(size_t)S_LEN*2;

    #pragma unroll
    for (int it = 0; it < 8; it++) {
        int e = it*256 + tid;
        int row = e >> 4, seg = e & 15;
        int panel = seg >> 3, c = seg & 7;
        uint32_t d = SWZ128((uint32_t)(row*128 + c*16));
        CP16(sb + panel*16384 + d, qHb + row*256 + seg*16);
    }

    auto load_kv = [&](int st, int kt) {
        uint32_t stb = sb + 32768 + st*AT_STAGE;
        #pragma unroll
        for (int it = 0; it < 4; it++) {
            int e = it*256 + tid;
            int row = e >> 4, seg = e & 15;
            int panel = seg >> 3, c = seg & 7;
            uint32_t d = SWZ128((uint32_t)(row*128 + c*16));
            size_t g = (size_t)(kt*64 + row)*256 + seg*16;
            CP16(stb + panel*8192 + d, kHb + g);
        }
        #pragma unroll
        for (int it = 0; it < 4; it++) {
            int e = it*256 + tid;
            int row = e >> 3, c = e & 7;
            uint32_t d = SWZ128((uint32_t)(row*128 + c*16));
            size_t g = (size_t)row*4096 + (size_t)kt*128 + c*16;
            CP16(stb + 16384 + d, vHb + g);
        }
    };

    load_kv(0, 0);
    CP_COMMIT();

    float o[16][4];
    #pragma unroll
    for (int t = 0; t < 16; t++)
        #pragma unroll
        for (int c = 0; c < 4; c++) o[t][c] = 0.f;
    float m0 = -1e30f, m1 = -1e30f, l0 = 0.f, l1 = 0.f;

    const float scale = 0.08838834764831845f;
    const int qrow_lo = qt*128 + wid*16;
    const int row0 = qrow_lo + (lid >> 2);
    const int col_in = (lid & 3) * 2;

    const int nkv = 2*qt + 2;
    for (int kt = 0; kt < nkv; kt++) {
        int buf = kt & 1;
        if (kt + 1 < nkv) {
            load_kv(buf ^ 1, kt + 1);
            CP_COMMIT();
            CP_WAIT(1);
        } else {
            CP_WAIT(0);
        }
        __syncthreads();

        bool skip = (kt*64 > qrow_lo + 15);
        if (!skip) {
            uint32_t stb = sb + 32768 + buf*AT_STAGE;

            float sacc[8][4];
            #pragma unroll
            for (int t = 0; t < 8; t++)
                #pragma unroll
                for (int c = 0; c < 4; c++) sacc[t][c] = 0.f;

            #pragma unroll
            for (int kk = 0; kk < 8; kk++) {
                int panel = kk >> 2;
                int kb = (kk & 3)*32;
                uint32_t qh[4];
                {
                    int rowA = wid*16 + (q & 1)*8 + r8;
                    uint32_t off = SWZ128((uint32_t)(rowA*128 + kb + (q >> 1)*16));
                    LDSM_X4(qh[0],qh[1],qh[2],qh[3], sb + panel*16384 + off);
                }
                #pragma unroll
                for (int j2 = 0; j2 < 4; j2++) {
                    int rowB = j2*16 + (q >> 1)*8 + r8;
                    uint32_t off = SWZ128((uint32_t)(rowB*128 + kb + (q & 1)*16));
                    uint32_t kh[4];
                    LDSM_X4(kh[0],kh[1],kh[2],kh[3], stb + panel*8192 + off);
                    MMA16816(sacc[j2*2],   qh, &kh[0]);
                    MMA16816(sacc[j2*2+1], qh, &kh[2]);
                }
            }

            #pragma unroll
            for (int t = 0; t < 8; t++)
                #pragma unroll
                for (int c = 0; c < 4; c++) sacc[t][c] *= scale;

            if (kt*64 + 63 > qrow_lo) {
                #pragma unroll
                for (int t = 0; t < 8; t++) {
                    int colg = kt*64 + t*8 + col_in;
                    if (colg   > row0)   sacc[t][0] = -1e30f;
                    if (colg+1 > row0)   sacc[t][1] = -1e30f;
                    if (colg   > row0+8) sacc[t][2] = -1e30f;
                    if (colg+1 > row0+8) sacc[t][3] = -1e30f;
                }
            }

            float mx0 = -1e30f, mx1 = -1e30f;
            #pragma unroll
            for (int t = 0; t < 8; t++) {
                mx0 = fmaxf(mx0, fmaxf(sacc[t][0], sacc[t][1]));
                mx1 = fmaxf(mx1, fmaxf(sacc[t][2], sacc[t][3]));
            }
            mx0 = fmaxf(mx0, __shfl_xor_sync(0xffffffffu, mx0, 1));
            mx0 = fmaxf(mx0, __shfl_xor_sync(0xffffffffu, mx0, 2));
            mx1 = fmaxf(mx1, __shfl_xor_sync(0xffffffffu, mx1, 1));
            mx1 = fmaxf(mx1, __shfl_xor_sync(0xffffffffu, mx1, 2));
            float mn0 = fmaxf(m0, mx0), mn1 = fmaxf(m1, mx1);
            float cr0 = __expf(m0 - mn0), cr1 = __expf(m1 - mn1);
            m0 = mn0; m1 = mn1;

            float s0 = 0.f, s1 = 0.f;
            #pragma unroll
            for (int t = 0; t < 8; t++) {
                sacc[t][0] = __expf(sacc[t][0] - mn0);
                sacc[t][1] = __expf(sacc[t][1] - mn0);
                sacc[t][2] = __expf(sacc[t][2] - mn1);
                sacc[t][3] = __expf(sacc[t][3] - mn1);
                s0 += sacc[t][0] + sacc[t][1];
                s1 += sacc[t][2] + sacc[t][3];
            }
            s0 += __shfl_xor_sync(0xffffffffu, s0, 1);
            s0 += __shfl_xor_sync(0xffffffffu, s0, 2);
            s1 += __shfl_xor_sync(0xffffffffu, s1, 1);
            s1 += __shfl_xor_sync(0xffffffffu, s1, 2);
            l0 = l0*cr0 + s0;
            l1 = l1*cr1 + s1;
            #pragma unroll
            for (int t = 0; t < 16; t++) {
                o[t][0] *= cr0; o[t][1] *= cr0;
                o[t][2] *= cr1; o[t][3] *= cr1;
            }

            uint32_t ph[4][4];
            #pragma unroll
            for (int t = 0; t < 4; t++) {
                #pragma unroll
                for (int u = 0; u < 2; u++) {
                    ph[t][u*2+0] = packh(sacc[2*t+u][0], sacc[2*t+u][1]);
                    ph[t][u*2+1] = packh(sacc[2*t+u][2], sacc[2*t+u][3]);
                }
            }

            #pragma unroll
            for (int ks = 0; ks < 4; ks++) {
                int kb = ks*32;
                #pragma unroll
                for (int j2 = 0; j2 < 8; j2++) {
                    int rowB = j2*16 + (q >> 1)*8 + r8;
                    uint32_t off = SWZ128((uint32_t)(rowB*128 + kb + (q & 1)*16));
                    uint32_t vh[4];
                    LDSM_X4(vh[0],vh[1],vh[2],vh[3], stb + 16384 + off);
                    MMA16816(o[j2*2],   ph[ks], &vh[0]);
                    MMA16816(o[j2*2+1], ph[ks], &vh[2]);
                }
            }
        }
        __syncthreads();
    }

    // ---- normalize + write Ctx as fp16 ----
    float inv0 = 1.0f / l0, inv1 = 1.0f / l1;
    size_t off0 = ((size_t)b*S_LEN + row0)     * HID + h*DH + col_in;
    size_t off1 = ((size_t)b*S_LEN + row0 + 8) * HID + h*DH + col_in;
    #pragma unroll
    for (int t = 0; t < 16; t++) {
        *(__half2*)(g_CtxH + off0 + t*8) =
            __half2{__float2half(o[t][0]*inv0), __float2half(o[t][1]*inv0)};
        *(__half2*)(g_CtxH + off1 + t*8) =
            __half2{__float2half(o[t][2]*inv1), __float2half(o[t][3]*inv1)};
    }
}

// ---------------- launch ----------------
extern "C" void kernel_launch(void* const* d_in, const int* in_sizes, int n_in,
                              void* d_out, int out_size)
{
    const float* hs = (const float*)d_in[0];
    const float* Wq = (const float*)d_in[1];
    const float* Wk = (const float*)d_in[2];
    const float* Wv = (const float*)d_in[3];
    const float* Wo = (const float*)d_in[4];
    const int* pos  = (const int*)d_in[6];
    float* out = (float*)d_out;

    float *Qp, *Kp, *Vp;
    cudaGetSymbolAddress((void**)&Qp, g_Q);
    cudaGetSymbolAddress((void**)&Kp, g_K);
    cudaGetSymbolAddress((void**)&Vp, g_V);

    __half *hsH,*WqH,*WkH,*WvH,*WoH,*CtxH;
    cudaGetSymbolAddress((void**)&hsH, g_hsH);
    cudaGetSymbolAddress((void**)&WqH, g_WqH);
    cudaGetSymbolAddress((void**)&WkH, g_WkH);
    cudaGetSymbolAddress((void**)&WvH, g_WvH);
    cudaGetSymbolAddress((void**)&WoH, g_WoH);
    cudaGetSymbolAddress((void**)&CtxH, g_CtxH);

    const int NELEM = NROWS*HID;
    const int SPLIT_BLOCKS = NELEM/4/256;

    conv_h_kernel<<<SPLIT_BLOCKS, 256>>>(hs, hsH);
    conv_h_kernel<<<SPLIT_BLOCKS, 256>>>(Wq, WqH);
    conv_h_kernel<<<SPLIT_BLOCKS, 256>>>(Wk, WkH);
    conv_h_kernel<<<SPLIT_BLOCKS, 256>>>(Wv, WvH);
    conv_h_kernel<<<SPLIT_BLOCKS, 256>>>(Wo, WoH);

    cudaFuncSetAttribute(gemm_mma1, cudaFuncAttributeMaxDynamicSharedMemorySize, GT1_SMEM);
    dim3 ggrid(HID/128, NROWS/128);   // 32 x 32

    gemm_mma1<<<ggrid, 256, GT1_SMEM>>>(hsH, WqH, Qp, 1);
    gemm_mma1<<<ggrid, 256, GT1_SMEM>>>(hsH, WkH, Kp, 1);
    gemm_mma1<<<ggrid, 256, GT1_SMEM>>>(hsH, WvH, Vp, 1);

    rope_table_kernel<<<(S_LEN*64)/256, 256>>>(pos);
    rope_apply_split_kernel<<<(NBH*S_LEN*64)/256, 256>>>();
    vt_split_kernel<<<dim3(S_LEN/32, DH/32, NBH), dim3(32,8)>>>();

    cudaFuncSetAttribute(attn_mma, cudaFuncAttributeMaxDynamicSharedMemorySize, AT2_SMEM);
    attn_mma<<<dim3(S_LEN/128, HEADS, BATCH), 256, AT2_SMEM>>>();

    gemm_mma1<<<ggrid, 256, GT1_SMEM>>>(CtxH, WoH, out, 0);
}

// round 12
// speedup vs baseline: 4.5067x; 1.0051x over previous
#include <cuda_runtime.h>
#include <cuda_fp16.h>
#include <math.h>
#include <cstdint>

#define HEADS 32
#define S_LEN 2048
#define BATCH 2
#define HID   4096
#define DH    128
#define NROWS (BATCH*S_LEN)   // 4096
#define NBH   (BATCH*HEADS)   // 64

// ---------------- scratch (static __device__, no allocs) ----------------
__device__ float g_cos[S_LEN*64];
__device__ float g_sin[S_LEN*64];

__device__ __half g_hsH[(size_t)NROWS*HID];
__device__ __half g_WqH[(size_t)HID*HID];
__device__ __half g_WkH[(size_t)HID*HID];
__device__ __half g_WvH[(size_t)HID*HID];
__device__ __half g_WoH[(size_t)HID*HID];
__device__ __half g_CtxH[(size_t)NROWS*HID];
__device__ __half g_QH[(size_t)NBH*S_LEN*DH];
__device__ __half g_KH[(size_t)NBH*S_LEN*DH];
__device__ __half g_VtH[(size_t)NBH*DH*S_LEN];   // [bh][dh][s]

// ---------------- helpers ----------------
__device__ __forceinline__ uint32_t smem_u32(const void* p) {
    uint32_t a;
    asm("{ .reg .u64 t; cvta.to.shared.u64 t, %1; cvt.u32.u64 %0, t; }" : "=r"(a) : "l"(p));
    return a;
}
#define CP16(dst, src)    asm volatile("cp.async.cg.shared.global [%0], [%1], 16;" :: "r"(dst), "l"(src) : "memory")
#define CP_COMMIT()       asm volatile("cp.async.commit_group;" ::: "memory")
#define CP_WAIT(n)        asm volatile("cp.async.wait_group %0;" :: "n"(n) : "memory")

#define LDSM_X4(r0,r1,r2,r3,a) \
    asm volatile("ldmatrix.sync.aligned.m8n8.x4.shared.b16 {%0,%1,%2,%3}, [%4];" \
        : "=r"(r0),"=r"(r1),"=r"(r2),"=r"(r3) : "r"(a))

#define MMA16816(d, a, b) \
    asm volatile("mma.sync.aligned.m16n8k16.row.col.f32.f16.f16.f32 " \
        "{%0,%1,%2,%3}, {%4,%5,%6,%7}, {%8,%9}, {%0,%1,%2,%3};" \
        : "+f"((d)[0]),"+f"((d)[1]),"+f"((d)[2]),"+f"((d)[3]) \
        : "r"((a)[0]),"r"((a)[1]),"r"((a)[2]),"r"((a)[3]), "r"((b)[0]),"r"((b)[1]))

#define SWZ128(x) ((x) ^ (((x) >> 3) & 0x70))

__device__ __forceinline__ uint32_t packh(float lo, float hi) {
    uint32_t r;   // first src operand -> high half
    asm("cvt.rn.f16x2.f32 %0, %1, %2;" : "=r"(r) : "f"(hi), "f"(lo));
    return r;
}

// ---------------- fp32 -> fp16 convert ----------------
__global__ void conv_h_kernel(const float* __restrict__ src, __half* __restrict__ dst)
{
    int i = (blockIdx.x*blockDim.x + threadIdx.x) * 4;
    float4 v = *(const float4*)(src + i);
    *(__half2*)(dst + i)     = __half2{__float2half(v.x), __float2half(v.y)};
    *(__half2*)(dst + i + 2) = __half2{__float2half(v.z), __float2half(v.w)};
}

// ---------------- RoPE table ----------------
__global__ void rope_table_kernel(const int* __restrict__ pos_ids)
{
    int idx = blockIdx.x*blockDim.x + threadIdx.x;
    int i = idx & 63;
    int s = idx >> 6;
    float pos = (float)pos_ids[s];
    double invf = pow(10000.0, -(double)(2*i) / 128.0);
    float ang = pos * (float)invf;
    float sn, cs;
    sincosf(ang, &sn, &cs);
    g_cos[idx] = cs;
    g_sin[idx] = sn;
}

// ---------------- HMMA GEMM, 1-product, fused epilogues --------------------
// mode 0: C fp32 row-major (O projection, out = Cf)
// mode 1: rope + fp16, per-head layout [b,h,s,d] (Q or K, out = Ch)
// mode 2: fp16 transpose to [b,h,d,s] (V, out = Ch)
#define GT1_STAGE 32768
#define GT1_SMEM  (2*GT1_STAGE)   // also holds the 64KB fp32 epilogue tile

__global__ __launch_bounds__(256, 2) void gemm_mma1(
    const __half* __restrict__ Ah, const __half* __restrict__ Bh,
    float* __restrict__ Cf, __half* __restrict__ Ch, int mode)
{
    extern __shared__ char smem[];
    const uint32_t sb = smem_u32(smem);
    const int tid = threadIdx.x, wid = tid >> 5, lid = tid & 31;
    const int bm = blockIdx.y * 128, bn = blockIdx.x * 128;
    const int wm = (wid >> 2) * 64, wn = (wid & 3) * 32;

    const char* aH = (const char*)Ah + (size_t)bm * (HID*2);
    const char* bH = (const char*)Bh + (size_t)bn * (HID*2);

    int srow[4], scol[4];
    #pragma unroll
    for (int j = 0; j < 4; j++) {
        int sidx = j*256 + tid;
        srow[j] = sidx >> 3;
        scol[j] = (sidx & 7) * 16;
    }

    auto load_chunk = [&](int stage, int chunk) {
        uint32_t st = sb + stage * GT1_STAGE;
        size_t off = (size_t)chunk * 128;
        #pragma unroll
        for (int j = 0; j < 4; j++) {
            uint32_t d = SWZ128((uint32_t)(srow[j]*128 + scol[j]));
            size_t g = (size_t)srow[j] * (HID*2) + off + scol[j];
            CP16(st +     0 + d, aH + g);
            CP16(st + 16384 + d, bH + g);
        }
    };

    float acc[4][4][4];
    #pragma unroll
    for (int i = 0; i < 4; i++)
        #pragma unroll
        for (int j = 0; j < 4; j++)
            #pragma unroll
            for (int c = 0; c < 4; c++) acc[i][j][c] = 0.f;

    const int q  = lid >> 3;
    const int r8 = lid & 7;

    load_chunk(0, 0);
    CP_COMMIT();

    const int NCHUNK = HID / 64;
    for (int chunk = 0; chunk < NCHUNK; chunk++) {
        int buf = chunk & 1;
        if (chunk + 1 < NCHUNK) {
            load_chunk(buf ^ 1, chunk + 1);
            CP_COMMIT();
            CP_WAIT(1);
        } else {
            CP_WAIT(0);
        }
        __syncthreads();

        uint32_t stA  = sb + buf * GT1_STAGE;
        uint32_t stBh = stA + 16384;

        #pragma unroll
        for (int kk = 0; kk < 4; kk++) {
            uint32_t ah[16];
            #pragma unroll
            for (int i = 0; i < 4; i++) {
                int rowA = wm + i*16 + (q & 1)*8 + r8;
                int kb   = kk*32 + (q >> 1)*16;
                uint32_t off = SWZ128((uint32_t)(rowA*128 + kb));
                LDSM_X4(ah[i*4+0], ah[i*4+1], ah[i*4+2], ah[i*4+3], stA + off);
            }
            #pragma unroll
            for (int j2 = 0; j2 < 2; j2++) {
                int rowB = wn + j2*16 + (q >> 1)*8 + r8;
                int kb   = kk*32 + (q & 1)*16;
                uint32_t off = SWZ128((uint32_t)(rowB*128 + kb));
                uint32_t bh[4];
                LDSM_X4(bh[0],bh[1],bh[2],bh[3], stBh + off);
                #pragma unroll
                for (int i = 0; i < 4; i++) {
                    MMA16816(acc[i][j2*2],   &ah[i*4], &bh[0]);
                    MMA16816(acc[i][j2*2+1], &ah[i*4], &bh[2]);
                }
            }
        }
        __syncthreads();
    }

    const int gr = lid >> 2;
    const int gc = (lid & 3) * 2;

    if (mode == 0) {
        // ---- fp32 row-major output ----
        #pragma unroll
        for (int i = 0; i < 4; i++) {
            #pragma unroll
            for (int half = 0; half < 2; half++) {
                int row = bm + wm + i*16 + gr + half*8;
                #pragma unroll
                for (int j = 0; j < 4; j++) {
                    int col = wn + j*8 + gc;
                    float2 v = half ? make_float2(acc[i][j][2], acc[i][j][3])
                                    : make_float2(acc[i][j][0], acc[i][j][1]);
                    *(float2*)(Cf + (size_t)row * HID + bn + col) = v;
                }
            }
        }
        return;
    }

    // ---- stash fp32 tile in smem (swizzled to avoid bank conflicts) ----
    float* tile = (float*)smem;
    #pragma unroll
    for (int i = 0; i < 4; i++) {
        #pragma unroll
        for (int half = 0; half < 2; half++) {
            int row = wm + i*16 + gr + half*8;          // local 0..127
            int sw  = (row & 7) << 2;
            #pragma unroll
            for (int j = 0; j < 4; j++) {
                int col = wn + j*8 + gc;
                float2 v = half ? make_float2(acc[i][j][2], acc[i][j][3])
                                : make_float2(acc[i][j][0], acc[i][j][1]);
                *(float2*)&tile[row*128 + (col ^ sw)] = v;
            }
        }
    }
    __syncthreads();

    const int b  = bm >> 11;               // batch of this row-tile
    const int s0 = bm & (S_LEN-1);         // first seq pos of tile
    const int hh = blockIdx.x;             // head
    const size_t bhBase = (size_t)(b*HEADS + hh);

    if (mode == 1) {
        // ---- RoPE + fp16, layout [bh][s][128] ----
        __half* outp = Ch + bhBase * S_LEN * DH;
        #pragma unroll
        for (int p = 0; p < 32; p++) {
            int idx = p*256 + tid;         // 0..8191
            int row = idx >> 6;            // 0..127
            int d   = idx & 63;
            int sw  = (row & 7) << 2;
            float x0 = tile[row*128 + (d ^ sw)];
            float x1 = tile[row*128 + ((d ^ sw) + 64)];
            int s = s0 + row;
            float cs = g_cos[(s<<6) + d];
            float sn = g_sin[(s<<6) + d];
            size_t o = (size_t)s * DH + d;
            outp[o]      = __float2half(x0*cs - x1*sn);
            outp[o + 64] = __float2half(x1*cs + x0*sn);
        }
    } else {
        // ---- fp16 transpose, layout [bh][d][S_LEN] ----
        __half* outp = Ch + bhBase * DH * S_LEN;
        #pragma unroll
        for (int p = 0; p < 64; p++) {
            int idx = p*256 + tid;         // 0..16383
            int d    = idx >> 7;           // 0..127
            int sloc = idx & 127;
            int sw   = (sloc & 7) << 2;
            float v = tile[sloc*128 + (d ^ sw)];
            outp[(size_t)d * S_LEN + s0 + sloc] = __float2half(v);
        }
    }
}

// ---------------- HMMA flash attention (fp16; S 1-product, PV 1-product) --
#define AT_STAGE 32768
#define AT2_SMEM (32768 + 2*AT_STAGE)

__global__ __launch_bounds__(256, 1) void attn_mma()
{
    extern __shared__ char smem[];
    const uint32_t sb = smem_u32(smem);
    const int tid = threadIdx.x, wid = tid >> 5, lid = tid & 31;
    const int qt = gridDim.x - 1 - blockIdx.x;     // largest q-tiles first
    const int h = blockIdx.y, b = blockIdx.z;
    const size_t bh = (size_t)b*HEADS + h;
    const int q  = lid >> 3;
    const int r8 = lid & 7;

    const char* qHb = (const char*)g_QH + (bh*S_LEN + (size_t)qt*128) * 256;
    const char* kHb = (const char*)g_KH + bh*S_LEN*256;
    const char* vHb = (const char*)g_VtH + bh*DH*(size_t)S_LEN*2;

    #pragma unroll
    for (int it = 0; it < 8; it++) {
        int e = it*256 + tid;
        int row = e >> 4, seg = e & 15;
        int panel = seg >> 3, c = seg & 7;
        uint32_t d = SWZ128((uint32_t)(row*128 + c*16));
        CP16(sb + panel*16384 + d, qHb + row*256 + seg*16);
    }

    auto load_kv = [&](int st, int kt) {
        uint32_t stb = sb + 32768 + st*AT_STAGE;
        #pragma unroll
        for (int it = 0; it < 4; it++) {
            int e = it*256 + tid;
            int row = e >> 4, seg = e & 15;
            int panel = seg >> 3, c = seg & 7;
            uint32_t d = SWZ128((uint32_t)(row*128 + c*16));
            size_t g = (size_t)(kt*64 + row)*256 + seg*16;
            CP16(stb + panel*8192 + d, kHb + g);
        }
        #pragma unroll
        for (int it = 0; it < 4; it++) {
            int e = it*256 + tid;
            int row = e >> 3, c = e & 7;
            uint32_t d = SWZ128((uint32_t)(row*128 + c*16));
            size_t g = (size_t)row*4096 + (size_t)kt*128 + c*16;
            CP16(stb + 16384 + d, vHb + g);
        }
    };

    load_kv(0, 0);
    CP_COMMIT();

    float o[16][4];
    #pragma unroll
    for (int t = 0; t < 16; t++)
        #pragma unroll
        for (int c = 0; c < 4; c++) o[t][c] = 0.f;
    float m0 = -1e30f, m1 = -1e30f, l0 = 0.f, l1 = 0.f;

    const float scale = 0.08838834764831845f;
    const int qrow_lo = qt*128 + wid*16;
    const int row0 = qrow_lo + (lid >> 2);
    const int col_in = (lid & 3) * 2;

    const int nkv = 2*qt + 2;
    for (int kt = 0; kt < nkv; kt++) {
        int buf = kt & 1;
        if (kt + 1 < nkv) {
            load_kv(buf ^ 1, kt + 1);
            CP_COMMIT();
            CP_WAIT(1);
        } else {
            CP_WAIT(0);
        }
        __syncthreads();

        bool skip = (kt*64 > qrow_lo + 15);
        if (!skip) {
            uint32_t stb = sb + 32768 + buf*AT_STAGE;

            float sacc[8][4];
            #pragma unroll
            for (int t = 0; t < 8; t++)
                #pragma unroll
                for (int c = 0; c < 4; c++) sacc[t][c] = 0.f;

            #pragma unroll
            for (int kk = 0; kk < 8; kk++) {
                int panel = kk >> 2;
                int kb = (kk & 3)*32;
                uint32_t qh[4];
                {
                    int rowA = wid*16 + (q & 1)*8 + r8;
                    uint32_t off = SWZ128((uint32_t)(rowA*128 + kb + (q >> 1)*16));
                    LDSM_X4(qh[0],qh[1],qh[2],qh[3], sb + panel*16384 + off);
                }
                #pragma unroll
                for (int j2 = 0; j2 < 4; j2++) {
                    int rowB = j2*16 + (q >> 1)*8 + r8;
                    uint32_t off = SWZ128((uint32_t)(rowB*128 + kb + (q & 1)*16));
                    uint32_t kh[4];
                    LDSM_X4(kh[0],kh[1],kh[2],kh[3], stb + panel*8192 + off);
                    MMA16816(sacc[j2*2],   qh, &kh[0]);
                    MMA16816(sacc[j2*2+1], qh, &kh[2]);
                }
            }

            #pragma unroll
            for (int t = 0; t < 8; t++)
                #pragma unroll
                for (int c = 0; c < 4; c++) sacc[t][c] *= scale;

            if (kt*64 + 63 > qrow_lo) {
                #pragma unroll
                for (int t = 0; t < 8; t++) {
                    int colg = kt*64 + t*8 + col_in;
                    if (colg   > row0)   sacc[t][0] = -1e30f;
                    if (colg+1 > row0)   sacc[t][1] = -1e30f;
                    if (colg   > row0+8) sacc[t][2] = -1e30f;
                    if (colg+1 > row0+8) sacc[t][3] = -1e30f;
                }
            }

            float mx0 = -1e30f, mx1 = -1e30f;
            #pragma unroll
            for (int t = 0; t < 8; t++) {
                mx0 = fmaxf(mx0, fmaxf(sacc[t][0], sacc[t][1]));
                mx1 = fmaxf(mx1, fmaxf(sacc[t][2], sacc[t][3]));
            }
            mx0 = fmaxf(mx0, __shfl_xor_sync(0xffffffffu, mx0, 1));
            mx0 = fmaxf(mx0, __shfl_xor_sync(0xffffffffu, mx0, 2));
            mx1 = fmaxf(mx1, __shfl_xor_sync(0xffffffffu, mx1, 1));
            mx1 = fmaxf(mx1, __shfl_xor_sync(0xffffffffu, mx1, 2));
            float mn0 = fmaxf(m0, mx0), mn1 = fmaxf(m1, mx1);
            float cr0 = __expf(m0 - mn0), cr1 = __expf(m1 - mn1);
            m0 = mn0; m1 = mn1;

            float s0 = 0.f, s1 = 0.f;
            #pragma unroll
            for (int t = 0; t < 8; t++) {
                sacc[t][0] = __expf(sacc[t][0] - mn0);
                sacc[t][1] = __expf(sacc[t][1] - mn0);
                sacc[t][2] = __expf(sacc[t][2] - mn1);
                sacc[t][3] = __expf(sacc[t][3] - mn1);
                s0 += sacc[t][0] + sacc[t][1];
                s1 += sacc[t][2] + sacc[t][3];
            }
            s0 += __shfl_xor_sync(0xffffffffu, s0, 1);
            s0 += __shfl_xor_sync(0xffffffffu, s0, 2);
            s1 += __shfl_xor_sync(0xffffffffu, s1, 1);
            s1 += __shfl_xor_sync(0xffffffffu, s1, 2);
            l0 = l0*cr0 + s0;
            l1 = l1*cr1 + s1;
            #pragma unroll
            for (int t = 0; t < 16; t++) {
                o[t][0] *= cr0; o[t][1] *= cr0;
                o[t][2] *= cr1; o[t][3] *= cr1;
            }

            uint32_t ph[4][4];
            #pragma unroll
            for (int t = 0; t < 4; t++) {
                #pragma unroll
                for (int u = 0; u < 2; u++) {
                    ph[t][u*2+0] = packh(sacc[2*t+u][0], sacc[2*t+u][1]);
                    ph[t][u*2+1] = packh(sacc[2*t+u][2], sacc[2*t+u][3]);
                }
            }

            #pragma unroll
            for (int ks = 0; ks < 4; ks++) {
                int kb = ks*32;
                #pragma unroll
                for (int j2 = 0; j2 < 8; j2++) {
                    int rowB = j2*16 + (q >> 1)*8 + r8;
                    uint32_t off = SWZ128((uint32_t)(rowB*128 + kb + (q & 1)*16));
                    uint32_t vh[4];
                    LDSM_X4(vh[0],vh[1],vh[2],vh[3], stb + 16384 + off);
                    MMA16816(o[j2*2],   ph[ks], &vh[0]);
                    MMA16816(o[j2*2+1], ph[ks], &vh[2]);
                }
            }
        }
        __syncthreads();
    }

    // ---- normalize + write Ctx as fp16 ----
    float inv0 = 1.0f / l0, inv1 = 1.0f / l1;
    size_t off0 = ((size_t)b*S_LEN + row0)     * HID + h*DH + col_in;
    size_t off1 = ((size_t)b*S_LEN + row0 + 8) * HID + h*DH + col_in;
    #pragma unroll
    for (int t = 0; t < 16; t++) {
        *(__half2*)(g_CtxH + off0 + t*8) =
            __half2{__float2half(o[t][0]*inv0), __float2half(o[t][1]*inv0)};
        *(__half2*)(g_CtxH + off1 + t*8) =
            __half2{__float2half(o[t][2]*inv1), __float2half(o[t][3]*inv1)};
    }
}

// ---------------- launch ----------------
extern "C" void kernel_launch(void* const* d_in, const int* in_sizes, int n_in,
                              void* d_out, int out_size)
{
    const float* hs = (const float*)d_in[0];
    const float* Wq = (const float*)d_in[1];
    const float* Wk = (const float*)d_in[2];
    const float* Wv = (const float*)d_in[3];
    const float* Wo = (const float*)d_in[4];
    const int* pos  = (const int*)d_in[6];
    float* out = (float*)d_out;

    __half *hsH,*WqH,*WkH,*WvH,*WoH,*CtxH,*QH,*KH,*VtH;
    cudaGetSymbolAddress((void**)&hsH, g_hsH);
    cudaGetSymbolAddress((void**)&WqH, g_WqH);
    cudaGetSymbolAddress((void**)&WkH, g_WkH);
    cudaGetSymbolAddress((void**)&WvH, g_WvH);
    cudaGetSymbolAddress((void**)&WoH, g_WoH);
    cudaGetSymbolAddress((void**)&CtxH, g_CtxH);
    cudaGetSymbolAddress((void**)&QH, g_QH);
    cudaGetSymbolAddress((void**)&KH, g_KH);
    cudaGetSymbolAddress((void**)&VtH, g_VtH);

    const int NELEM = NROWS*HID;
    const int SPLIT_BLOCKS = NELEM/4/256;

    rope_table_kernel<<<(S_LEN*64)/256, 256>>>(pos);
    conv_h_kernel<<<SPLIT_BLOCKS, 256>>>(hs, hsH);
    conv_h_kernel<<<SPLIT_BLOCKS, 256>>>(Wq, WqH);
    conv_h_kernel<<<SPLIT_BLOCKS, 256>>>(Wk, WkH);
    conv_h_kernel<<<SPLIT_BLOCKS, 256>>>(Wv, WvH);
    conv_h_kernel<<<SPLIT_BLOCKS, 256>>>(Wo, WoH);

    cudaFuncSetAttribute(gemm_mma1, cudaFuncAttributeMaxDynamicSharedMemorySize, GT1_SMEM);
    dim3 ggrid(HID/128, NROWS/128);   // 32 x 32

    gemm_mma1<<<ggrid, 256, GT1_SMEM>>>(hsH, WqH, nullptr, QH,  1);
    gemm_mma1<<<ggrid, 256, GT1_SMEM>>>(hsH, WkH, nullptr, KH,  1);
    gemm_mma1<<<ggrid, 256, GT1_SMEM>>>(hsH, WvH, nullptr, VtH, 2);

    cudaFuncSetAttribute(attn_mma, cudaFuncAttributeMaxDynamicSharedMemorySize, AT2_SMEM);
    attn_mma<<<dim3(S_LEN/128, HEADS, BATCH), 256, AT2_SMEM>>>();

    gemm_mma1<<<ggrid, 256, GT1_SMEM>>>(CtxH, WoH, out, nullptr, 0);
}

// round 14
// speedup vs baseline: 4.6441x; 1.0305x over previous
#include <cuda_runtime.h>
#include <cuda_fp16.h>
#include <math.h>
#include <cstdint>

#define HEADS 32
#define S_LEN 2048
#define BATCH 2
#define HID   4096
#define DH    128
#define NROWS (BATCH*S_LEN)   // 4096
#define NBH   (BATCH*HEADS)   // 64

// ---------------- scratch (static __device__, no allocs) ----------------
__device__ float g_cos[S_LEN*64];
__device__ float g_sin[S_LEN*64];

__device__ __half g_hsH[(size_t)NROWS*HID];
__device__ __half g_WqH[(size_t)HID*HID];
__device__ __half g_WkH[(size_t)HID*HID];
__device__ __half g_WvH[(size_t)HID*HID];
__device__ __half g_WoH[(size_t)HID*HID];
__device__ __half g_CtxH[(size_t)NROWS*HID];
__device__ __half g_QH[(size_t)NBH*S_LEN*DH];
__device__ __half g_KH[(size_t)NBH*S_LEN*DH];
__device__ __half g_VtH[(size_t)NBH*DH*S_LEN];   // [bh][dh][s]

// ---------------- helpers ----------------
__device__ __forceinline__ uint32_t smem_u32(const void* p) {
    uint32_t a;
    asm("{ .reg .u64 t; cvta.to.shared.u64 t, %1; cvt.u32.u64 %0, t; }" : "=r"(a) : "l"(p));
    return a;
}
#define CP16(dst, src)    asm volatile("cp.async.cg.shared.global [%0], [%1], 16;" :: "r"(dst), "l"(src) : "memory")
#define CP_COMMIT()       asm volatile("cp.async.commit_group;" ::: "memory")
#define CP_WAIT(n)        asm volatile("cp.async.wait_group %0;" :: "n"(n) : "memory")

#define LDSM_X4(r0,r1,r2,r3,a) \
    asm volatile("ldmatrix.sync.aligned.m8n8.x4.shared.b16 {%0,%1,%2,%3}, [%4];" \
        : "=r"(r0),"=r"(r1),"=r"(r2),"=r"(r3) : "r"(a))

#define MMA16816(d, a, b) \
    asm volatile("mma.sync.aligned.m16n8k16.row.col.f32.f16.f16.f32 " \
        "{%0,%1,%2,%3}, {%4,%5,%6,%7}, {%8,%9}, {%0,%1,%2,%3};" \
        : "+f"((d)[0]),"+f"((d)[1]),"+f"((d)[2]),"+f"((d)[3]) \
        : "r"((a)[0]),"r"((a)[1]),"r"((a)[2]),"r"((a)[3]), "r"((b)[0]),"r"((b)[1]))

#define SWZ128(x) ((x) ^ (((x) >> 3) & 0x70))

__device__ __forceinline__ uint32_t packh(float lo, float hi) {
    uint32_t r;   // first src operand -> high half
    asm("cvt.rn.f16x2.f32 %0, %1, %2;" : "=r"(r) : "f"(hi), "f"(lo));
    return r;
}

// ---------------- fp32 -> fp16 convert (5 tensors, one launch) ------------
__global__ void conv_h5_kernel(const float* s0, __half* d0,
                               const float* s1, __half* d1,
                               const float* s2, __half* d2,
                               const float* s3, __half* d3,
                               const float* s4, __half* d4)
{
    const float* src;
    __half* dst;
    switch (blockIdx.y) {
        case 0: src = s0; dst = d0; break;
        case 1: src = s1; dst = d1; break;
        case 2: src = s2; dst = d2; break;
        case 3: src = s3; dst = d3; break;
        default: src = s4; dst = d4; break;
    }
    int i = (blockIdx.x*blockDim.x + threadIdx.x) * 4;
    float4 v = *(const float4*)(src + i);
    *(__half2*)(dst + i)     = __half2{__float2half(v.x), __float2half(v.y)};
    *(__half2*)(dst + i + 2) = __half2{__float2half(v.z), __float2half(v.w)};
}

// ---------------- RoPE table ----------------
__global__ void rope_table_kernel(const int* __restrict__ pos_ids)
{
    int idx = blockIdx.x*blockDim.x + threadIdx.x;
    int i = idx & 63;
    int s = idx >> 6;
    float pos = (float)pos_ids[s];
    double invf = pow(10000.0, -(double)(2*i) / 128.0);
    float ang = pos * (float)invf;
    float sn, cs;
    sincosf(ang, &sn, &cs);
    g_cos[idx] = cs;
    g_sin[idx] = sn;
}

#define GT1_STAGE 32768
#define GT1_SMEM  (2*GT1_STAGE)   // also holds the 64KB fp32 epilogue tile

// ---------------- merged Q/K/V projection GEMM (z selects) ----------------
// z=0: Q (rope epilogue), z=1: K (rope epilogue), z=2: V (transpose epilogue)
__global__ __launch_bounds__(256, 2) void gemm_qkv(const __half* __restrict__ Ah)
{
    extern __shared__ char smem[];
    const uint32_t sb = smem_u32(smem);
    const int tid = threadIdx.x, wid = tid >> 5, lid = tid & 31;
    const int bm = blockIdx.y * 128, bn = blockIdx.x * 128;
    const int wm = (wid >> 2) * 64, wn = (wid & 3) * 32;
    const int z = blockIdx.z;

    const __half* Bsel = (z == 0) ? g_WqH : (z == 1) ? g_WkH : g_WvH;

    const char* aH = (const char*)Ah + (size_t)bm * (HID*2);
    const char* bH = (const char*)Bsel + (size_t)bn * (HID*2);

    int srow[4], scol[4];
    #pragma unroll
    for (int j = 0; j < 4; j++) {
        int sidx = j*256 + tid;
        srow[j] = sidx >> 3;
        scol[j] = (sidx & 7) * 16;
    }

    auto load_chunk = [&](int stage, int chunk) {
        uint32_t st = sb + stage * GT1_STAGE;
        size_t off = (size_t)chunk * 128;
        #pragma unroll
        for (int j = 0; j < 4; j++) {
            uint32_t d = SWZ128((uint32_t)(srow[j]*128 + scol[j]));
            size_t g = (size_t)srow[j] * (HID*2) + off + scol[j];
            CP16(st +     0 + d, aH + g);
            CP16(st + 16384 + d, bH + g);
        }
    };

    float acc[4][4][4];
    #pragma unroll
    for (int i = 0; i < 4; i++)
        #pragma unroll
        for (int j = 0; j < 4; j++)
            #pragma unroll
            for (int c = 0; c < 4; c++) acc[i][j][c] = 0.f;

    const int q  = lid >> 3;
    const int r8 = lid & 7;

    load_chunk(0, 0);
    CP_COMMIT();

    const int NCHUNK = HID / 64;
    for (int chunk = 0; chunk < NCHUNK; chunk++) {
        int buf = chunk & 1;
        if (chunk + 1 < NCHUNK) {
            load_chunk(buf ^ 1, chunk + 1);
            CP_COMMIT();
            CP_WAIT(1);
        } else {
            CP_WAIT(0);
        }
        __syncthreads();

        uint32_t stA  = sb + buf * GT1_STAGE;
        uint32_t stBh = stA + 16384;

        #pragma unroll
        for (int kk = 0; kk < 4; kk++) {
            uint32_t ah[16];
            #pragma unroll
            for (int i = 0; i < 4; i++) {
                int rowA = wm + i*16 + (q & 1)*8 + r8;
                int kb   = kk*32 + (q >> 1)*16;
                uint32_t off = SWZ128((uint32_t)(rowA*128 + kb));
                LDSM_X4(ah[i*4+0], ah[i*4+1], ah[i*4+2], ah[i*4+3], stA + off);
            }
            #pragma unroll
            for (int j2 = 0; j2 < 2; j2++) {
                int rowB = wn + j2*16 + (q >> 1)*8 + r8;
                int kb   = kk*32 + (q & 1)*16;
                uint32_t off = SWZ128((uint32_t)(rowB*128 + kb));
                uint32_t bh[4];
                LDSM_X4(bh[0],bh[1],bh[2],bh[3], stBh + off);
                #pragma unroll
                for (int i = 0; i < 4; i++) {
                    MMA16816(acc[i][j2*2],   &ah[i*4], &bh[0]);
                    MMA16816(acc[i][j2*2+1], &ah[i*4], &bh[2]);
                }
            }
        }
        __syncthreads();
    }

    const int gr = lid >> 2;
    const int gc = (lid & 3) * 2;

    // ---- stash fp32 tile in smem (swizzled) ----
    float* tile = (float*)smem;
    #pragma unroll
    for (int i = 0; i < 4; i++) {
        #pragma unroll
        for (int half = 0; half < 2; half++) {
            int row = wm + i*16 + gr + half*8;
            int sw  = (row & 7) << 2;
            #pragma unroll
            for (int j = 0; j < 4; j++) {
                int col = wn + j*8 + gc;
                float2 v = half ? make_float2(acc[i][j][2], acc[i][j][3])
                                : make_float2(acc[i][j][0], acc[i][j][1]);
                *(float2*)&tile[row*128 + (col ^ sw)] = v;
            }
        }
    }
    __syncthreads();

    const int b  = bm >> 11;
    const int s0 = bm & (S_LEN-1);
    const int hh = blockIdx.x;
    const size_t bhBase = (size_t)(b*HEADS + hh);

    if (z < 2) {
        // ---- RoPE + fp16, layout [bh][s][128] ----
        __half* outp = ((z == 0) ? g_QH : g_KH) + bhBase * S_LEN * DH;
        #pragma unroll
        for (int p = 0; p < 32; p++) {
            int idx = p*256 + tid;
            int row = idx >> 6;
            int d   = idx & 63;
            int sw  = (row & 7) << 2;
            float x0 = tile[row*128 + (d ^ sw)];
            float x1 = tile[row*128 + ((d ^ sw) + 64)];
            int s = s0 + row;
            float cs = g_cos[(s<<6) + d];
            float sn = g_sin[(s<<6) + d];
            size_t o = (size_t)s * DH + d;
            outp[o]      = __float2half(x0*cs - x1*sn);
            outp[o + 64] = __float2half(x1*cs + x0*sn);
        }
    } else {
        // ---- fp16 transpose, layout [bh][d][S_LEN] ----
        __half* outp = g_VtH + bhBase * DH * S_LEN;
        #pragma unroll
        for (int p = 0; p < 64; p++) {
            int idx = p*256 + tid;
            int d    = idx >> 7;
            int sloc = idx & 127;
            int sw   = (sloc & 7) << 2;
            float v = tile[sloc*128 + (d ^ sw)];
            outp[(size_t)d * S_LEN + s0 + sloc] = __float2half(v);
        }
    }
}

// ---------------- O-projection GEMM (fp32 output) ----------------
__global__ __launch_bounds__(256, 2) void gemm_mma1(
    const __half* __restrict__ Ah, const __half* __restrict__ Bh,
    float* __restrict__ Cf)
{
    extern __shared__ char smem[];
    const uint32_t sb = smem_u32(smem);
    const int tid = threadIdx.x, wid = tid >> 5, lid = tid & 31;
    const int bm = blockIdx.y * 128, bn = blockIdx.x * 128;
    const int wm = (wid >> 2) * 64, wn = (wid & 3) * 32;

    const char* aH = (const char*)Ah + (size_t)bm * (HID*2);
    const char* bH = (const char*)Bh + (size_t)bn * (HID*2);

    int srow[4], scol[4];
    #pragma unroll
    for (int j = 0; j < 4; j++) {
        int sidx = j*256 + tid;
        srow[j] = sidx >> 3;
        scol[j] = (sidx & 7) * 16;
    }

    auto load_chunk = [&](int stage, int chunk) {
        uint32_t st = sb + stage * GT1_STAGE;
        size_t off = (size_t)chunk * 128;
        #pragma unroll
        for (int j = 0; j < 4; j++) {
            uint32_t d = SWZ128((uint32_t)(srow[j]*128 + scol[j]));
            size_t g = (size_t)srow[j] * (HID*2) + off + scol[j];
            CP16(st +     0 + d, aH + g);
            CP16(st + 16384 + d, bH + g);
        }
    };

    float acc[4][4][4];
    #pragma unroll
    for (int i = 0; i < 4; i++)
        #pragma unroll
        for (int j = 0; j < 4; j++)
            #pragma unroll
            for (int c = 0; c < 4; c++) acc[i][j][c] = 0.f;

    const int q  = lid >> 3;
    const int r8 = lid & 7;

    load_chunk(0, 0);
    CP_COMMIT();

    const int NCHUNK = HID / 64;
    for (int chunk = 0; chunk < NCHUNK; chunk++) {
        int buf = chunk & 1;
        if (chunk + 1 < NCHUNK) {
            load_chunk(buf ^ 1, chunk + 1);
            CP_COMMIT();
            CP_WAIT(1);
        } else {
            CP_WAIT(0);
        }
        __syncthreads();

        uint32_t stA  = sb + buf * GT1_STAGE;
        uint32_t stBh = stA + 16384;

        #pragma unroll
        for (int kk = 0; kk < 4; kk++) {
            uint32_t ah[16];
            #pragma unroll
            for (int i = 0; i < 4; i++) {
                int rowA = wm + i*16 + (q & 1)*8 + r8;
                int kb   = kk*32 + (q >> 1)*16;
                uint32_t off = SWZ128((uint32_t)(rowA*128 + kb));
                LDSM_X4(ah[i*4+0], ah[i*4+1], ah[i*4+2], ah[i*4+3], stA + off);
            }
            #pragma unroll
            for (int j2 = 0; j2 < 2; j2++) {
                int rowB = wn + j2*16 + (q >> 1)*8 + r8;
                int kb   = kk*32 + (q & 1)*16;
                uint32_t off = SWZ128((uint32_t)(rowB*128 + kb));
                uint32_t bh[4];
                LDSM_X4(bh[0],bh[1],bh[2],bh[3], stBh + off);
                #pragma unroll
                for (int i = 0; i < 4; i++) {
                    MMA16816(acc[i][j2*2],   &ah[i*4], &bh[0]);
                    MMA16816(acc[i][j2*2+1], &ah[i*4], &bh[2]);
                }
            }
        }
        __syncthreads();
    }

    const int gr = lid >> 2;
    const int gc = (lid & 3) * 2;
    #pragma unroll
    for (int i = 0; i < 4; i++) {
        #pragma unroll
        for (int half = 0; half < 2; half++) {
            int row = bm + wm + i*16 + gr + half*8;
            #pragma unroll
            for (int j = 0; j < 4; j++) {
                int col = wn + j*8 + gc;
                float2 v = half ? make_float2(acc[i][j][2], acc[i][j][3])
                                : make_float2(acc[i][j][0], acc[i][j][1]);
                *(float2*)(Cf + (size_t)row * HID + bn + col) = v;
            }
        }
    }
}

// ---------------- HMMA flash attention (3-stage pipeline) -----------------
#define AT_STAGE 32768
#define AT2_SMEM (32768 + 3*AT_STAGE)

__global__ __launch_bounds__(256, 1) void attn_mma()
{
    extern __shared__ char smem[];
    const uint32_t sb = smem_u32(smem);
    const int tid = threadIdx.x, wid = tid >> 5, lid = tid & 31;
    const int qt = gridDim.x - 1 - blockIdx.x;     // largest q-tiles first
    const int h = blockIdx.y, b = blockIdx.z;
    const size_t bh = (size_t)b*HEADS + h;
    const int q  = lid >> 3;
    const int r8 = lid & 7;

    const char* qHb = (const char*)g_QH + (bh*S_LEN + (size_t)qt*128) * 256;
    const char* kHb = (const char*)g_KH + bh*S_LEN*256;
    const char* vHb = (const char*)g_VtH + bh*DH*(size_t)S_LEN*2;

    #pragma unroll
    for (int it = 0; it < 8; it++) {
        int e = it*256 + tid;
        int row = e >> 4, seg = e & 15;
        int panel = seg >> 3, c = seg & 7;
        uint32_t d = SWZ128((uint32_t)(row*128 + c*16));
        CP16(sb + panel*16384 + d, qHb + row*256 + seg*16);
    }

    auto load_kv = [&](int st, int kt) {
        uint32_t stb = sb + 32768 + st*AT_STAGE;
        #pragma unroll
        for (int it = 0; it < 4; it++) {
            int e = it*256 + tid;
            int row = e >> 4, seg = e & 15;
            int panel = seg >> 3, c = seg & 7;
            uint32_t d = SWZ128((uint32_t)(row*128 + c*16));
            size_t g = (size_t)(kt*64 + row)*256 + seg*16;
            CP16(stb + panel*8192 + d, kHb + g);
        }
        #pragma unroll
        for (int it = 0; it < 4; it++) {
            int e = it*256 + tid;
            int row = e >> 3, c = e & 7;
            uint32_t d = SWZ128((uint32_t)(row*128 + c*16));
            size_t g = (size_t)row*4096 + (size_t)kt*128 + c*16;
            CP16(stb + 16384 + d, vHb + g);
        }
    };

    const int nkv = 2*qt + 2;

    load_kv(0, 0);
    CP_COMMIT();
    if (nkv > 1) { load_kv(1, 1); CP_COMMIT(); }

    float o[16][4];
    #pragma unroll
    for (int t = 0; t < 16; t++)
        #pragma unroll
        for (int c = 0; c < 4; c++) o[t][c] = 0.f;
    float m0 = -1e30f, m1 = -1e30f, l0 = 0.f, l1 = 0.f;

    const float scale = 0.08838834764831845f;
    const int qrow_lo = qt*128 + wid*16;
    const int row0 = qrow_lo + (lid >> 2);
    const int col_in = (lid & 3) * 2;

    int buf = 0;
    for (int kt = 0; kt < nkv; kt++) {
        if (kt + 2 < nkv) {
            int st2 = kt + 2;
            int b2 = st2 - (st2/3)*3;
            load_kv(b2, st2);
            CP_COMMIT();
            CP_WAIT(2);
        } else if (kt + 1 < nkv) {
            CP_WAIT(1);
        } else {
            CP_WAIT(0);
        }
        __syncthreads();

        bool skip = (kt*64 > qrow_lo + 15);
        if (!skip) {
            uint32_t stb = sb + 32768 + buf*AT_STAGE;

            float sacc[8][4];
            #pragma unroll
            for (int t = 0; t < 8; t++)
                #pragma unroll
                for (int c = 0; c < 4; c++) sacc[t][c] = 0.f;

            #pragma unroll
            for (int kk = 0; kk < 8; kk++) {
                int panel = kk >> 2;
                int kb = (kk & 3)*32;
                uint32_t qh[4];
                {
                    int rowA = wid*16 + (q & 1)*8 + r8;
                    uint32_t off = SWZ128((uint32_t)(rowA*128 + kb + (q >> 1)*16));
                    LDSM_X4(qh[0],qh[1],qh[2],qh[3], sb + panel*16384 + off);
                }
                #pragma unroll
                for (int j2 = 0; j2 < 4; j2++) {
                    int rowB = j2*16 + (q >> 1)*8 + r8;
                    uint32_t off = SWZ128((uint32_t)(rowB*128 + kb + (q & 1)*16));
                    uint32_t kh[4];
                    LDSM_X4(kh[0],kh[1],kh[2],kh[3], stb + panel*8192 + off);
                    MMA16816(sacc[j2*2],   qh, &kh[0]);
                    MMA16816(sacc[j2*2+1], qh, &kh[2]);
                }
            }

            #pragma unroll
            for (int t = 0; t < 8; t++)
                #pragma unroll
                for (int c = 0; c < 4; c++) sacc[t][c] *= scale;

            if (kt*64 + 63 > qrow_lo) {
                #pragma unroll
                for (int t = 0; t < 8; t++) {
                    int colg = kt*64 + t*8 + col_in;
                    if (colg   > row0)   sacc[t][0] = -1e30f;
                    if (colg+1 > row0)   sacc[t][1] = -1e30f;
                    if (colg   > row0+8) sacc[t][2] = -1e30f;
                    if (colg+1 > row0+8) sacc[t][3] = -1e30f;
                }
            }

            float mx0 = -1e30f, mx1 = -1e30f;
            #pragma unroll
            for (int t = 0; t < 8; t++) {
                mx0 = fmaxf(mx0, fmaxf(sacc[t][0], sacc[t][1]));
                mx1 = fmaxf(mx1, fmaxf(sacc[t][2], sacc[t][3]));
            }
            mx0 = fmaxf(mx0, __shfl_xor_sync(0xffffffffu, mx0, 1));
            mx0 = fmaxf(mx0, __shfl_xor_sync(0xffffffffu, mx0, 2));
            mx1 = fmaxf(mx1, __shfl_xor_sync(0xffffffffu, mx1, 1));
            mx1 = fmaxf(mx1, __shfl_xor_sync(0xffffffffu, mx1, 2));
            float mn0 = fmaxf(m0, mx0), mn1 = fmaxf(m1, mx1);
            float cr0 = __expf(m0 - mn0), cr1 = __expf(m1 - mn1);
            m0 = mn0; m1 = mn1;

            float s0 = 0.f, s1 = 0.f;
            #pragma unroll
            for (int t = 0; t < 8; t++) {
                sacc[t][0] = __expf(sacc[t][0] - mn0);
                sacc[t][1] = __expf(sacc[t][1] - mn0);
                sacc[t][2] = __expf(sacc[t][2] - mn1);
                sacc[t][3] = __expf(sacc[t][3] - mn1);
                s0 += sacc[t][0] + sacc[t][1];
                s1 += sacc[t][2] + sacc[t][3];
            }
            s0 += __shfl_xor_sync(0xffffffffu, s0, 1);
            s0 += __shfl_xor_sync(0xffffffffu, s0, 2);
            s1 += __shfl_xor_sync(0xffffffffu, s1, 1);
            s1 += __shfl_xor_sync(0xffffffffu, s1, 2);
            l0 = l0*cr0 + s0;
            l1 = l1*cr1 + s1;
            #pragma unroll
            for (int t = 0; t < 16; t++) {
                o[t][0] *= cr0; o[t][1] *= cr0;
                o[t][2] *= cr1; o[t][3] *= cr1;
            }

            uint32_t ph[4][4];
            #pragma unroll
            for (int t = 0; t < 4; t++) {
                #pragma unroll
                for (int u = 0; u < 2; u++) {
                    ph[t][u*2+0] = packh(sacc[2*t+u][0], sacc[2*t+u][1]);
                    ph[t][u*2+1] = packh(sacc[2*t+u][2], sacc[2*t+u][3]);
                }
            }

            #pragma unroll
            for (int ks = 0; ks < 4; ks++) {
                int kb = ks*32;
                #pragma unroll
                for (int j2 = 0; j2 < 8; j2++) {
                    int rowB = j2*16 + (q >> 1)*8 + r8;
                    uint32_t off = SWZ128((uint32_t)(rowB*128 + kb + (q & 1)*16));
                    uint32_t vh[4];
                    LDSM_X4(vh[0],vh[1],vh[2],vh[3], stb + 16384 + off);
                    MMA16816(o[j2*2],   ph[ks], &vh[0]);
                    MMA16816(o[j2*2+1], ph[ks], &vh[2]);
                }
            }
        }
        __syncthreads();
        if (++buf == 3) buf = 0;
    }

    // ---- normalize + write Ctx as fp16 ----
    float inv0 = 1.0f / l0, inv1 = 1.0f / l1;
    size_t off0 = ((size_t)b*S_LEN + row0)     * HID + h*DH + col_in;
    size_t off1 = ((size_t)b*S_LEN + row0 + 8) * HID + h*DH + col_in;
    #pragma unroll
    for (int t = 0; t < 16; t++) {
        *(__half2*)(g_CtxH + off0 + t*8) =
            __half2{__float2half(o[t][0]*inv0), __float2half(o[t][1]*inv0)};
        *(__half2*)(g_CtxH + off1 + t*8) =
            __half2{__float2half(o[t][2]*inv1), __float2half(o[t][3]*inv1)};
    }
}

// ---------------- launch ----------------
extern "C" void kernel_launch(void* const* d_in, const int* in_sizes, int n_in,
                              void* d_out, int out_size)
{
    const float* hs = (const float*)d_in[0];
    const float* Wq = (const float*)d_in[1];
    const float* Wk = (const float*)d_in[2];
    const float* Wv = (const float*)d_in[3];
    const float* Wo = (const float*)d_in[4];
    const int* pos  = (const int*)d_in[6];
    float* out = (float*)d_out;

    __half *hsH,*WqH,*WkH,*WvH,*WoH,*CtxH;
    cudaGetSymbolAddress((void**)&hsH, g_hsH);
    cudaGetSymbolAddress((void**)&WqH, g_WqH);
    cudaGetSymbolAddress((void**)&WkH, g_WkH);
    cudaGetSymbolAddress((void**)&WvH, g_WvH);
    cudaGetSymbolAddress((void**)&WoH, g_WoH);
    cudaGetSymbolAddress((void**)&CtxH, g_CtxH);

    const int NELEM = NROWS*HID;
    const int SPLIT_BLOCKS = NELEM/4/256;

    rope_table_kernel<<<(S_LEN*64)/256, 256>>>(pos);
    conv_h5_kernel<<<dim3(SPLIT_BLOCKS, 5), 256>>>(hs, hsH, Wq, WqH, Wk, WkH,
                                                   Wv, WvH, Wo, WoH);

    cudaFuncSetAttribute(gemm_qkv,  cudaFuncAttributeMaxDynamicSharedMemorySize, GT1_SMEM);
    cudaFuncSetAttribute(gemm_mma1, cudaFuncAttributeMaxDynamicSharedMemorySize, GT1_SMEM);

    gemm_qkv<<<dim3(HID/128, NROWS/128, 3), 256, GT1_SMEM>>>(hsH);

    cudaFuncSetAttribute(attn_mma, cudaFuncAttributeMaxDynamicSharedMemorySize, AT2_SMEM);
    attn_mma<<<dim3(S_LEN/128, HEADS, BATCH), 256, AT2_SMEM>>>();

    gemm_mma1<<<dim3(HID/128, NROWS/128), 256, GT1_SMEM>>>(CtxH, WoH, out);
}

// round 15
// speedup vs baseline: 4.7332x; 1.0192x over previous
#include <cuda_runtime.h>
#include <cuda_fp16.h>
#include <math.h>
#include <cstdint>

#define HEADS 32
#define S_LEN 2048
#define BATCH 2
#define HID   4096
#define DH    128
#define NROWS (BATCH*S_LEN)   // 4096
#define NBH   (BATCH*HEADS)   // 64

// ---------------- scratch (static __device__, no allocs) ----------------
__device__ float g_cos[S_LEN*64];
__device__ float g_sin[S_LEN*64];

__device__ __half g_hsH[(size_t)NROWS*HID];
__device__ __half g_WqH[(size_t)HID*HID];
__device__ __half g_WkH[(size_t)HID*HID];
__device__ __half g_WvH[(size_t)HID*HID];
__device__ __half g_WoH[(size_t)HID*HID];
__device__ __half g_CtxH[(size_t)NROWS*HID];
__device__ __half g_QH[(size_t)NBH*S_LEN*DH];
__device__ __half g_KH[(size_t)NBH*S_LEN*DH];
__device__ __half g_VtH[(size_t)NBH*DH*S_LEN];   // [bh][dh][s]

// ---------------- helpers ----------------
__device__ __forceinline__ uint32_t smem_u32(const void* p) {
    uint32_t a;
    asm("{ .reg .u64 t; cvta.to.shared.u64 t, %1; cvt.u32.u64 %0, t; }" : "=r"(a) : "l"(p));
    return a;
}
#define CP16(dst, src)    asm volatile("cp.async.cg.shared.global [%0], [%1], 16;" :: "r"(dst), "l"(src) : "memory")
#define CP_COMMIT()       asm volatile("cp.async.commit_group;" ::: "memory")
#define CP_WAIT(n)        asm volatile("cp.async.wait_group %0;" :: "n"(n) : "memory")

#define LDSM_X4(r0,r1,r2,r3,a) \
    asm volatile("ldmatrix.sync.aligned.m8n8.x4.shared.b16 {%0,%1,%2,%3}, [%4];" \
        : "=r"(r0),"=r"(r1),"=r"(r2),"=r"(r3) : "r"(a))

#define MMA16816(d, a, b) \
    asm volatile("mma.sync.aligned.m16n8k16.row.col.f32.f16.f16.f32 " \
        "{%0,%1,%2,%3}, {%4,%5,%6,%7}, {%8,%9}, {%0,%1,%2,%3};" \
        : "+f"((d)[0]),"+f"((d)[1]),"+f"((d)[2]),"+f"((d)[3]) \
        : "r"((a)[0]),"r"((a)[1]),"r"((a)[2]),"r"((a)[3]), "r"((b)[0]),"r"((b)[1]))

#define SWZ128(x) ((x) ^ (((x) >> 3) & 0x70))

__device__ __forceinline__ uint32_t packh(float lo, float hi) {
    uint32_t r;   // first src operand -> high half
    asm("cvt.rn.f16x2.f32 %0, %1, %2;" : "=r"(r) : "f"(hi), "f"(lo));
    return r;
}

// ---------------- fp32 -> fp16 convert (5 tensors, one launch) ------------
__global__ void conv_h5_kernel(const float* s0, __half* d0,
                               const float* s1, __half* d1,
                               const float* s2, __half* d2,
                               const float* s3, __half* d3,
                               const float* s4, __half* d4)
{
    const float* src;
    __half* dst;
    switch (blockIdx.y) {
        case 0: src = s0; dst = d0; break;
        case 1: src = s1; dst = d1; break;
        case 2: src = s2; dst = d2; break;
        case 3: src = s3; dst = d3; break;
        default: src = s4; dst = d4; break;
    }
    int i = (blockIdx.x*blockDim.x + threadIdx.x) * 4;
    float4 v = *(const float4*)(src + i);
    *(__half2*)(dst + i)     = __half2{__float2half(v.x), __float2half(v.y)};
    *(__half2*)(dst + i + 2) = __half2{__float2half(v.z), __float2half(v.w)};
}

// ---------------- RoPE table: one block per frequency i ----------------
__global__ void rope_table_kernel(const int* __restrict__ pos_ids)
{
    int i = blockIdx.x;                       // 0..63
    double invf = pow(10000.0, -(double)(2*i) / 128.0);
    float invff = (float)invf;
    for (int s = threadIdx.x; s < S_LEN; s += blockDim.x) {
        float pos = (float)pos_ids[s];
        float ang = pos * invff;              // same fp32 product as before
        float sn, cs;
        sincosf(ang, &sn, &cs);
        g_cos[(s<<6) + i] = cs;
        g_sin[(s<<6) + i] = sn;
    }
}

#define GT1_STAGE 32768
#define GT1_SMEM  (2*GT1_STAGE)   // also holds the 64KB fp32 epilogue tile

// ---------------- merged Q/K/V projection GEMM (z selects) ----------------
__global__ __launch_bounds__(256, 2) void gemm_qkv(const __half* __restrict__ Ah)
{
    extern __shared__ char smem[];
    const uint32_t sb = smem_u32(smem);
    const int tid = threadIdx.x, wid = tid >> 5, lid = tid & 31;
    const int bm = blockIdx.y * 128, bn = blockIdx.x * 128;
    const int wm = (wid >> 2) * 64, wn = (wid & 3) * 32;
    const int z = blockIdx.z;

    const __half* Bsel = (z == 0) ? g_WqH : (z == 1) ? g_WkH : g_WvH;

    const char* aH = (const char*)Ah + (size_t)bm * (HID*2);
    const char* bH = (const char*)Bsel + (size_t)bn * (HID*2);

    int srow[4], scol[4];
    #pragma unroll
    for (int j = 0; j < 4; j++) {
        int sidx = j*256 + tid;
        srow[j] = sidx >> 3;
        scol[j] = (sidx & 7) * 16;
    }

    auto load_chunk = [&](int stage, int chunk) {
        uint32_t st = sb + stage * GT1_STAGE;
        size_t off = (size_t)chunk * 128;
        #pragma unroll
        for (int j = 0; j < 4; j++) {
            uint32_t d = SWZ128((uint32_t)(srow[j]*128 + scol[j]));
            size_t g = (size_t)srow[j] * (HID*2) + off + scol[j];
            CP16(st +     0 + d, aH + g);
            CP16(st + 16384 + d, bH + g);
        }
    };

    float acc[4][4][4];
    #pragma unroll
    for (int i = 0; i < 4; i++)
        #pragma unroll
        for (int j = 0; j < 4; j++)
            #pragma unroll
            for (int c = 0; c < 4; c++) acc[i][j][c] = 0.f;

    const int q  = lid >> 3;
    const int r8 = lid & 7;

    load_chunk(0, 0);
    CP_COMMIT();

    const int NCHUNK = HID / 64;
    for (int chunk = 0; chunk < NCHUNK; chunk++) {
        int buf = chunk & 1;
        if (chunk + 1 < NCHUNK) {
            load_chunk(buf ^ 1, chunk + 1);
            CP_COMMIT();
            CP_WAIT(1);
        } else {
            CP_WAIT(0);
        }
        __syncthreads();

        uint32_t stA  = sb + buf * GT1_STAGE;
        uint32_t stBh = stA + 16384;

        #pragma unroll
        for (int kk = 0; kk < 4; kk++) {
            uint32_t ah[16];
            #pragma unroll
            for (int i = 0; i < 4; i++) {
                int rowA = wm + i*16 + (q & 1)*8 + r8;
                int kb   = kk*32 + (q >> 1)*16;
                uint32_t off = SWZ128((uint32_t)(rowA*128 + kb));
                LDSM_X4(ah[i*4+0], ah[i*4+1], ah[i*4+2], ah[i*4+3], stA + off);
            }
            #pragma unroll
            for (int j2 = 0; j2 < 2; j2++) {
                int rowB = wn + j2*16 + (q >> 1)*8 + r8;
                int kb   = kk*32 + (q & 1)*16;
                uint32_t off = SWZ128((uint32_t)(rowB*128 + kb));
                uint32_t bh[4];
                LDSM_X4(bh[0],bh[1],bh[2],bh[3], stBh + off);
                #pragma unroll
                for (int i = 0; i < 4; i++) {
                    MMA16816(acc[i][j2*2],   &ah[i*4], &bh[0]);
                    MMA16816(acc[i][j2*2+1], &ah[i*4], &bh[2]);
                }
            }
        }
        __syncthreads();
    }

    const int gr = lid >> 2;
    const int gc = (lid & 3) * 2;

    float* tile = (float*)smem;
    #pragma unroll
    for (int i = 0; i < 4; i++) {
        #pragma unroll
        for (int half = 0; half < 2; half++) {
            int row = wm + i*16 + gr + half*8;
            int sw  = (row & 7) << 2;
            #pragma unroll
            for (int j = 0; j < 4; j++) {
                int col = wn + j*8 + gc;
                float2 v = half ? make_float2(acc[i][j][2], acc[i][j][3])
                                : make_float2(acc[i][j][0], acc[i][j][1]);
                *(float2*)&tile[row*128 + (col ^ sw)] = v;
            }
        }
    }
    __syncthreads();

    const int b  = bm >> 11;
    const int s0 = bm & (S_LEN-1);
    const int hh = blockIdx.x;
    const size_t bhBase = (size_t)(b*HEADS + hh);

    if (z < 2) {
        __half* outp = ((z == 0) ? g_QH : g_KH) + bhBase * S_LEN * DH;
        #pragma unroll
        for (int p = 0; p < 32; p++) {
            int idx = p*256 + tid;
            int row = idx >> 6;
            int d   = idx & 63;
            int sw  = (row & 7) << 2;
            float x0 = tile[row*128 + (d ^ sw)];
            float x1 = tile[row*128 + ((d ^ sw) + 64)];
            int s = s0 + row;
            float cs = g_cos[(s<<6) + d];
            float sn = g_sin[(s<<6) + d];
            size_t o = (size_t)s * DH + d;
            outp[o]      = __float2half(x0*cs - x1*sn);
            outp[o + 64] = __float2half(x1*cs + x0*sn);
        }
    } else {
        __half* outp = g_VtH + bhBase * DH * S_LEN;
        #pragma unroll
        for (int p = 0; p < 64; p++) {
            int idx = p*256 + tid;
            int d    = idx >> 7;
            int sloc = idx & 127;
            int sw   = (sloc & 7) << 2;
            float v = tile[sloc*128 + (d ^ sw)];
            outp[(size_t)d * S_LEN + s0 + sloc] = __float2half(v);
        }
    }
}

// ---------------- O-projection GEMM (fp32 output) ----------------
__global__ __launch_bounds__(256, 2) void gemm_mma1(
    const __half* __restrict__ Ah, const __half* __restrict__ Bh,
    float* __restrict__ Cf)
{
    extern __shared__ char smem[];
    const uint32_t sb = smem_u32(smem);
    const int tid = threadIdx.x, wid = tid >> 5, lid = tid & 31;
    const int bm = blockIdx.y * 128, bn = blockIdx.x * 128;
    const int wm = (wid >> 2) * 64, wn = (wid & 3) * 32;

    const char* aH = (const char*)Ah + (size_t)bm * (HID*2);
    const char* bH = (const char*)Bh + (size_t)bn * (HID*2);

    int srow[4], scol[4];
    #pragma unroll
    for (int j = 0; j < 4; j++) {
        int sidx = j*256 + tid;
        srow[j] = sidx >> 3;
        scol[j] = (sidx & 7) * 16;
    }

    auto load_chunk = [&](int stage, int chunk) {
        uint32_t st = sb + stage * GT1_STAGE;
        size_t off = (size_t)chunk * 128;
        #pragma unroll
        for (int j = 0; j < 4; j++) {
            uint32_t d = SWZ128((uint32_t)(srow[j]*128 + scol[j]));
            size_t g = (size_t)srow[j] * (HID*2) + off + scol[j];
            CP16(st +     0 + d, aH + g);
            CP16(st + 16384 + d, bH + g);
        }
    };

    float acc[4][4][4];
    #pragma unroll
    for (int i = 0; i < 4; i++)
        #pragma unroll
        for (int j = 0; j < 4; j++)
            #pragma unroll
            for (int c = 0; c < 4; c++) acc[i][j][c] = 0.f;

    const int q  = lid >> 3;
    const int r8 = lid & 7;

    load_chunk(0, 0);
    CP_COMMIT();

    const int NCHUNK = HID / 64;
    for (int chunk = 0; chunk < NCHUNK; chunk++) {
        int buf = chunk & 1;
        if (chunk + 1 < NCHUNK) {
            load_chunk(buf ^ 1, chunk + 1);
            CP_COMMIT();
            CP_WAIT(1);
        } else {
            CP_WAIT(0);
        }
        __syncthreads();

        uint32_t stA  = sb + buf * GT1_STAGE;
        uint32_t stBh = stA + 16384;

        #pragma unroll
        for (int kk = 0; kk < 4; kk++) {
            uint32_t ah[16];
            #pragma unroll
            for (int i = 0; i < 4; i++) {
                int rowA = wm + i*16 + (q & 1)*8 + r8;
                int kb   = kk*32 + (q >> 1)*16;
                uint32_t off = SWZ128((uint32_t)(rowA*128 + kb));
                LDSM_X4(ah[i*4+0], ah[i*4+1], ah[i*4+2], ah[i*4+3], stA + off);
            }
            #pragma unroll
            for (int j2 = 0; j2 < 2; j2++) {
                int rowB = wn + j2*16 + (q >> 1)*8 + r8;
                int kb   = kk*32 + (q & 1)*16;
                uint32_t off = SWZ128((uint32_t)(rowB*128 + kb));
                uint32_t bh[4];
                LDSM_X4(bh[0],bh[1],bh[2],bh[3], stBh + off);
                #pragma unroll
                for (int i = 0; i < 4; i++) {
                    MMA16816(acc[i][j2*2],   &ah[i*4], &bh[0]);
                    MMA16816(acc[i][j2*2+1], &ah[i*4], &bh[2]);
                }
            }
        }
        __syncthreads();
    }

    const int gr = lid >> 2;
    const int gc = (lid & 3) * 2;
    #pragma unroll
    for (int i = 0; i < 4; i++) {
        #pragma unroll
        for (int half = 0; half < 2; half++) {
            int row = bm + wm + i*16 + gr + half*8;
            #pragma unroll
            for (int j = 0; j < 4; j++) {
                int col = wn + j*8 + gc;
                float2 v = half ? make_float2(acc[i][j][2], acc[i][j][3])
                                : make_float2(acc[i][j][0], acc[i][j][1]);
                *(float2*)(Cf + (size_t)row * HID + bn + col) = v;
            }
        }
    }
}

// ---------------- HMMA flash attention: 64 q-rows/CTA, 128 thr, 2 CTA/SM --
// smem: Q 16K | 2 stages x { Kh 2x8K, VtH 16K } = 16K + 64K = 80K
#define AT_STAGE 32768
#define AT2_SMEM (16384 + 2*AT_STAGE)

__global__ __launch_bounds__(128, 2) void attn_mma()
{
    extern __shared__ char smem[];
    const uint32_t sb = smem_u32(smem);
    const int tid = threadIdx.x, wid = tid >> 5, lid = tid & 31;
    const int qt = gridDim.x - 1 - blockIdx.x;     // largest q-tiles first
    const int h = blockIdx.y, b = blockIdx.z;
    const size_t bh = (size_t)b*HEADS + h;
    const int q  = lid >> 3;
    const int r8 = lid & 7;

    const char* qHb = (const char*)g_QH + (bh*S_LEN + (size_t)qt*64) * 256;
    const char* kHb = (const char*)g_KH + bh*S_LEN*256;
    const char* vHb = (const char*)g_VtH + bh*DH*(size_t)S_LEN*2;

    // ---- Q load: 64 rows x 16 segs = 1024, 8 iters x 128 thr ----
    #pragma unroll
    for (int it = 0; it < 8; it++) {
        int e = it*128 + tid;
        int row = e >> 4, seg = e & 15;
        int panel = seg >> 3, c = seg & 7;
        uint32_t d = SWZ128((uint32_t)(row*128 + c*16));
        CP16(sb + panel*8192 + d, qHb + row*256 + seg*16);
    }

    auto load_kv = [&](int st, int kt) {
        uint32_t stb = sb + 16384 + st*AT_STAGE;
        #pragma unroll
        for (int it = 0; it < 8; it++) {
            int e = it*128 + tid;
            int row = e >> 4, seg = e & 15;
            int panel = seg >> 3, c = seg & 7;
            uint32_t d = SWZ128((uint32_t)(row*128 + c*16));
            size_t g = (size_t)(kt*64 + row)*256 + seg*16;
            CP16(stb + panel*8192 + d, kHb + g);
        }
        #pragma unroll
        for (int it = 0; it < 8; it++) {
            int e = it*128 + tid;
            int row = e >> 3, c = e & 7;
            uint32_t d = SWZ128((uint32_t)(row*128 + c*16));
            size_t g = (size_t)row*4096 + (size_t)kt*128 + c*16;
            CP16(stb + 16384 + d, vHb + g);
        }
    };

    load_kv(0, 0);
    CP_COMMIT();

    float o[16][4];
    #pragma unroll
    for (int t = 0; t < 16; t++)
        #pragma unroll
        for (int c = 0; c < 4; c++) o[t][c] = 0.f;
    float m0 = -1e30f, m1 = -1e30f, l0 = 0.f, l1 = 0.f;

    const float scale = 0.08838834764831845f;
    const int qrow_lo = qt*64 + wid*16;
    const int row0 = qrow_lo + (lid >> 2);
    const int col_in = (lid & 3) * 2;

    const int nkv = qt + 1;
    for (int kt = 0; kt < nkv; kt++) {
        int buf = kt & 1;
        if (kt + 1 < nkv) {
            load_kv(buf ^ 1, kt + 1);
            CP_COMMIT();
            CP_WAIT(1);
        } else {
            CP_WAIT(0);
        }
        __syncthreads();

        bool skip = (kt*64 > qrow_lo + 15);
        if (!skip) {
            uint32_t stb = sb + 16384 + buf*AT_STAGE;

            float sacc[8][4];
            #pragma unroll
            for (int t = 0; t < 8; t++)
                #pragma unroll
                for (int c = 0; c < 4; c++) sacc[t][c] = 0.f;

            #pragma unroll
            for (int kk = 0; kk < 8; kk++) {
                int panel = kk >> 2;
                int kb = (kk & 3)*32;
                uint32_t qh[4];
                {
                    int rowA = wid*16 + (q & 1)*8 + r8;
                    uint32_t off = SWZ128((uint32_t)(rowA*128 + kb + (q >> 1)*16));
                    LDSM_X4(qh[0],qh[1],qh[2],qh[3], sb + panel*8192 + off);
                }
                #pragma unroll
                for (int j2 = 0; j2 < 4; j2++) {
                    int rowB = j2*16 + (q >> 1)*8 + r8;
                    uint32_t off = SWZ128((uint32_t)(rowB*128 + kb + (q & 1)*16));
                    uint32_t kh[4];
                    LDSM_X4(kh[0],kh[1],kh[2],kh[3], stb + panel*8192 + off);
                    MMA16816(sacc[j2*2],   qh, &kh[0]);
                    MMA16816(sacc[j2*2+1], qh, &kh[2]);
                }
            }

            #pragma unroll
            for (int t = 0; t < 8; t++)
                #pragma unroll
                for (int c = 0; c < 4; c++) sacc[t][c] *= scale;

            if (kt*64 + 63 > qrow_lo) {
                #pragma unroll
                for (int t = 0; t < 8; t++) {
                    int colg = kt*64 + t*8 + col_in;
                    if (colg   > row0)   sacc[t][0] = -1e30f;
                    if (colg+1 > row0)   sacc[t][1] = -1e30f;
                    if (colg   > row0+8) sacc[t][2] = -1e30f;
                    if (colg+1 > row0+8) sacc[t][3] = -1e30f;
                }
            }

            float mx0 = -1e30f, mx1 = -1e30f;
            #pragma unroll
            for (int t = 0; t < 8; t++) {
                mx0 = fmaxf(mx0, fmaxf(sacc[t][0], sacc[t][1]));
                mx1 = fmaxf(mx1, fmaxf(sacc[t][2], sacc[t][3]));
            }
            mx0 = fmaxf(mx0, __shfl_xor_sync(0xffffffffu, mx0, 1));
            mx0 = fmaxf(mx0, __shfl_xor_sync(0xffffffffu, mx0, 2));
            mx1 = fmaxf(mx1, __shfl_xor_sync(0xffffffffu, mx1, 1));
            mx1 = fmaxf(mx1, __shfl_xor_sync(0xffffffffu, mx1, 2));
            float mn0 = fmaxf(m0, mx0), mn1 = fmaxf(m1, mx1);
            float cr0 = __expf(m0 - mn0), cr1 = __expf(m1 - mn1);
            m0 = mn0; m1 = mn1;

            float s0 = 0.f, s1 = 0.f;
            #pragma unroll
            for (int t = 0; t < 8; t++) {
                sacc[t][0] = __expf(sacc[t][0] - mn0);
                sacc[t][1] = __expf(sacc[t][1] - mn0);
                sacc[t][2] = __expf(sacc[t][2] - mn1);
                sacc[t][3] = __expf(sacc[t][3] - mn1);
                s0 += sacc[t][0] + sacc[t][1];
                s1 += sacc[t][2] + sacc[t][3];
            }
            s0 += __shfl_xor_sync(0xffffffffu, s0, 1);
            s0 += __shfl_xor_sync(0xffffffffu, s0, 2);
            s1 += __shfl_xor_sync(0xffffffffu, s1, 1);
            s1 += __shfl_xor_sync(0xffffffffu, s1, 2);
            l0 = l0*cr0 + s0;
            l1 = l1*cr1 + s1;

            // skip o-rescale when no lane's max moved (cr==1 exactly)
            if (!__all_sync(0xffffffffu, (cr0 == 1.f) & (cr1 == 1.f))) {
                #pragma unroll
                for (int t = 0; t < 16; t++) {
                    o[t][0] *= cr0; o[t][1] *= cr0;
                    o[t][2] *= cr1; o[t][3] *= cr1;
                }
            }

            uint32_t ph[4][4];
            #pragma unroll
            for (int t = 0; t < 4; t++) {
                #pragma unroll
                for (int u = 0; u < 2; u++) {
                    ph[t][u*2+0] = packh(sacc[2*t+u][0], sacc[2*t+u][1]);
                    ph[t][u*2+1] = packh(sacc[2*t+u][2], sacc[2*t+u][3]);
                }
            }

            #pragma unroll
            for (int ks = 0; ks < 4; ks++) {
                int kb = ks*32;
                #pragma unroll
                for (int j2 = 0; j2 < 8; j2++) {
                    int rowB = j2*16 + (q >> 1)*8 + r8;
                    uint32_t off = SWZ128((uint32_t)(rowB*128 + kb + (q & 1)*16));
                    uint32_t vh[4];
                    LDSM_X4(vh[0],vh[1],vh[2],vh[3], stb + 16384 + off);
                    MMA16816(o[j2*2],   ph[ks], &vh[0]);
                    MMA16816(o[j2*2+1], ph[ks], &vh[2]);
                }
            }
        }
        __syncthreads();
    }

    // ---- normalize + write Ctx as fp16 ----
    float inv0 = 1.0f / l0, inv1 = 1.0f / l1;
    size_t off0 = ((size_t)b*S_LEN + row0)     * HID + h*DH + col_in;
    size_t off1 = ((size_t)b*S_LEN + row0 + 8) * HID + h*DH + col_in;
    #pragma unroll
    for (int t = 0; t < 16; t++) {
        *(__half2*)(g_CtxH + off0 + t*8) =
            __half2{__float2half(o[t][0]*inv0), __float2half(o[t][1]*inv0)};
        *(__half2*)(g_CtxH + off1 + t*8) =
            __half2{__float2half(o[t][2]*inv1), __float2half(o[t][3]*inv1)};
    }
}

// ---------------- launch ----------------
extern "C" void kernel_launch(void* const* d_in, const int* in_sizes, int n_in,
                              void* d_out, int out_size)
{
    const float* hs = (const float*)d_in[0];
    const float* Wq = (const float*)d_in[1];
    const float* Wk = (const float*)d_in[2];
    const float* Wv = (const float*)d_in[3];
    const float* Wo = (const float*)d_in[4];
    const int* pos  = (const int*)d_in[6];
    float* out = (float*)d_out;

    __half *hsH,*WqH,*WkH,*WvH,*WoH,*CtxH;
    cudaGetSymbolAddress((void**)&hsH, g_hsH);
    cudaGetSymbolAddress((void**)&WqH, g_WqH);
    cudaGetSymbolAddress((void**)&WkH, g_WkH);
    cudaGetSymbolAddress((void**)&WvH, g_WvH);
    cudaGetSymbolAddress((void**)&WoH, g_WoH);
    cudaGetSymbolAddress((void**)&CtxH, g_CtxH);

    const int NELEM = NROWS*HID;
    const int SPLIT_BLOCKS = NELEM/4/256;

    rope_table_kernel<<<64, 256>>>(pos);
    conv_h5_kernel<<<dim3(SPLIT_BLOCKS, 5), 256>>>(hs, hsH, Wq, WqH, Wk, WkH,
                                                   Wv, WvH, Wo, WoH);

    cudaFuncSetAttribute(gemm_qkv,  cudaFuncAttributeMaxDynamicSharedMemorySize, GT1_SMEM);
    cudaFuncSetAttribute(gemm_mma1, cudaFuncAttributeMaxDynamicSharedMemorySize, GT1_SMEM);

    gemm_qkv<<<dim3(HID/128, NROWS/128, 3), 256, GT1_SMEM>>>(hsH);

    cudaFuncSetAttribute(attn_mma, cudaFuncAttributeMaxDynamicSharedMemorySize, AT2_SMEM);
    attn_mma<<<dim3(S_LEN/64, HEADS, BATCH), 128, AT2_SMEM>>>();

    gemm_mma1<<<dim3(HID/128, NROWS/128), 256, GT1_SMEM>>>(CtxH, WoH, out);
}

// round 16
// speedup vs baseline: 4.7543x; 1.0045x over previous
#include <cuda_runtime.h>
#include <cuda_fp16.h>
#include <math.h>
#include <cstdint>

#define HEADS 32
#define S_LEN 2048
#define BATCH 2
#define HID   4096
#define DH    128
#define NROWS (BATCH*S_LEN)   // 4096
#define NBH   (BATCH*HEADS)   // 64

// scale * log2(e): QK logits land pre-scaled for exp2
#define QSCALE 0.12752465f    // (1/sqrt(128)) * 1.4426950408889634

// ---------------- scratch (static __device__, no allocs) ----------------
__device__ float g_cos[S_LEN*64];
__device__ float g_sin[S_LEN*64];

__device__ __half g_hsH[(size_t)NROWS*HID];
__device__ __half g_WqH[(size_t)HID*HID];
__device__ __half g_WkH[(size_t)HID*HID];
__device__ __half g_WvH[(size_t)HID*HID];
__device__ __half g_WoH[(size_t)HID*HID];
__device__ __half g_CtxH[(size_t)NROWS*HID];
__device__ __half g_QH[(size_t)NBH*S_LEN*DH];
__device__ __half g_KH[(size_t)NBH*S_LEN*DH];
__device__ __half g_VtH[(size_t)NBH*DH*S_LEN];   // [bh][dh][s]

// ---------------- helpers ----------------
__device__ __forceinline__ uint32_t smem_u32(const void* p) {
    uint32_t a;
    asm("{ .reg .u64 t; cvta.to.shared.u64 t, %1; cvt.u32.u64 %0, t; }" : "=r"(a) : "l"(p));
    return a;
}
#define CP16(dst, src)    asm volatile("cp.async.cg.shared.global [%0], [%1], 16;" :: "r"(dst), "l"(src) : "memory")
#define CP_COMMIT()       asm volatile("cp.async.commit_group;" ::: "memory")
#define CP_WAIT(n)        asm volatile("cp.async.wait_group %0;" :: "n"(n) : "memory")

#define LDSM_X4(r0,r1,r2,r3,a) \
    asm volatile("ldmatrix.sync.aligned.m8n8.x4.shared.b16 {%0,%1,%2,%3}, [%4];" \
        : "=r"(r0),"=r"(r1),"=r"(r2),"=r"(r3) : "r"(a))

#define MMA16816(d, a, b) \
    asm volatile("mma.sync.aligned.m16n8k16.row.col.f32.f16.f16.f32 " \
        "{%0,%1,%2,%3}, {%4,%5,%6,%7}, {%8,%9}, {%0,%1,%2,%3};" \
        : "+f"((d)[0]),"+f"((d)[1]),"+f"((d)[2]),"+f"((d)[3]) \
        : "r"((a)[0]),"r"((a)[1]),"r"((a)[2]),"r"((a)[3]), "r"((b)[0]),"r"((b)[1]))

#define SWZ128(x) ((x) ^ (((x) >> 3) & 0x70))

__device__ __forceinline__ uint32_t packh(float lo, float hi) {
    uint32_t r;   // first src operand -> high half
    asm("cvt.rn.f16x2.f32 %0, %1, %2;" : "=r"(r) : "f"(hi), "f"(lo));
    return r;
}

// ---------------- fp32 -> fp16 convert (5 tensors) + rope table -----------
__global__ void conv_h5_kernel(const float* s0, __half* d0,
                               const float* s1, __half* d1,
                               const float* s2, __half* d2,
                               const float* s3, __half* d3,
                               const float* s4, __half* d4,
                               const int* __restrict__ pos_ids)
{
    if (blockIdx.y == 5) {
        // rope table: first 64 blocks, one frequency each
        int i = blockIdx.x;
        if (i >= 64) return;
        double invf = pow(10000.0, -(double)(2*i) / 128.0);
        float invff = (float)invf;
        for (int s = threadIdx.x; s < S_LEN; s += blockDim.x) {
            float pos = (float)pos_ids[s];
            float ang = pos * invff;
            float sn, cs;
            sincosf(ang, &sn, &cs);
            g_cos[(s<<6) + i] = cs;
            g_sin[(s<<6) + i] = sn;
        }
        return;
    }
    const float* src;
    __half* dst;
    switch (blockIdx.y) {
        case 0: src = s0; dst = d0; break;
        case 1: src = s1; dst = d1; break;
        case 2: src = s2; dst = d2; break;
        case 3: src = s3; dst = d3; break;
        default: src = s4; dst = d4; break;
    }
    int i = (blockIdx.x*blockDim.x + threadIdx.x) * 4;
    float4 v = *(const float4*)(src + i);
    *(__half2*)(dst + i)     = __half2{__float2half(v.x), __float2half(v.y)};
    *(__half2*)(dst + i + 2) = __half2{__float2half(v.z), __float2half(v.w)};
}

#define GT1_STAGE 32768
#define GT1_SMEM  (2*GT1_STAGE)   // also holds the 64KB fp32 epilogue tile

// ---------------- merged Q/K/V projection GEMM (z selects) ----------------
__global__ __launch_bounds__(256, 2) void gemm_qkv(const __half* __restrict__ Ah)
{
    extern __shared__ char smem[];
    const uint32_t sb = smem_u32(smem);
    const int tid = threadIdx.x, wid = tid >> 5, lid = tid & 31;
    const int bm = blockIdx.y * 128, bn = blockIdx.x * 128;
    const int wm = (wid >> 2) * 64, wn = (wid & 3) * 32;
    const int z = blockIdx.z;

    const __half* Bsel = (z == 0) ? g_WqH : (z == 1) ? g_WkH : g_WvH;

    const char* aH = (const char*)Ah + (size_t)bm * (HID*2);
    const char* bH = (const char*)Bsel + (size_t)bn * (HID*2);

    int srow[4], scol[4];
    #pragma unroll
    for (int j = 0; j < 4; j++) {
        int sidx = j*256 + tid;
        srow[j] = sidx >> 3;
        scol[j] = (sidx & 7) * 16;
    }

    auto load_chunk = [&](int stage, int chunk) {
        uint32_t st = sb + stage * GT1_STAGE;
        size_t off = (size_t)chunk * 128;
        #pragma unroll
        for (int j = 0; j < 4; j++) {
            uint32_t d = SWZ128((uint32_t)(srow[j]*128 + scol[j]));
            size_t g = (size_t)srow[j] * (HID*2) + off + scol[j];
            CP16(st +     0 + d, aH + g);
            CP16(st + 16384 + d, bH + g);
        }
    };

    float acc[4][4][4];
    #pragma unroll
    for (int i = 0; i < 4; i++)
        #pragma unroll
        for (int j = 0; j < 4; j++)
            #pragma unroll
            for (int c = 0; c < 4; c++) acc[i][j][c] = 0.f;

    const int q  = lid >> 3;
    const int r8 = lid & 7;

    load_chunk(0, 0);
    CP_COMMIT();

    const int NCHUNK = HID / 64;
    for (int chunk = 0; chunk < NCHUNK; chunk++) {
        int buf = chunk & 1;
        if (chunk + 1 < NCHUNK) {
            load_chunk(buf ^ 1, chunk + 1);
            CP_COMMIT();
            CP_WAIT(1);
        } else {
            CP_WAIT(0);
        }
        __syncthreads();

        uint32_t stA  = sb + buf * GT1_STAGE;
        uint32_t stBh = stA + 16384;

        #pragma unroll
        for (int kk = 0; kk < 4; kk++) {
            uint32_t ah[16];
            #pragma unroll
            for (int i = 0; i < 4; i++) {
                int rowA = wm + i*16 + (q & 1)*8 + r8;
                int kb   = kk*32 + (q >> 1)*16;
                uint32_t off = SWZ128((uint32_t)(rowA*128 + kb));
                LDSM_X4(ah[i*4+0], ah[i*4+1], ah[i*4+2], ah[i*4+3], stA + off);
            }
            #pragma unroll
            for (int j2 = 0; j2 < 2; j2++) {
                int rowB = wn + j2*16 + (q >> 1)*8 + r8;
                int kb   = kk*32 + (q & 1)*16;
                uint32_t off = SWZ128((uint32_t)(rowB*128 + kb));
                uint32_t bh[4];
                LDSM_X4(bh[0],bh[1],bh[2],bh[3], stBh + off);
                #pragma unroll
                for (int i = 0; i < 4; i++) {
                    MMA16816(acc[i][j2*2],   &ah[i*4], &bh[0]);
                    MMA16816(acc[i][j2*2+1], &ah[i*4], &bh[2]);
                }
            }
        }
        __syncthreads();
    }

    const int gr = lid >> 2;
    const int gc = (lid & 3) * 2;

    float* tile = (float*)smem;
    #pragma unroll
    for (int i = 0; i < 4; i++) {
        #pragma unroll
        for (int half = 0; half < 2; half++) {
            int row = wm + i*16 + gr + half*8;
            int sw  = (row & 7) << 2;
            #pragma unroll
            for (int j = 0; j < 4; j++) {
                int col = wn + j*8 + gc;
                float2 v = half ? make_float2(acc[i][j][2], acc[i][j][3])
                                : make_float2(acc[i][j][0], acc[i][j][1]);
                *(float2*)&tile[row*128 + (col ^ sw)] = v;
            }
        }
    }
    __syncthreads();

    const int b  = bm >> 11;
    const int s0 = bm & (S_LEN-1);
    const int hh = blockIdx.x;
    const size_t bhBase = (size_t)(b*HEADS + hh);

    if (z < 2) {
        // RoPE + fp16; Q additionally folded with scale*log2e
        const float fs = (z == 0) ? QSCALE : 1.0f;
        __half* outp = ((z == 0) ? g_QH : g_KH) + bhBase * S_LEN * DH;
        #pragma unroll
        for (int p = 0; p < 32; p++) {
            int idx = p*256 + tid;
            int row = idx >> 6;
            int d   = idx & 63;
            int sw  = (row & 7) << 2;
            float x0 = tile[row*128 + (d ^ sw)];
            float x1 = tile[row*128 + ((d ^ sw) + 64)];
            int s = s0 + row;
            float cs = g_cos[(s<<6) + d];
            float sn = g_sin[(s<<6) + d];
            size_t o = (size_t)s * DH + d;
            outp[o]      = __float2half((x0*cs - x1*sn) * fs);
            outp[o + 64] = __float2half((x1*cs + x0*sn) * fs);
        }
    } else {
        __half* outp = g_VtH + bhBase * DH * S_LEN;
        #pragma unroll
        for (int p = 0; p < 64; p++) {
            int idx = p*256 + tid;
            int d    = idx >> 7;
            int sloc = idx & 127;
            int sw   = (sloc & 7) << 2;
            float v = tile[sloc*128 + (d ^ sw)];
            outp[(size_t)d * S_LEN + s0 + sloc] = __float2half(v);
        }
    }
}

// ---------------- O-projection GEMM (fp32 output) ----------------
__global__ __launch_bounds__(256, 2) void gemm_mma1(
    const __half* __restrict__ Ah, const __half* __restrict__ Bh,
    float* __restrict__ Cf)
{
    extern __shared__ char smem[];
    const uint32_t sb = smem_u32(smem);
    const int tid = threadIdx.x, wid = tid >> 5, lid = tid & 31;
    const int bm = blockIdx.y * 128, bn = blockIdx.x * 128;
    const int wm = (wid >> 2) * 64, wn = (wid & 3) * 32;

    const char* aH = (const char*)Ah + (size_t)bm * (HID*2);
    const char* bH = (const char*)Bh + (size_t)bn * (HID*2);

    int srow[4], scol[4];
    #pragma unroll
    for (int j = 0; j < 4; j++) {
        int sidx = j*256 + tid;
        srow[j] = sidx >> 3;
        scol[j] = (sidx & 7) * 16;
    }

    auto load_chunk = [&](int stage, int chunk) {
        uint32_t st = sb + stage * GT1_STAGE;
        size_t off = (size_t)chunk * 128;
        #pragma unroll
        for (int j = 0; j < 4; j++) {
            uint32_t d = SWZ128((uint32_t)(srow[j]*128 + scol[j]));
            size_t g = (size_t)srow[j] * (HID*2) + off + scol[j];
            CP16(st +     0 + d, aH + g);
            CP16(st + 16384 + d, bH + g);
        }
    };

    float acc[4][4][4];
    #pragma unroll
    for (int i = 0; i < 4; i++)
        #pragma unroll
        for (int j = 0; j < 4; j++)
            #pragma unroll
            for (int c = 0; c < 4; c++) acc[i][j][c] = 0.f;

    const int q  = lid >> 3;
    const int r8 = lid & 7;

    load_chunk(0, 0);
    CP_COMMIT();

    const int NCHUNK = HID / 64;
    for (int chunk = 0; chunk < NCHUNK; chunk++) {
        int buf = chunk & 1;
        if (chunk + 1 < NCHUNK) {
            load_chunk(buf ^ 1, chunk + 1);
            CP_COMMIT();
            CP_WAIT(1);
        } else {
            CP_WAIT(0);
        }
        __syncthreads();

        uint32_t stA  = sb + buf * GT1_STAGE;
        uint32_t stBh = stA + 16384;

        #pragma unroll
        for (int kk = 0; kk < 4; kk++) {
            uint32_t ah[16];
            #pragma unroll
            for (int i = 0; i < 4; i++) {
                int rowA = wm + i*16 + (q & 1)*8 + r8;
                int kb   = kk*32 + (q >> 1)*16;
                uint32_t off = SWZ128((uint32_t)(rowA*128 + kb));
                LDSM_X4(ah[i*4+0], ah[i*4+1], ah[i*4+2], ah[i*4+3], stA + off);
            }
            #pragma unroll
            for (int j2 = 0; j2 < 2; j2++) {
                int rowB = wn + j2*16 + (q >> 1)*8 + r8;
                int kb   = kk*32 + (q & 1)*16;
                uint32_t off = SWZ128((uint32_t)(rowB*128 + kb));
                uint32_t bh[4];
                LDSM_X4(bh[0],bh[1],bh[2],bh[3], stBh + off);
                #pragma unroll
                for (int i = 0; i < 4; i++) {
                    MMA16816(acc[i][j2*2],   &ah[i*4], &bh[0]);
                    MMA16816(acc[i][j2*2+1], &ah[i*4], &bh[2]);
                }
            }
        }
        __syncthreads();
    }

    const int gr = lid >> 2;
    const int gc = (lid & 3) * 2;
    #pragma unroll
    for (int i = 0; i < 4; i++) {
        #pragma unroll
        for (int half = 0; half < 2; half++) {
            int row = bm + wm + i*16 + gr + half*8;
            #pragma unroll
            for (int j = 0; j < 4; j++) {
                int col = wn + j*8 + gc;
                float2 v = half ? make_float2(acc[i][j][2], acc[i][j][3])
                                : make_float2(acc[i][j][0], acc[i][j][1]);
                *(float2*)(Cf + (size_t)row * HID + bn + col) = v;
            }
        }
    }
}

// ---------------- HMMA flash attention: 64 q-rows/CTA, 128 thr, 2 CTA/SM --
#define AT_STAGE 32768
#define AT2_SMEM (16384 + 2*AT_STAGE)

__global__ __launch_bounds__(128, 2) void attn_mma()
{
    extern __shared__ char smem[];
    const uint32_t sb = smem_u32(smem);
    const int tid = threadIdx.x, wid = tid >> 5, lid = tid & 31;
    const int qt = gridDim.x - 1 - blockIdx.x;     // largest q-tiles first
    const int h = blockIdx.y, b = blockIdx.z;
    const size_t bh = (size_t)b*HEADS + h;
    const int q  = lid >> 3;
    const int r8 = lid & 7;

    const char* qHb = (const char*)g_QH + (bh*S_LEN + (size_t)qt*64) * 256;
    const char* kHb = (const char*)g_KH + bh*S_LEN*256;
    const char* vHb = (const char*)g_VtH + bh*DH*(size_t)S_LEN*2;

    #pragma unroll
    for (int it = 0; it < 8; it++) {
        int e = it*128 + tid;
        int row = e >> 4, seg = e & 15;
        int panel = seg >> 3, c = seg & 7;
        uint32_t d = SWZ128((uint32_t)(row*128 + c*16));
        CP16(sb + panel*8192 + d, qHb + row*256 + seg*16);
    }

    auto load_kv = [&](int st, int kt) {
        uint32_t stb = sb + 16384 + st*AT_STAGE;
        #pragma unroll
        for (int it = 0; it < 8; it++) {
            int e = it*128 + tid;
            int row = e >> 4, seg = e & 15;
            int panel = seg >> 3, c = seg & 7;
            uint32_t d = SWZ128((uint32_t)(row*128 + c*16));
            size_t g = (size_t)(kt*64 + row)*256 + seg*16;
            CP16(stb + panel*8192 + d, kHb + g);
        }
        #pragma unroll
        for (int it = 0; it < 8; it++) {
            int e = it*128 + tid;
            int row = e >> 3, c = e & 7;
            uint32_t d = SWZ128((uint32_t)(row*128 + c*16));
            size_t g = (size_t)row*4096 + (size_t)kt*128 + c*16;
            CP16(stb + 16384 + d, vHb + g);
        }
    };

    load_kv(0, 0);
    CP_COMMIT();

    float o[16][4];
    #pragma unroll
    for (int t = 0; t < 16; t++)
        #pragma unroll
        for (int c = 0; c < 4; c++) o[t][c] = 0.f;
    float m0 = -1e30f, m1 = -1e30f, l0 = 0.f, l1 = 0.f;

    const int qrow_lo = qt*64 + wid*16;
    const int row0 = qrow_lo + (lid >> 2);
    const int col_in = (lid & 3) * 2;

    const int nkv = qt + 1;
    for (int kt = 0; kt < nkv; kt++) {
        int buf = kt & 1;
        if (kt + 1 < nkv) {
            load_kv(buf ^ 1, kt + 1);
            CP_COMMIT();
            CP_WAIT(1);
        } else {
            CP_WAIT(0);
        }
        __syncthreads();

        bool skip = (kt*64 > qrow_lo + 15);
        if (!skip) {
            uint32_t stb = sb + 16384 + buf*AT_STAGE;

            float sacc[8][4];
            #pragma unroll
            for (int t = 0; t < 8; t++)
                #pragma unroll
                for (int c = 0; c < 4; c++) sacc[t][c] = 0.f;

            #pragma unroll
            for (int kk = 0; kk < 8; kk++) {
                int panel = kk >> 2;
                int kb = (kk & 3)*32;
                uint32_t qh[4];
                {
                    int rowA = wid*16 + (q & 1)*8 + r8;
                    uint32_t off = SWZ128((uint32_t)(rowA*128 + kb + (q >> 1)*16));
                    LDSM_X4(qh[0],qh[1],qh[2],qh[3], sb + panel*8192 + off);
                }
                #pragma unroll
                for (int j2 = 0; j2 < 4; j2++) {
                    int rowB = j2*16 + (q >> 1)*8 + r8;
                    uint32_t off = SWZ128((uint32_t)(rowB*128 + kb + (q & 1)*16));
                    uint32_t kh[4];
                    LDSM_X4(kh[0],kh[1],kh[2],kh[3], stb + panel*8192 + off);
                    MMA16816(sacc[j2*2],   qh, &kh[0]);
                    MMA16816(sacc[j2*2+1], qh, &kh[2]);
                }
            }

            // (scale*log2e pre-folded into Q — sacc is already in exp2 domain)
            if (kt*64 + 63 > qrow_lo) {
                #pragma unroll
                for (int t = 0; t < 8; t++) {
                    int colg = kt*64 + t*8 + col_in;
                    if (colg   > row0)   sacc[t][0] = -1e30f;
                    if (colg+1 > row0)   sacc[t][1] = -1e30f;
                    if (colg   > row0+8) sacc[t][2] = -1e30f;
                    if (colg+1 > row0+8) sacc[t][3] = -1e30f;
                }
            }

            float mx0 = -1e30f, mx1 = -1e30f;
            #pragma unroll
            for (int t = 0; t < 8; t++) {
                mx0 = fmaxf(mx0, fmaxf(sacc[t][0], sacc[t][1]));
                mx1 = fmaxf(mx1, fmaxf(sacc[t][2], sacc[t][3]));
            }
            mx0 = fmaxf(mx0, __shfl_xor_sync(0xffffffffu, mx0, 1));
            mx0 = fmaxf(mx0, __shfl_xor_sync(0xffffffffu, mx0, 2));
            mx1 = fmaxf(mx1, __shfl_xor_sync(0xffffffffu, mx1, 1));
            mx1 = fmaxf(mx1, __shfl_xor_sync(0xffffffffu, mx1, 2));
            float mn0 = fmaxf(m0, mx0), mn1 = fmaxf(m1, mx1);
            float cr0 = exp2f(m0 - mn0), cr1 = exp2f(m1 - mn1);
            m0 = mn0; m1 = mn1;

            float s0 = 0.f, s1 = 0.f;
            #pragma unroll
            for (int t = 0; t < 8; t++) {
                sacc[t][0] = exp2f(sacc[t][0] - mn0);
                sacc[t][1] = exp2f(sacc[t][1] - mn0);
                sacc[t][2] = exp2f(sacc[t][2] - mn1);
                sacc[t][3] = exp2f(sacc[t][3] - mn1);
                s0 += sacc[t][0] + sacc[t][1];
                s1 += sacc[t][2] + sacc[t][3];
            }
            s0 += __shfl_xor_sync(0xffffffffu, s0, 1);
            s0 += __shfl_xor_sync(0xffffffffu, s0, 2);
            s1 += __shfl_xor_sync(0xffffffffu, s1, 1);
            s1 += __shfl_xor_sync(0xffffffffu, s1, 2);
            l0 = l0*cr0 + s0;
            l1 = l1*cr1 + s1;

            if (!__all_sync(0xffffffffu, (cr0 == 1.f) & (cr1 == 1.f))) {
                #pragma unroll
                for (int t = 0; t < 16; t++) {
                    o[t][0] *= cr0; o[t][1] *= cr0;
                    o[t][2] *= cr1; o[t][3] *= cr1;
                }
            }

            uint32_t ph[4][4];
            #pragma unroll
            for (int t = 0; t < 4; t++) {
                #pragma unroll
                for (int u = 0; u < 2; u++) {
                    ph[t][u*2+0] = packh(sacc[2*t+u][0], sacc[2*t+u][1]);
                    ph[t][u*2+1] = packh(sacc[2*t+u][2], sacc[2*t+u][3]);
                }
            }

            #pragma unroll
            for (int ks = 0; ks < 4; ks++) {
                int kb = ks*32;
                #pragma unroll
                for (int j2 = 0; j2 < 8; j2++) {
                    int rowB = j2*16 + (q >> 1)*8 + r8;
                    uint32_t off = SWZ128((uint32_t)(rowB*128 + kb + (q & 1)*16));
                    uint32_t vh[4];
                    LDSM_X4(vh[0],vh[1],vh[2],vh[3], stb + 16384 + off);
                    MMA16816(o[j2*2],   ph[ks], &vh[0]);
                    MMA16816(o[j2*2+1], ph[ks], &vh[2]);
                }
            }
        }
        __syncthreads();
    }

    // ---- normalize + write Ctx as fp16 ----
    float inv0 = 1.0f / l0, inv1 = 1.0f / l1;
    size_t off0 = ((size_t)b*S_LEN + row0)     * HID + h*DH + col_in;
    size_t off1 = ((size_t)b*S_LEN + row0 + 8) * HID + h*DH + col_in;
    #pragma unroll
    for (int t = 0; t < 16; t++) {
        *(__half2*)(g_CtxH + off0 + t*8) =
            __half2{__float2half(o[t][0]*inv0), __float2half(o[t][1]*inv0)};
        *(__half2*)(g_CtxH + off1 + t*8) =
            __half2{__float2half(o[t][2]*inv1), __float2half(o[t][3]*inv1)};
    }
}

// ---------------- launch ----------------
extern "C" void kernel_launch(void* const* d_in, const int* in_sizes, int n_in,
                              void* d_out, int out_size)
{
    const float* hs = (const float*)d_in[0];
    const float* Wq = (const float*)d_in[1];
    const float* Wk = (const float*)d_in[2];
    const float* Wv = (const float*)d_in[3];
    const float* Wo = (const float*)d_in[4];
    const int* pos  = (const int*)d_in[6];
    float* out = (float*)d_out;

    __half *hsH,*WqH,*WkH,*WvH,*WoH,*CtxH;
    cudaGetSymbolAddress((void**)&hsH, g_hsH);
    cudaGetSymbolAddress((void**)&WqH, g_WqH);
    cudaGetSymbolAddress((void**)&WkH, g_WkH);
    cudaGetSymbolAddress((void**)&WvH, g_WvH);
    cudaGetSymbolAddress((void**)&WoH, g_WoH);
    cudaGetSymbolAddress((void**)&CtxH, g_CtxH);

    const int NELEM = NROWS*HID;
    const int SPLIT_BLOCKS = NELEM/4/256;

    conv_h5_kernel<<<dim3(SPLIT_BLOCKS, 6), 256>>>(hs, hsH, Wq, WqH, Wk, WkH,
                                                   Wv, WvH, Wo, WoH, pos);

    cudaFuncSetAttribute(gemm_qkv,  cudaFuncAttributeMaxDynamicSharedMemorySize, GT1_SMEM);
    cudaFuncSetAttribute(gemm_mma1, cudaFuncAttributeMaxDynamicSharedMemorySize, GT1_SMEM);

    gemm_qkv<<<dim3(HID/128, NROWS/128, 3), 256, GT1_SMEM>>>(hsH);

    cudaFuncSetAttribute(attn_mma, cudaFuncAttributeMaxDynamicSharedMemorySize, AT2_SMEM);
    attn_mma<<<dim3(S_LEN/64, HEADS, BATCH), 128, AT2_SMEM>>>();

    gemm_mma1<<<dim3(HID/128, NROWS/128), 256, GT1_SMEM>>>(CtxH, WoH, out);
}